// round 1
// baseline (speedup 1.0000x reference)
#include <cuda_runtime.h>
#include <cuda_bf16.h>
#include <cstdint>
#include <cstdio>

// ---------------- problem constants ----------------
#define B_   32
#define C_   512
#define H_   32
#define W_   32
#define NH_  16
#define WS_  4
#define HD_  32            // C/NH
#define NTOK 16            // WS*WS
#define T_   32768         // B*H*W tokens
#define MLPH 2048
#define EPS_ 1e-5f

// ---------------- scratch (device globals; no allocs allowed) ----------------
__device__ float g_xh [ (size_t)T_ * C_ ];    // residual stream (window-major token order)
__device__ float g_xn [ (size_t)T_ * C_ ];    // LN1 output
__device__ float g_qkv[ (size_t)T_ * 3 * C_ ];
__device__ float g_ctx[ (size_t)T_ * C_ ];    // attention context
__device__ float g_xh2[ (size_t)T_ * C_ ];    // after proj + residual
__device__ float g_hn [ (size_t)T_ * C_ ];    // LN2 output
__device__ float g_h1 [ (size_t)T_ * MLPH ];  // MLP hidden (post-GELU)

// ---------------- helpers ----------------
__device__ __forceinline__ float to_tf32(float x) {
    uint32_t u;
    asm("cvt.rna.tf32.f32 %0, %1;" : "=r"(u) : "f"(x));
    return __uint_as_float(u);
}

__device__ __forceinline__ void mma_tf32(float* c, const uint32_t* a, const uint32_t* b) {
    asm("mma.sync.aligned.m16n8k8.row.col.f32.tf32.tf32.f32 "
        "{%0,%1,%2,%3}, {%4,%5,%6,%7}, {%8,%9}, {%0,%1,%2,%3};\n"
        : "+f"(c[0]), "+f"(c[1]), "+f"(c[2]), "+f"(c[3])
        : "r"(a[0]), "r"(a[1]), "r"(a[2]), "r"(a[3]),
          "r"(b[0]), "r"(b[1]));
}

__device__ __forceinline__ float gelu_exact(float x) {
    return 0.5f * x * (1.0f + erff(x * 0.7071067811865475f));
}

// ===================================================================
// Kernel 1: transpose [B,C,H,W] -> token rows (window-major), LN1
// block = (b, h) row of 32 tokens; smem tile [32][513]
// ===================================================================
__global__ void __launch_bounds__(256) ln1_kernel(
    const float* __restrict__ x, const float* __restrict__ nw,
    const float* __restrict__ nb, float* __restrict__ xh, float* __restrict__ xn)
{
    extern __shared__ float tile[];  // [32][513]
    __shared__ float s_sum[32], s_sq[32], s_mean[32], s_rstd[32];
    int bidx = blockIdx.x;
    int bb = bidx >> 5;          // batch
    int h  = bidx & 31;          // row
    int t  = threadIdx.x;
    if (t < 32) { s_sum[t] = 0.f; s_sq[t] = 0.f; }
    __syncthreads();

    const float* xp = x + ((size_t)bb * C_) * (H_ * W_) + (size_t)h * W_;
    float lsum = 0.f, lsq = 0.f;
    for (int idx = t; idx < C_ * 32; idx += 256) {
        int c = idx >> 5, ww = idx & 31;
        float v = xp[(size_t)c * (H_ * W_) + ww];   // coalesced over ww
        tile[ww * 513 + c] = v;
        lsum += v; lsq += v * v;
    }
    atomicAdd(&s_sum[t & 31], lsum);
    atomicAdd(&s_sq [t & 31], lsq);
    __syncthreads();
    if (t < 32) {
        float m = s_sum[t] * (1.f / C_);
        float v = s_sq[t] * (1.f / C_) - m * m;
        s_mean[t] = m; s_rstd[t] = rsqrtf(v + EPS_);
    }
    __syncthreads();

    int wh = h >> 2, i = h & 3;
    for (int idx = t; idx < 32 * C_; idx += 256) {
        int ww = idx >> 9, c = idx & (C_ - 1);
        int wwi = ww >> 2, j = ww & 3;
        int wid = (bb * 8 + wh) * 8 + wwi;
        size_t r = (size_t)wid * NTOK + i * 4 + j;
        float v = tile[ww * 513 + c];
        xh[r * C_ + c] = v;
        xn[r * C_ + c] = (v - s_mean[ww]) * s_rstd[ww] * nw[c] + nb[c];
    }
}

// ===================================================================
// Kernel: generic tf32 GEMM  Out[M,N] = A[M,K] @ W[N,K]^T + epilogue
// BM=128 BN=64 BK=16, 256 threads, warps 4(m) x 2(n), warp tile 32x32
// MODE 0: +bias | 1: gelu(+bias) | 2: +bias+res | 3: +bias+res, permuted store
// ===================================================================
#define BM 128
#define BN 64
#define BK 16

template<int MODE>
__global__ void __launch_bounds__(256) gemm_tf32(
    const float* __restrict__ A, const float* __restrict__ Wm,
    const float* __restrict__ bias, const float* __restrict__ res,
    float* __restrict__ out, int M, int N, int K)
{
    __shared__ float As[BK][BM + 8];
    __shared__ float Bs[BK][BN + 8];

    int tid  = threadIdx.x;
    int bm   = blockIdx.y * BM;
    int bn   = blockIdx.x * BN;
    int lane = tid & 31, warp = tid >> 5;
    int wm = (warp & 3) * 32;
    int wn = (warp >> 2) * 32;
    int tq = lane & 3, g = lane >> 2;

    // global load mapping
    int aRow0 = tid >> 2;          // + 64 for second float4
    int aK0   = (tid & 3) * 4;
    int bRow  = tid >> 2;
    int bK0   = (tid & 3) * 4;

    float acc[2][4][4] = {};

    const int nK = K / BK;
    const float* aBase0 = A  + (size_t)(bm + aRow0) * K + aK0;
    const float* aBase1 = A  + (size_t)(bm + aRow0 + 64) * K + aK0;
    const float* bBase  = Wm + (size_t)(bn + bRow) * K + bK0;

    // prologue: tile 0
    float4 ra0 = *(const float4*)(aBase0);
    float4 ra1 = *(const float4*)(aBase1);
    float4 rb0 = *(const float4*)(bBase);
    {
        float* p0 = (float*)&ra0; float* p1 = (float*)&ra1; float* pb = (float*)&rb0;
        #pragma unroll
        for (int s = 0; s < 4; ++s) {
            As[aK0 + s][aRow0]      = to_tf32(p0[s]);
            As[aK0 + s][aRow0 + 64] = to_tf32(p1[s]);
            Bs[bK0 + s][bRow]       = to_tf32(pb[s]);
        }
    }
    __syncthreads();

    for (int kt = 0; kt < nK; ++kt) {
        float4 na0, na1, nb0;
        if (kt + 1 < nK) {
            int ko = (kt + 1) * BK;
            na0 = *(const float4*)(aBase0 + ko);
            na1 = *(const float4*)(aBase1 + ko);
            nb0 = *(const float4*)(bBase  + ko);
        }

        #pragma unroll
        for (int ks = 0; ks < BK; ks += 8) {
            uint32_t a[2][4], b[4][2];
            #pragma unroll
            for (int mi = 0; mi < 2; ++mi) {
                int mr = wm + mi * 16;
                a[mi][0] = __float_as_uint(As[ks + tq    ][mr + g    ]);
                a[mi][1] = __float_as_uint(As[ks + tq    ][mr + g + 8]);
                a[mi][2] = __float_as_uint(As[ks + tq + 4][mr + g    ]);
                a[mi][3] = __float_as_uint(As[ks + tq + 4][mr + g + 8]);
            }
            #pragma unroll
            for (int ni = 0; ni < 4; ++ni) {
                int nc = wn + ni * 8 + g;
                b[ni][0] = __float_as_uint(Bs[ks + tq    ][nc]);
                b[ni][1] = __float_as_uint(Bs[ks + tq + 4][nc]);
            }
            #pragma unroll
            for (int mi = 0; mi < 2; ++mi)
                #pragma unroll
                for (int ni = 0; ni < 4; ++ni)
                    mma_tf32(acc[mi][ni], a[mi], b[ni]);
        }
        __syncthreads();
        if (kt + 1 < nK) {
            float* p0 = (float*)&na0; float* p1 = (float*)&na1; float* pb = (float*)&nb0;
            #pragma unroll
            for (int s = 0; s < 4; ++s) {
                As[aK0 + s][aRow0]      = to_tf32(p0[s]);
                As[aK0 + s][aRow0 + 64] = to_tf32(p1[s]);
                Bs[bK0 + s][bRow]       = to_tf32(pb[s]);
            }
        }
        __syncthreads();
    }

    // epilogue
    #pragma unroll
    for (int mi = 0; mi < 2; ++mi) {
        #pragma unroll
        for (int ni = 0; ni < 4; ++ni) {
            int r0  = bm + wm + mi * 16 + g;
            int col = bn + wn + ni * 8 + tq * 2;
            #pragma unroll
            for (int half = 0; half < 2; ++half) {
                int r = r0 + half * 8;
                #pragma unroll
                for (int e = 0; e < 2; ++e) {
                    int c = col + e;
                    float v = acc[mi][ni][half * 2 + e] + bias[c];
                    if (MODE == 0) {
                        out[(size_t)r * N + c] = v;
                    } else if (MODE == 1) {
                        out[(size_t)r * N + c] = gelu_exact(v);
                    } else if (MODE == 2) {
                        out[(size_t)r * N + c] = v + res[(size_t)r * N + c];
                    } else {
                        v += res[(size_t)r * N + c];
                        int wi = r >> 4, tt = r & 15;
                        int bb = wi >> 6, wh = (wi >> 3) & 7, ww = wi & 7;
                        int hh = wh * 4 + (tt >> 2), wc = ww * 4 + (tt & 3);
                        out[(((size_t)bb * C_ + c) * H_ + hh) * W_ + wc] = v;
                    }
                }
            }
        }
    }
}

// ===================================================================
// Kernel: windowed attention. block = window (2048), 128 thr = 4 warps.
// Each warp processes 2 heads at once (lane = 16*hh + n), 2 iterations.
// ===================================================================
__global__ void __launch_bounds__(128) attn_kernel(
    const float* __restrict__ qkv, const float* __restrict__ rpb,
    float* __restrict__ ctx)
{
    int w    = blockIdx.x;
    int lane = threadIdx.x & 31;
    int warp = threadIdx.x >> 5;
    int n    = lane & 15;
    int hh   = lane >> 4;
    const float scale = 0.17677669529663687f;   // 1/sqrt(32)
    size_t base = (size_t)w * NTOK * (3 * C_);

    #pragma unroll
    for (int it = 0; it < 2; ++it) {
        int head = warp * 4 + it * 2 + hh;

        float4 q[8];
        const float4* qp = (const float4*)(qkv + base + (size_t)n * (3 * C_) + head * HD_);
        #pragma unroll
        for (int i = 0; i < 8; ++i) {
            q[i] = qp[i];
            q[i].x *= scale; q[i].y *= scale; q[i].z *= scale; q[i].w *= scale;
        }

        float s[16];
        int i1 = n >> 2, j1 = n & 3;
        #pragma unroll
        for (int m = 0; m < 16; ++m) {
            const float4* kp = (const float4*)(qkv + base + (size_t)m * (3 * C_) + C_ + head * HD_);
            float acc = 0.f;
            #pragma unroll
            for (int i = 0; i < 8; ++i) {
                float4 kv = kp[i];
                acc += q[i].x * kv.x + q[i].y * kv.y + q[i].z * kv.z + q[i].w * kv.w;
            }
            int i2 = m >> 2, j2 = m & 3;
            int ridx = (i1 - i2 + 3) * 7 + (j1 - j2 + 3);
            s[m] = acc + rpb[ridx * NH_ + head];
        }

        float mx = s[0];
        #pragma unroll
        for (int m = 1; m < 16; ++m) mx = fmaxf(mx, s[m]);
        float sum = 0.f;
        #pragma unroll
        for (int m = 0; m < 16; ++m) { s[m] = expf(s[m] - mx); sum += s[m]; }
        float inv = 1.f / sum;

        float4 o[8];
        #pragma unroll
        for (int i = 0; i < 8; ++i) { o[i].x = 0.f; o[i].y = 0.f; o[i].z = 0.f; o[i].w = 0.f; }
        #pragma unroll
        for (int m = 0; m < 16; ++m) {
            float p = s[m] * inv;
            const float4* vp = (const float4*)(qkv + base + (size_t)m * (3 * C_) + 2 * C_ + head * HD_);
            #pragma unroll
            for (int i = 0; i < 8; ++i) {
                float4 vv = vp[i];
                o[i].x += p * vv.x; o[i].y += p * vv.y; o[i].z += p * vv.z; o[i].w += p * vv.w;
            }
        }
        float4* op = (float4*)(ctx + (size_t)(w * NTOK + n) * C_ + head * HD_);
        #pragma unroll
        for (int i = 0; i < 8; ++i) op[i] = o[i];
    }
}

// ===================================================================
// Kernel: LN2 over contiguous rows
// ===================================================================
__global__ void __launch_bounds__(128) ln2_kernel(
    const float* __restrict__ in, const float* __restrict__ nw,
    const float* __restrict__ nb, float* __restrict__ outp)
{
    int r = blockIdx.x;
    int t = threadIdx.x;
    int lane = t & 31, warp = t >> 5;
    float4 v = ((const float4*)(in + (size_t)r * C_))[t];
    float ls = v.x + v.y + v.z + v.w;
    float lq = v.x*v.x + v.y*v.y + v.z*v.z + v.w*v.w;
    #pragma unroll
    for (int off = 16; off; off >>= 1) {
        ls += __shfl_down_sync(0xffffffffu, ls, off);
        lq += __shfl_down_sync(0xffffffffu, lq, off);
    }
    __shared__ float ss[4], sq2[4];
    __shared__ float sm, sr;
    if (lane == 0) { ss[warp] = ls; sq2[warp] = lq; }
    __syncthreads();
    if (t == 0) {
        float S = ss[0] + ss[1] + ss[2] + ss[3];
        float Q = sq2[0] + sq2[1] + sq2[2] + sq2[3];
        float m = S * (1.f / C_);
        float var = Q * (1.f / C_) - m * m;
        sm = m; sr = rsqrtf(var + EPS_);
    }
    __syncthreads();
    float m = sm, rs = sr;
    float4 wv = ((const float4*)nw)[t];
    float4 bv = ((const float4*)nb)[t];
    float4 o;
    o.x = (v.x - m) * rs * wv.x + bv.x;
    o.y = (v.y - m) * rs * wv.y + bv.y;
    o.z = (v.z - m) * rs * wv.z + bv.z;
    o.w = (v.w - m) * rs * wv.w + bv.w;
    ((float4*)(outp + (size_t)r * C_))[t] = o;
}

// ===================================================================
// host launch
// ===================================================================
extern "C" void kernel_launch(void* const* d_in, const int* in_sizes, int n_in,
                              void* d_out, int out_size)
{
    const float* x     = (const float*)d_in[0];
    const float* n1w   = (const float*)d_in[1];
    const float* n1b   = (const float*)d_in[2];
    const float* qkvw  = (const float*)d_in[3];
    const float* qkvb  = (const float*)d_in[4];
    const float* rpb   = (const float*)d_in[5];
    const float* projw = (const float*)d_in[6];
    const float* projb = (const float*)d_in[7];
    const float* n2w   = (const float*)d_in[8];
    const float* n2b   = (const float*)d_in[9];
    const float* w1    = (const float*)d_in[10];
    const float* b1    = (const float*)d_in[11];
    const float* w2    = (const float*)d_in[12];
    const float* b2    = (const float*)d_in[13];
    float* out = (float*)d_out;

    float *xh, *xn, *qkvp, *ctx, *xh2, *hn, *h1;
    cudaGetSymbolAddress((void**)&xh,   g_xh);
    cudaGetSymbolAddress((void**)&xn,   g_xn);
    cudaGetSymbolAddress((void**)&qkvp, g_qkv);
    cudaGetSymbolAddress((void**)&ctx,  g_ctx);
    cudaGetSymbolAddress((void**)&xh2,  g_xh2);
    cudaGetSymbolAddress((void**)&hn,   g_hn);
    cudaGetSymbolAddress((void**)&h1,   g_h1);

    int ln1_smem = 32 * 513 * 4;
    cudaFuncSetAttribute(ln1_kernel, cudaFuncAttributeMaxDynamicSharedMemorySize, ln1_smem);

    // 1. transpose + LN1
    ln1_kernel<<<B_ * H_, 256, ln1_smem>>>(x, n1w, n1b, xh, xn);

    // 2. QKV projection [32768,512] x [1536,512]^T
    {
        dim3 grid((3 * C_) / BN, T_ / BM);
        gemm_tf32<0><<<grid, 256>>>(xn, qkvw, qkvb, nullptr, qkvp, T_, 3 * C_, C_);
    }

    // 3. window attention
    attn_kernel<<<T_ / NTOK, 128>>>(qkvp, rpb, ctx);

    // 4. proj + bias + residual
    {
        dim3 grid(C_ / BN, T_ / BM);
        gemm_tf32<2><<<grid, 256>>>(ctx, projw, projb, xh, xh2, T_, C_, C_);
    }

    // 5. LN2
    ln2_kernel<<<T_, 128>>>(xh2, n2w, n2b, hn);

    // 6. MLP1 + bias + GELU
    {
        dim3 grid(MLPH / BN, T_ / BM);
        gemm_tf32<1><<<grid, 256>>>(hn, w1, b1, nullptr, h1, T_, MLPH, C_);
    }

    // 7. MLP2 + bias + residual + un-permute to [B,C,H,W]
    {
        dim3 grid(C_ / BN, T_ / BM);
        gemm_tf32<3><<<grid, 256>>>(h1, w2, b2, xh2, out, T_, C_, MLPH);
    }
}

// round 2
// speedup vs baseline: 1.9857x; 1.9857x over previous
#include <cuda_runtime.h>
#include <cuda_bf16.h>
#include <cstdint>
#include <cstdio>

// ---------------- problem constants ----------------
#define B_   32
#define C_   512
#define H_   32
#define W_   32
#define NH_  16
#define WS_  4
#define HD_  32            // C/NH
#define NTOK 16            // WS*WS
#define T_   32768         // B*H*W tokens
#define MLPH 2048
#define EPS_ 1e-5f

// ---------------- scratch (device globals; no allocs allowed) ----------------
__device__ float g_xh [ (size_t)T_ * C_ ];    // residual stream (window-major token order)
__device__ float g_xn [ (size_t)T_ * C_ ];    // LN1 output
__device__ float g_qkv[ (size_t)T_ * 3 * C_ ];
__device__ float g_ctx[ (size_t)T_ * C_ ];    // attention context
__device__ float g_xh2[ (size_t)T_ * C_ ];    // after proj + residual
__device__ float g_hn [ (size_t)T_ * C_ ];    // LN2 output
__device__ float g_h1 [ (size_t)T_ * MLPH ];  // MLP hidden (post-GELU)

// ---------------- helpers ----------------
__device__ __forceinline__ void mma_tf32(float* c, const uint32_t* a, const uint32_t* b) {
    asm volatile("mma.sync.aligned.m16n8k8.row.col.f32.tf32.tf32.f32 "
        "{%0,%1,%2,%3}, {%4,%5,%6,%7}, {%8,%9}, {%0,%1,%2,%3};\n"
        : "+f"(c[0]), "+f"(c[1]), "+f"(c[2]), "+f"(c[3])
        : "r"(a[0]), "r"(a[1]), "r"(a[2]), "r"(a[3]),
          "r"(b[0]), "r"(b[1]));
}

__device__ __forceinline__ void cp16(float* sdst, const float* gsrc) {
    uint32_t s = (uint32_t)__cvta_generic_to_shared(sdst);
    asm volatile("cp.async.cg.shared.global [%0], [%1], 16;\n" :: "r"(s), "l"(gsrc));
}
#define CP_COMMIT() asm volatile("cp.async.commit_group;\n" ::: "memory")
#define CP_WAIT2()  asm volatile("cp.async.wait_group 2;\n" ::: "memory")

__device__ __forceinline__ float gelu_exact(float x) {
    return 0.5f * x * (1.0f + erff(x * 0.7071067811865475f));
}

// ===================================================================
// Kernel 1: transpose [B,C,H,W] -> token rows (window-major), LN1
// ===================================================================
__global__ void __launch_bounds__(256) ln1_kernel(
    const float* __restrict__ x, const float* __restrict__ nw,
    const float* __restrict__ nb, float* __restrict__ xh, float* __restrict__ xn)
{
    extern __shared__ float tile[];  // [32][513]
    __shared__ float s_sum[32], s_sq[32], s_mean[32], s_rstd[32];
    int bidx = blockIdx.x;
    int bb = bidx >> 5;          // batch
    int h  = bidx & 31;          // row
    int t  = threadIdx.x;
    if (t < 32) { s_sum[t] = 0.f; s_sq[t] = 0.f; }
    __syncthreads();

    const float* xp = x + ((size_t)bb * C_) * (H_ * W_) + (size_t)h * W_;
    float lsum = 0.f, lsq = 0.f;
    for (int idx = t; idx < C_ * 32; idx += 256) {
        int c = idx >> 5, ww = idx & 31;
        float v = xp[(size_t)c * (H_ * W_) + ww];   // coalesced over ww
        tile[ww * 513 + c] = v;
        lsum += v; lsq += v * v;
    }
    atomicAdd(&s_sum[t & 31], lsum);
    atomicAdd(&s_sq [t & 31], lsq);
    __syncthreads();
    if (t < 32) {
        float m = s_sum[t] * (1.f / C_);
        float v = s_sq[t] * (1.f / C_) - m * m;
        s_mean[t] = m; s_rstd[t] = rsqrtf(v + EPS_);
    }
    __syncthreads();

    int wh = h >> 2, i = h & 3;
    for (int idx = t; idx < 32 * C_; idx += 256) {
        int ww = idx >> 9, c = idx & (C_ - 1);
        int wwi = ww >> 2, j = ww & 3;
        int wid = (bb * 8 + wh) * 8 + wwi;
        size_t r = (size_t)wid * NTOK + i * 4 + j;
        float v = tile[ww * 513 + c];
        xh[r * C_ + c] = v;
        xn[r * C_ + c] = (v - s_mean[ww]) * s_rstd[ww] * nw[c] + nb[c];
    }
}

// ===================================================================
// tf32 GEMM: Out[M,N] = A[M,K] @ W[N,K]^T + epilogue
// BM=128 BN=128 BK=16, 256 thr, warps 2(m)x4(n), warp tile 64x32.
// cp.async 4-stage pipeline, k-interleaved layout so fragment loads
// are LDS.128 (one float4 = both k8 slices for this thread).
// Physical col p in [0,16): p=4t   -> slice0 k=t
//                           p=4t+1 -> slice0 k=t+4
//                           p=4t+2 -> slice1 k=t
//                           p=4t+3 -> slice1 k=t+4
// Same permutation for A and B => GEMM result unchanged.
// MODE 0:+bias | 1:gelu(+bias) | 2:+bias+res | 3:+bias+res permuted store
// ===================================================================
#define BM 128
#define BN 128
#define BK 16
#define STAGES 4
#define STAGE_F 4096   // floats per stage (A 2048 + B 2048)

template<int MODE>
__global__ void __launch_bounds__(256) gemm_tc(
    const float* __restrict__ A, const float* __restrict__ Wm,
    const float* __restrict__ bias, const float* __restrict__ res,
    float* __restrict__ out, int M, int N, int K)
{
    extern __shared__ float smem[];   // STAGES * STAGE_F floats

    int tid  = threadIdx.x;
    int bm   = blockIdx.y * BM;
    int bn   = blockIdx.x * BN;
    int lane = tid & 31, warp = tid >> 5;
    int wm = (warp & 1) * 64;
    int wn = (warp >> 1) * 32;
    int tq = lane & 3, g = lane >> 2;
    const int nK = K / BK;

    const float* aG = A  + (size_t)bm * K;
    const float* bG = Wm + (size_t)bn * K;

    // per-thread load assignment: 2 A-chunks + 2 B-chunks of 16B per stage
    int ch0 = tid;          // chunks 0..255
    int ch1 = tid + 256;    // chunks 256..511
    int ar0 = ch0 >> 2, ac0 = (ch0 & 3) * 4;
    int ar1 = ch1 >> 2, ac1 = (ch1 & 3) * 4;

    float acc[4][4][4];
    #pragma unroll
    for (int i = 0; i < 4; ++i)
        #pragma unroll
        for (int j = 0; j < 4; ++j)
            #pragma unroll
            for (int e = 0; e < 4; ++e) acc[i][j][e] = 0.f;

    // prologue: fill STAGES-1 stages
    #pragma unroll
    for (int s = 0; s < STAGES - 1; ++s) {
        float* sb = smem + s * STAGE_F;
        cp16(sb + ar0 * 16 + ac0,        aG + (size_t)ar0 * K + s * BK + ac0);
        cp16(sb + ar1 * 16 + ac1,        aG + (size_t)ar1 * K + s * BK + ac1);
        cp16(sb + 2048 + ar0 * 16 + ac0, bG + (size_t)ar0 * K + s * BK + ac0);
        cp16(sb + 2048 + ar1 * 16 + ac1, bG + (size_t)ar1 * K + s * BK + ac1);
        CP_COMMIT();
    }

    for (int kt = 0; kt < nK; ++kt) {
        CP_WAIT2();
        __syncthreads();

        const float* As = smem + (kt & (STAGES - 1)) * STAGE_F;
        const float* Bs = As + 2048;

        float4 b4[4];
        #pragma unroll
        for (int ni = 0; ni < 4; ++ni)
            b4[ni] = *(const float4*)(Bs + (wn + ni * 8 + g) * 16 + tq * 4);

        #pragma unroll
        for (int mi = 0; mi < 4; ++mi) {
            float4 a0 = *(const float4*)(As + (wm + mi * 16 + g)     * 16 + tq * 4);
            float4 a1 = *(const float4*)(As + (wm + mi * 16 + g + 8) * 16 + tq * 4);
            uint32_t aa0[4] = { __float_as_uint(a0.x), __float_as_uint(a1.x),
                                __float_as_uint(a0.y), __float_as_uint(a1.y) };
            uint32_t aa1[4] = { __float_as_uint(a0.z), __float_as_uint(a1.z),
                                __float_as_uint(a0.w), __float_as_uint(a1.w) };
            #pragma unroll
            for (int ni = 0; ni < 4; ++ni) {
                uint32_t bb0[2] = { __float_as_uint(b4[ni].x), __float_as_uint(b4[ni].y) };
                uint32_t bb1[2] = { __float_as_uint(b4[ni].z), __float_as_uint(b4[ni].w) };
                mma_tf32(acc[mi][ni], aa0, bb0);
                mma_tf32(acc[mi][ni], aa1, bb1);
            }
        }

        int kn = kt + STAGES - 1;
        if (kn < nK) {
            float* sb = smem + (kn & (STAGES - 1)) * STAGE_F;
            cp16(sb + ar0 * 16 + ac0,        aG + (size_t)ar0 * K + kn * BK + ac0);
            cp16(sb + ar1 * 16 + ac1,        aG + (size_t)ar1 * K + kn * BK + ac1);
            cp16(sb + 2048 + ar0 * 16 + ac0, bG + (size_t)ar0 * K + kn * BK + ac0);
            cp16(sb + 2048 + ar1 * 16 + ac1, bG + (size_t)ar1 * K + kn * BK + ac1);
        }
        CP_COMMIT();
    }

    // epilogue
    #pragma unroll
    for (int mi = 0; mi < 4; ++mi) {
        #pragma unroll
        for (int ni = 0; ni < 4; ++ni) {
            int c = bn + wn + ni * 8 + tq * 2;
            float2 bv = *(const float2*)(bias + c);
            #pragma unroll
            for (int half = 0; half < 2; ++half) {
                int r = bm + wm + mi * 16 + g + half * 8;
                float v0 = acc[mi][ni][half * 2 + 0] + bv.x;
                float v1 = acc[mi][ni][half * 2 + 1] + bv.y;
                if (MODE == 0) {
                    *(float2*)(out + (size_t)r * N + c) = make_float2(v0, v1);
                } else if (MODE == 1) {
                    *(float2*)(out + (size_t)r * N + c) =
                        make_float2(gelu_exact(v0), gelu_exact(v1));
                } else if (MODE == 2) {
                    float2 rv = *(const float2*)(res + (size_t)r * N + c);
                    *(float2*)(out + (size_t)r * N + c) =
                        make_float2(v0 + rv.x, v1 + rv.y);
                } else {
                    float2 rv = *(const float2*)(res + (size_t)r * N + c);
                    v0 += rv.x; v1 += rv.y;
                    int wi = r >> 4, tt = r & 15;
                    int bb = wi >> 6, wh = (wi >> 3) & 7, ww = wi & 7;
                    int hh = wh * 4 + (tt >> 2), wc = ww * 4 + (tt & 3);
                    out[(((size_t)bb * C_ + c)     * H_ + hh) * W_ + wc] = v0;
                    out[(((size_t)bb * C_ + c + 1) * H_ + hh) * W_ + wc] = v1;
                }
            }
        }
    }
}

// ===================================================================
// windowed attention: block = window, 128 thr = 4 warps, warp = 2 heads
// ===================================================================
__global__ void __launch_bounds__(128) attn_kernel(
    const float* __restrict__ qkv, const float* __restrict__ rpb,
    float* __restrict__ ctx)
{
    int w    = blockIdx.x;
    int lane = threadIdx.x & 31;
    int warp = threadIdx.x >> 5;
    int n    = lane & 15;
    int hh   = lane >> 4;
    const float scale = 0.17677669529663687f;   // 1/sqrt(32)
    size_t base = (size_t)w * NTOK * (3 * C_);

    #pragma unroll
    for (int it = 0; it < 2; ++it) {
        int head = warp * 4 + it * 2 + hh;

        float4 q[8];
        const float4* qp = (const float4*)(qkv + base + (size_t)n * (3 * C_) + head * HD_);
        #pragma unroll
        for (int i = 0; i < 8; ++i) {
            q[i] = qp[i];
            q[i].x *= scale; q[i].y *= scale; q[i].z *= scale; q[i].w *= scale;
        }

        float s[16];
        int i1 = n >> 2, j1 = n & 3;
        #pragma unroll
        for (int m = 0; m < 16; ++m) {
            const float4* kp = (const float4*)(qkv + base + (size_t)m * (3 * C_) + C_ + head * HD_);
            float acc = 0.f;
            #pragma unroll
            for (int i = 0; i < 8; ++i) {
                float4 kv = kp[i];
                acc += q[i].x * kv.x + q[i].y * kv.y + q[i].z * kv.z + q[i].w * kv.w;
            }
            int i2 = m >> 2, j2 = m & 3;
            int ridx = (i1 - i2 + 3) * 7 + (j1 - j2 + 3);
            s[m] = acc + rpb[ridx * NH_ + head];
        }

        float mx = s[0];
        #pragma unroll
        for (int m = 1; m < 16; ++m) mx = fmaxf(mx, s[m]);
        float sum = 0.f;
        #pragma unroll
        for (int m = 0; m < 16; ++m) { s[m] = expf(s[m] - mx); sum += s[m]; }
        float inv = 1.f / sum;

        float4 o[8];
        #pragma unroll
        for (int i = 0; i < 8; ++i) { o[i].x = 0.f; o[i].y = 0.f; o[i].z = 0.f; o[i].w = 0.f; }
        #pragma unroll
        for (int m = 0; m < 16; ++m) {
            float p = s[m] * inv;
            const float4* vp = (const float4*)(qkv + base + (size_t)m * (3 * C_) + 2 * C_ + head * HD_);
            #pragma unroll
            for (int i = 0; i < 8; ++i) {
                float4 vv = vp[i];
                o[i].x += p * vv.x; o[i].y += p * vv.y; o[i].z += p * vv.z; o[i].w += p * vv.w;
            }
        }
        float4* op = (float4*)(ctx + (size_t)(w * NTOK + n) * C_ + head * HD_);
        #pragma unroll
        for (int i = 0; i < 8; ++i) op[i] = o[i];
    }
}

// ===================================================================
// LN2 over contiguous rows
// ===================================================================
__global__ void __launch_bounds__(128) ln2_kernel(
    const float* __restrict__ in, const float* __restrict__ nw,
    const float* __restrict__ nb, float* __restrict__ outp)
{
    int r = blockIdx.x;
    int t = threadIdx.x;
    int lane = t & 31, warp = t >> 5;
    float4 v = ((const float4*)(in + (size_t)r * C_))[t];
    float ls = v.x + v.y + v.z + v.w;
    float lq = v.x*v.x + v.y*v.y + v.z*v.z + v.w*v.w;
    #pragma unroll
    for (int off = 16; off; off >>= 1) {
        ls += __shfl_down_sync(0xffffffffu, ls, off);
        lq += __shfl_down_sync(0xffffffffu, lq, off);
    }
    __shared__ float ss[4], sq2[4];
    __shared__ float sm, sr;
    if (lane == 0) { ss[warp] = ls; sq2[warp] = lq; }
    __syncthreads();
    if (t == 0) {
        float S = ss[0] + ss[1] + ss[2] + ss[3];
        float Q = sq2[0] + sq2[1] + sq2[2] + sq2[3];
        float m = S * (1.f / C_);
        float var = Q * (1.f / C_) - m * m;
        sm = m; sr = rsqrtf(var + EPS_);
    }
    __syncthreads();
    float m = sm, rs = sr;
    float4 wv = ((const float4*)nw)[t];
    float4 bv = ((const float4*)nb)[t];
    float4 o;
    o.x = (v.x - m) * rs * wv.x + bv.x;
    o.y = (v.y - m) * rs * wv.y + bv.y;
    o.z = (v.z - m) * rs * wv.z + bv.z;
    o.w = (v.w - m) * rs * wv.w + bv.w;
    ((float4*)(outp + (size_t)r * C_))[t] = o;
}

// ===================================================================
// host launch
// ===================================================================
extern "C" void kernel_launch(void* const* d_in, const int* in_sizes, int n_in,
                              void* d_out, int out_size)
{
    const float* x     = (const float*)d_in[0];
    const float* n1w   = (const float*)d_in[1];
    const float* n1b   = (const float*)d_in[2];
    const float* qkvw  = (const float*)d_in[3];
    const float* qkvb  = (const float*)d_in[4];
    const float* rpb   = (const float*)d_in[5];
    const float* projw = (const float*)d_in[6];
    const float* projb = (const float*)d_in[7];
    const float* n2w   = (const float*)d_in[8];
    const float* n2b   = (const float*)d_in[9];
    const float* w1    = (const float*)d_in[10];
    const float* b1    = (const float*)d_in[11];
    const float* w2    = (const float*)d_in[12];
    const float* b2    = (const float*)d_in[13];
    float* out = (float*)d_out;

    float *xh, *xn, *qkvp, *ctx, *xh2, *hn, *h1;
    cudaGetSymbolAddress((void**)&xh,   g_xh);
    cudaGetSymbolAddress((void**)&xn,   g_xn);
    cudaGetSymbolAddress((void**)&qkvp, g_qkv);
    cudaGetSymbolAddress((void**)&ctx,  g_ctx);
    cudaGetSymbolAddress((void**)&xh2,  g_xh2);
    cudaGetSymbolAddress((void**)&hn,   g_hn);
    cudaGetSymbolAddress((void**)&h1,   g_h1);

    int ln1_smem = 32 * 513 * 4;
    cudaFuncSetAttribute(ln1_kernel, cudaFuncAttributeMaxDynamicSharedMemorySize, ln1_smem);
    int gsm = STAGES * STAGE_F * 4;   // 64 KB
    cudaFuncSetAttribute(gemm_tc<0>, cudaFuncAttributeMaxDynamicSharedMemorySize, gsm);
    cudaFuncSetAttribute(gemm_tc<1>, cudaFuncAttributeMaxDynamicSharedMemorySize, gsm);
    cudaFuncSetAttribute(gemm_tc<2>, cudaFuncAttributeMaxDynamicSharedMemorySize, gsm);
    cudaFuncSetAttribute(gemm_tc<3>, cudaFuncAttributeMaxDynamicSharedMemorySize, gsm);

    // 1. transpose + LN1
    ln1_kernel<<<B_ * H_, 256, ln1_smem>>>(x, n1w, n1b, xh, xn);

    // 2. QKV projection [32768,512] x [1536,512]^T
    {
        dim3 grid((3 * C_) / BN, T_ / BM);
        gemm_tc<0><<<grid, 256, gsm>>>(xn, qkvw, qkvb, nullptr, qkvp, T_, 3 * C_, C_);
    }

    // 3. window attention
    attn_kernel<<<T_ / NTOK, 128>>>(qkvp, rpb, ctx);

    // 4. proj + bias + residual
    {
        dim3 grid(C_ / BN, T_ / BM);
        gemm_tc<2><<<grid, 256, gsm>>>(ctx, projw, projb, xh, xh2, T_, C_, C_);
    }

    // 5. LN2
    ln2_kernel<<<T_, 128>>>(xh2, n2w, n2b, hn);

    // 6. MLP1 + bias + GELU
    {
        dim3 grid(MLPH / BN, T_ / BM);
        gemm_tc<1><<<grid, 256, gsm>>>(hn, w1, b1, nullptr, h1, T_, MLPH, C_);
    }

    // 7. MLP2 + bias + residual + un-permute to [B,C,H,W]
    {
        dim3 grid(C_ / BN, T_ / BM);
        gemm_tc<3><<<grid, 256, gsm>>>(h1, w2, b2, xh2, out, T_, C_, MLPH);
    }
}

// round 5
// speedup vs baseline: 2.1346x; 1.0750x over previous
#include <cuda_runtime.h>
#include <cuda_bf16.h>
#include <cstdint>
#include <cstdio>

// ---------------- problem constants ----------------
#define B_   32
#define C_   512
#define H_   32
#define W_   32
#define NH_  16
#define WS_  4
#define HD_  32
#define NTOK 16
#define T_   32768
#define MLPH 2048
#define EPS_ 1e-5f

// ---------------- scratch (device globals; no allocs allowed) ----------------
__device__ float g_xh [ (size_t)T_ * C_ ];
__device__ float g_xn [ (size_t)T_ * C_ ];
__device__ float g_qkv[ (size_t)T_ * 3 * C_ ];
__device__ float g_ctx[ (size_t)T_ * C_ ];
__device__ float g_xh2[ (size_t)T_ * C_ ];
__device__ float g_hn [ (size_t)T_ * C_ ];
__device__ float g_h1 [ (size_t)T_ * MLPH ];

// ---------------- helpers ----------------
__device__ __forceinline__ void mma_tf32(float* c, const uint32_t* a, const uint32_t* b) {
    asm volatile("mma.sync.aligned.m16n8k8.row.col.f32.tf32.tf32.f32 "
        "{%0,%1,%2,%3}, {%4,%5,%6,%7}, {%8,%9}, {%0,%1,%2,%3};\n"
        : "+f"(c[0]), "+f"(c[1]), "+f"(c[2]), "+f"(c[3])
        : "r"(a[0]), "r"(a[1]), "r"(a[2]), "r"(a[3]),
          "r"(b[0]), "r"(b[1]));
}

__device__ __forceinline__ void cp16(float* sdst, const float* gsrc) {
    uint32_t s = (uint32_t)__cvta_generic_to_shared(sdst);
    asm volatile("cp.async.cg.shared.global [%0], [%1], 16;\n" :: "r"(s), "l"(gsrc));
}
#define CP_COMMIT() asm volatile("cp.async.commit_group;\n" ::: "memory")
#define CP_WAIT1()  asm volatile("cp.async.wait_group 1;\n" ::: "memory")

__device__ __forceinline__ float gelu_exact(float x) {
    return 0.5f * x * (1.0f + erff(x * 0.7071067811865475f));
}
__device__ __forceinline__ uint32_t fu(float x) { return __float_as_uint(x); }

// ===================================================================
// tf32 GEMM: Out[M,N] = A[M,K] @ W[N,K]^T + epilogue
// CTA 128x128, 128 threads = 4 warps (2m x 2n), warp tile 64x64.
// BK=32 floats (128B rows), 3-stage cp.async ring, parity-XOR swizzle
// so all fragment LDS.128 are phase-conflict-free.
// k-permutation within each 16-col group applied identically to A and B
// (GEMM is k-permutation invariant).
// MODE 0:+bias | 1:gelu(+bias) | 2:+bias+res | 3:+bias+res permuted store
// ===================================================================
#define STAGE_F 8192            // floats per stage: A 4096 + B 4096
#define GSMEM   (3 * STAGE_F * 4)   // 96 KB

template<int MODE>
__global__ void __launch_bounds__(128, 2) gemm_tc(
    const float* __restrict__ A, const float* __restrict__ Wm,
    const float* __restrict__ bias, const float* __restrict__ res,
    float* __restrict__ out, int M, int N, int K)
{
    extern __shared__ float smem[];

    const int tid  = threadIdx.x;
    const int lane = tid & 31, warp = tid >> 5;
    const int bm   = blockIdx.y * 128;
    const int bn   = blockIdx.x * 128;
    const int wm   = (warp & 1) * 64;
    const int wn   = (warp >> 1) * 64;
    const int tq   = lane & 3, g = lane >> 2;
    const int xsw  = (g & 1) << 2;          // fragment-read swizzle
    const int nK   = K >> 5;

    const float* aG = A  + (size_t)bm * K;
    const float* bG = Wm + (size_t)bn * K;

    // cp.async store mapping: thread owns rows r0+16i, chunk c4 (swizzled)
    const int r0  = tid >> 3, c4 = tid & 7;
    const int cps = c4 ^ ((r0 & 1) << 2);   // store swizzle (parity const per thread)

    float acc[4][8][4];
    #pragma unroll
    for (int i = 0; i < 4; ++i)
        #pragma unroll
        for (int j = 0; j < 8; ++j)
            #pragma unroll
            for (int e = 0; e < 4; ++e) acc[i][j][e] = 0.f;

    auto issue = [&](int st, int kt) {
        float* sb = smem + st * STAGE_F;
        const float* ga = aG + kt * 32 + c4 * 4;
        const float* gb = bG + kt * 32 + c4 * 4;
        #pragma unroll
        for (int i = 0; i < 8; ++i) {
            int r = r0 + i * 16;
            cp16(sb + r * 32 + cps * 4,        ga + (size_t)r * K);
            cp16(sb + 4096 + r * 32 + cps * 4, gb + (size_t)r * K);
        }
    };

    issue(0, 0); CP_COMMIT();
    issue(1, 1); CP_COMMIT();

    for (int kt = 0; kt < nK; ++kt) {
        CP_WAIT1();
        __syncthreads();
        int kn = kt + 2;
        if (kn < nK) issue(kn % 3, kn);
        CP_COMMIT();

        const float* As = smem + (kt % 3) * STAGE_F;
        const float* Bs = As + 4096;

        #pragma unroll
        for (int p = 0; p < 2; ++p) {
            const int cf = (((p << 2) + tq) ^ xsw) * 4;   // fragment chunk offset
            float4 bq[8];
            #pragma unroll
            for (int ni = 0; ni < 8; ++ni)
                bq[ni] = *(const float4*)(Bs + (wn + ni * 8 + g) * 32 + cf);
            #pragma unroll
            for (int mi = 0; mi < 4; ++mi) {
                int ra = wm + mi * 16 + g;
                float4 a0 = *(const float4*)(As + ra * 32 + cf);
                float4 a1 = *(const float4*)(As + (ra + 8) * 32 + cf);
                uint32_t aa0[4] = { fu(a0.x), fu(a1.x), fu(a0.y), fu(a1.y) };
                uint32_t aa1[4] = { fu(a0.z), fu(a1.z), fu(a0.w), fu(a1.w) };
                #pragma unroll
                for (int ni = 0; ni < 8; ++ni) {
                    uint32_t bb0[2] = { fu(bq[ni].x), fu(bq[ni].y) };
                    uint32_t bb1[2] = { fu(bq[ni].z), fu(bq[ni].w) };
                    mma_tf32(acc[mi][ni], aa0, bb0);
                    mma_tf32(acc[mi][ni], aa1, bb1);
                }
            }
        }
    }

    // epilogue
    #pragma unroll
    for (int mi = 0; mi < 4; ++mi) {
        #pragma unroll
        for (int ni = 0; ni < 8; ++ni) {
            int c = bn + wn + ni * 8 + tq * 2;
            float2 bv = *(const float2*)(bias + c);
            #pragma unroll
            for (int half = 0; half < 2; ++half) {
                int r = bm + wm + mi * 16 + g + half * 8;
                float v0 = acc[mi][ni][half * 2 + 0] + bv.x;
                float v1 = acc[mi][ni][half * 2 + 1] + bv.y;
                if (MODE == 0) {
                    *(float2*)(out + (size_t)r * N + c) = make_float2(v0, v1);
                } else if (MODE == 1) {
                    *(float2*)(out + (size_t)r * N + c) =
                        make_float2(gelu_exact(v0), gelu_exact(v1));
                } else if (MODE == 2) {
                    float2 rv = *(const float2*)(res + (size_t)r * N + c);
                    *(float2*)(out + (size_t)r * N + c) =
                        make_float2(v0 + rv.x, v1 + rv.y);
                } else {
                    float2 rv = *(const float2*)(res + (size_t)r * N + c);
                    v0 += rv.x; v1 += rv.y;
                    int wi = r >> 4, tt = r & 15;
                    int bb = wi >> 6, wh = (wi >> 3) & 7, ww = wi & 7;
                    int hh = wh * 4 + (tt >> 2), wc = ww * 4 + (tt & 3);
                    out[(((size_t)bb * C_ + c)     * H_ + hh) * W_ + wc] = v0;
                    out[(((size_t)bb * C_ + c + 1) * H_ + hh) * W_ + wc] = v1;
                }
            }
        }
    }
}

// ===================================================================
// Kernel 1: transpose [B,C,H,W] -> token rows (window-major), LN1
// ===================================================================
__global__ void __launch_bounds__(256) ln1_kernel(
    const float* __restrict__ x, const float* __restrict__ nw,
    const float* __restrict__ nb, float* __restrict__ xh, float* __restrict__ xn)
{
    extern __shared__ float tile[];  // [32][513]
    __shared__ float s_sum[32], s_sq[32], s_mean[32], s_rstd[32];
    int bidx = blockIdx.x;
    int bb = bidx >> 5, h = bidx & 31;
    int t = threadIdx.x;
    if (t < 32) { s_sum[t] = 0.f; s_sq[t] = 0.f; }
    __syncthreads();

    const float* xp = x + ((size_t)bb * C_) * (H_ * W_) + (size_t)h * W_;
    float lsum = 0.f, lsq = 0.f;
    for (int idx = t; idx < C_ * 32; idx += 256) {
        int c = idx >> 5, ww = idx & 31;
        float v = xp[(size_t)c * (H_ * W_) + ww];
        tile[ww * 513 + c] = v;
        lsum += v; lsq += v * v;
    }
    atomicAdd(&s_sum[t & 31], lsum);
    atomicAdd(&s_sq [t & 31], lsq);
    __syncthreads();
    if (t < 32) {
        float m = s_sum[t] * (1.f / C_);
        float v = s_sq[t] * (1.f / C_) - m * m;
        s_mean[t] = m; s_rstd[t] = rsqrtf(v + EPS_);
    }
    __syncthreads();

    int wh = h >> 2, i = h & 3;
    for (int idx = t; idx < 32 * C_; idx += 256) {
        int ww = idx >> 9, c = idx & (C_ - 1);
        int wwi = ww >> 2, j = ww & 3;
        int wid = (bb * 8 + wh) * 8 + wwi;
        size_t r = (size_t)wid * NTOK + i * 4 + j;
        float v = tile[ww * 513 + c];
        xh[r * C_ + c] = v;
        xn[r * C_ + c] = (v - s_mean[ww]) * s_rstd[ww] * nw[c] + nb[c];
    }
}

// ===================================================================
// windowed attention: block = window, 128 thr = 4 warps, warp = 2 heads
// ===================================================================
__global__ void __launch_bounds__(128) attn_kernel(
    const float* __restrict__ qkv, const float* __restrict__ rpb,
    float* __restrict__ ctx)
{
    int w    = blockIdx.x;
    int lane = threadIdx.x & 31;
    int warp = threadIdx.x >> 5;
    int n    = lane & 15;
    int hh   = lane >> 4;
    const float scale = 0.17677669529663687f;
    size_t base = (size_t)w * NTOK * (3 * C_);

    #pragma unroll
    for (int it = 0; it < 2; ++it) {
        int head = warp * 4 + it * 2 + hh;
        float4 q[8];
        const float4* qp = (const float4*)(qkv + base + (size_t)n * (3 * C_) + head * HD_);
        #pragma unroll
        for (int i = 0; i < 8; ++i) {
            q[i] = qp[i];
            q[i].x *= scale; q[i].y *= scale; q[i].z *= scale; q[i].w *= scale;
        }
        float s[16];
        int i1 = n >> 2, j1 = n & 3;
        #pragma unroll
        for (int m = 0; m < 16; ++m) {
            const float4* kp = (const float4*)(qkv + base + (size_t)m * (3 * C_) + C_ + head * HD_);
            float acc = 0.f;
            #pragma unroll
            for (int i = 0; i < 8; ++i) {
                float4 kv = kp[i];
                acc += q[i].x * kv.x + q[i].y * kv.y + q[i].z * kv.z + q[i].w * kv.w;
            }
            int i2 = m >> 2, j2 = m & 3;
            int ridx = (i1 - i2 + 3) * 7 + (j1 - j2 + 3);
            s[m] = acc + rpb[ridx * NH_ + head];
        }
        float mx = s[0];
        #pragma unroll
        for (int m = 1; m < 16; ++m) mx = fmaxf(mx, s[m]);
        float sum = 0.f;
        #pragma unroll
        for (int m = 0; m < 16; ++m) { s[m] = expf(s[m] - mx); sum += s[m]; }
        float inv = 1.f / sum;
        float4 o[8];
        #pragma unroll
        for (int i = 0; i < 8; ++i) { o[i].x = 0.f; o[i].y = 0.f; o[i].z = 0.f; o[i].w = 0.f; }
        #pragma unroll
        for (int m = 0; m < 16; ++m) {
            float p = s[m] * inv;
            const float4* vp = (const float4*)(qkv + base + (size_t)m * (3 * C_) + 2 * C_ + head * HD_);
            #pragma unroll
            for (int i = 0; i < 8; ++i) {
                float4 vv = vp[i];
                o[i].x += p * vv.x; o[i].y += p * vv.y; o[i].z += p * vv.z; o[i].w += p * vv.w;
            }
        }
        float4* op = (float4*)(ctx + (size_t)(w * NTOK + n) * C_ + head * HD_);
        #pragma unroll
        for (int i = 0; i < 8; ++i) op[i] = o[i];
    }
}

// ===================================================================
// LN2 over contiguous rows
// ===================================================================
__global__ void __launch_bounds__(128) ln2_kernel(
    const float* __restrict__ in, const float* __restrict__ nw,
    const float* __restrict__ nb, float* __restrict__ outp)
{
    int r = blockIdx.x;
    int t = threadIdx.x;
    int lane = t & 31, warp = t >> 5;
    float4 v = ((const float4*)(in + (size_t)r * C_))[t];
    float ls = v.x + v.y + v.z + v.w;
    float lq = v.x*v.x + v.y*v.y + v.z*v.z + v.w*v.w;
    #pragma unroll
    for (int off = 16; off; off >>= 1) {
        ls += __shfl_down_sync(0xffffffffu, ls, off);
        lq += __shfl_down_sync(0xffffffffu, lq, off);
    }
    __shared__ float ss[4], sq2[4];
    __shared__ float sm, sr;
    if (lane == 0) { ss[warp] = ls; sq2[warp] = lq; }
    __syncthreads();
    if (t == 0) {
        float S = ss[0] + ss[1] + ss[2] + ss[3];
        float Q = sq2[0] + sq2[1] + sq2[2] + sq2[3];
        float m = S * (1.f / C_);
        float var = Q * (1.f / C_) - m * m;
        sm = m; sr = rsqrtf(var + EPS_);
    }
    __syncthreads();
    float m = sm, rs = sr;
    float4 wv = ((const float4*)nw)[t];
    float4 bv = ((const float4*)nb)[t];
    float4 o;
    o.x = (v.x - m) * rs * wv.x + bv.x;
    o.y = (v.y - m) * rs * wv.y + bv.y;
    o.z = (v.z - m) * rs * wv.z + bv.z;
    o.w = (v.w - m) * rs * wv.w + bv.w;
    ((float4*)(outp + (size_t)r * C_))[t] = o;
}

// ===================================================================
// host launch
// ===================================================================
extern "C" void kernel_launch(void* const* d_in, const int* in_sizes, int n_in,
                              void* d_out, int out_size)
{
    const float* x     = (const float*)d_in[0];
    const float* n1w   = (const float*)d_in[1];
    const float* n1b   = (const float*)d_in[2];
    const float* qkvw  = (const float*)d_in[3];
    const float* qkvb  = (const float*)d_in[4];
    const float* rpb   = (const float*)d_in[5];
    const float* projw = (const float*)d_in[6];
    const float* projb = (const float*)d_in[7];
    const float* n2w   = (const float*)d_in[8];
    const float* n2b   = (const float*)d_in[9];
    const float* w1    = (const float*)d_in[10];
    const float* b1    = (const float*)d_in[11];
    const float* w2    = (const float*)d_in[12];
    const float* b2    = (const float*)d_in[13];
    float* out = (float*)d_out;

    float *xh, *xn, *qkvp, *ctx, *xh2, *hn, *h1;
    cudaGetSymbolAddress((void**)&xh,   g_xh);
    cudaGetSymbolAddress((void**)&xn,   g_xn);
    cudaGetSymbolAddress((void**)&qkvp, g_qkv);
    cudaGetSymbolAddress((void**)&ctx,  g_ctx);
    cudaGetSymbolAddress((void**)&xh2,  g_xh2);
    cudaGetSymbolAddress((void**)&hn,   g_hn);
    cudaGetSymbolAddress((void**)&h1,   g_h1);

    int ln1_smem = 32 * 513 * 4;
    cudaFuncSetAttribute(ln1_kernel, cudaFuncAttributeMaxDynamicSharedMemorySize, ln1_smem);
    cudaFuncSetAttribute(gemm_tc<0>, cudaFuncAttributeMaxDynamicSharedMemorySize, GSMEM);
    cudaFuncSetAttribute(gemm_tc<1>, cudaFuncAttributeMaxDynamicSharedMemorySize, GSMEM);
    cudaFuncSetAttribute(gemm_tc<2>, cudaFuncAttributeMaxDynamicSharedMemorySize, GSMEM);
    cudaFuncSetAttribute(gemm_tc<3>, cudaFuncAttributeMaxDynamicSharedMemorySize, GSMEM);

    // 1. transpose + LN1
    ln1_kernel<<<B_ * H_, 256, ln1_smem>>>(x, n1w, n1b, xh, xn);

    // 2. QKV projection [32768,512] x [1536,512]^T
    gemm_tc<0><<<dim3((3 * C_) / 128, T_ / 128), 128, GSMEM>>>(
        xn, qkvw, qkvb, nullptr, qkvp, T_, 3 * C_, C_);

    // 3. window attention
    attn_kernel<<<T_ / NTOK, 128>>>(qkvp, rpb, ctx);

    // 4. proj + bias + residual
    gemm_tc<2><<<dim3(C_ / 128, T_ / 128), 128, GSMEM>>>(
        ctx, projw, projb, xh, xh2, T_, C_, C_);

    // 5. LN2
    ln2_kernel<<<T_, 128>>>(xh2, n2w, n2b, hn);

    // 6. MLP1 + bias + GELU
    gemm_tc<1><<<dim3(MLPH / 128, T_ / 128), 128, GSMEM>>>(
        hn, w1, b1, nullptr, h1, T_, MLPH, C_);

    // 7. MLP2 + bias + residual + un-permute to [B,C,H,W]
    gemm_tc<3><<<dim3(C_ / 128, T_ / 128), 128, GSMEM>>>(
        h1, w2, b2, xh2, out, T_, C_, MLPH);
}

// round 6
// speedup vs baseline: 3.1599x; 1.4804x over previous
#include <cuda_runtime.h>
#include <cuda_fp16.h>
#include <cstdint>
#include <cstdio>

// ---------------- problem constants ----------------
#define B_   32
#define C_   512
#define H_   32
#define W_   32
#define NH_  16
#define WS_  4
#define HD_  32
#define NTOK 16
#define T_   32768
#define MLPH 2048
#define EPS_ 1e-5f

// ---------------- scratch (device globals; no allocs allowed) ----------------
__device__ float  g_xh  [ (size_t)T_ * C_ ];     // residual (window-major)
__device__ float  g_qkv [ (size_t)T_ * 3 * C_ ]; // fp32 qkv for attention
__device__ float  g_xh2 [ (size_t)T_ * C_ ];     // after proj + residual
__device__ __half g_xn_h [ (size_t)T_ * C_ ];    // LN1 out (fp16)
__device__ __half g_ctx_h[ (size_t)T_ * C_ ];    // attn context (fp16)
__device__ __half g_hn_h [ (size_t)T_ * C_ ];    // LN2 out (fp16)
__device__ __half g_h1_h [ (size_t)T_ * MLPH ];  // MLP hidden (fp16)
__device__ __half g_wq_h [ (size_t)3 * C_ * C_ ];
__device__ __half g_wp_h [ (size_t)C_ * C_ ];
__device__ __half g_w1_h [ (size_t)MLPH * C_ ];
__device__ __half g_w2_h [ (size_t)C_ * MLPH ];

// ---------------- helpers ----------------
__device__ __forceinline__ void mma_f16(float* c, const uint32_t* a, const uint32_t* b) {
    asm volatile("mma.sync.aligned.m16n8k16.row.col.f32.f16.f16.f32 "
        "{%0,%1,%2,%3}, {%4,%5,%6,%7}, {%8,%9}, {%0,%1,%2,%3};\n"
        : "+f"(c[0]), "+f"(c[1]), "+f"(c[2]), "+f"(c[3])
        : "r"(a[0]), "r"(a[1]), "r"(a[2]), "r"(a[3]),
          "r"(b[0]), "r"(b[1]));
}

#define LDMX4(r, addr) \
    asm volatile("ldmatrix.sync.aligned.m8n8.x4.shared.b16 {%0,%1,%2,%3}, [%4];" \
        : "=r"((r)[0]), "=r"((r)[1]), "=r"((r)[2]), "=r"((r)[3]) : "r"(addr))

__device__ __forceinline__ void cp16(const void* sdst, const void* gsrc) {
    uint32_t s = (uint32_t)__cvta_generic_to_shared(sdst);
    asm volatile("cp.async.cg.shared.global [%0], [%1], 16;\n" :: "r"(s), "l"(gsrc));
}
#define CP_COMMIT() asm volatile("cp.async.commit_group;\n" ::: "memory")
#define CP_WAIT1()  asm volatile("cp.async.wait_group 1;\n" ::: "memory")

__device__ __forceinline__ float gelu_exact(float x) {
    return 0.5f * x * (1.0f + erff(x * 0.7071067811865475f));
}

// ===================================================================
// fp32 -> fp16 conversion (weights), n divisible by 4
// ===================================================================
__global__ void f2h_kernel(const float* __restrict__ s, __half* __restrict__ d, int n) {
    int i = (blockIdx.x * blockDim.x + threadIdx.x) * 4;
    if (i < n) {
        float4 v = *(const float4*)(s + i);
        __half2* dp = (__half2*)(d + i);
        dp[0] = __floats2half2_rn(v.x, v.y);
        dp[1] = __floats2half2_rn(v.z, v.w);
    }
}

// ===================================================================
// fp16 GEMM: Out[M,N] = A[M,K] @ W[N,K]^T + epilogue
// CTA 128x128, 128 thr = 4 warps (2m x 2n), warp tile 64x64.
// BK=64 halves (128B rows), SW128 chunk-XOR swizzle, 3-stage cp.async
// ring, ldmatrix.x4 fragment loads, mma.m16n8k16.f16 (fp32 accum).
// MODE 0:+bias fp32 out | 1:gelu(+bias) fp16 out | 2:+bias+res fp32 |
// MODE 3:+bias+res permuted fp32 store
// ===================================================================
#define STAGE_H 16384            // halves per stage: A 8192 + B 8192 (32 KB)
#define GSMEM   (3 * STAGE_H * 2)    // 96 KB

template<int MODE>
__global__ void __launch_bounds__(128, 2) gemm_h(
    const __half* __restrict__ A, const __half* __restrict__ Wm,
    const float* __restrict__ bias, const float* __restrict__ res,
    void* __restrict__ outv, int M, int N, int K)
{
    extern __shared__ __half smem[];

    const int tid  = threadIdx.x;
    const int lane = tid & 31, warp = tid >> 5;
    const int bm   = blockIdx.y * 128;
    const int bn   = blockIdx.x * 128;
    const int wm   = (warp & 1) * 64;
    const int wn   = (warp >> 1) * 64;
    const int tq   = lane & 3, g = lane >> 2;
    const int nK   = K >> 6;

    // cp.async store mapping: rows r0+16i, logical 16B-chunk c8
    const int r0 = tid >> 3, c8 = tid & 7;
    const int physc = c8 ^ (r0 & 7);     // row parity const across i (16i % 8 == 0)

    // ldmatrix lane decomposition
    const int lsub = lane & 7;           // row within 8x8
    const int lh   = (lane >> 3) & 1;    // which 8-row group
    const int lk   = lane >> 4;          // which k8 chunk
    const uint32_t sbase = (uint32_t)__cvta_generic_to_shared(smem);
    const uint32_t rowoff = (uint32_t)((lh * 8 + lsub) * 128);  // bytes

    float acc[4][8][4];
    #pragma unroll
    for (int i = 0; i < 4; ++i)
        #pragma unroll
        for (int j = 0; j < 8; ++j)
            #pragma unroll
            for (int e = 0; e < 4; ++e) acc[i][j][e] = 0.f;

    auto issue = [&](int st, int kt) {
        __half* sb = smem + st * STAGE_H;
        #pragma unroll
        for (int i = 0; i < 8; ++i) {
            int r = r0 + i * 16;
            cp16(sb + r * 64 + physc * 8,
                 A  + (size_t)(bm + r) * K + kt * 64 + c8 * 8);
            cp16(sb + 8192 + r * 64 + physc * 8,
                 Wm + (size_t)(bn + r) * K + kt * 64 + c8 * 8);
        }
    };

    issue(0, 0); CP_COMMIT();
    issue(1, 1); CP_COMMIT();

    for (int kt = 0; kt < nK; ++kt) {
        CP_WAIT1();
        __syncthreads();
        int kn = kt + 2;
        if (kn < nK) issue(kn % 3, kn);
        CP_COMMIT();

        const uint32_t As = sbase + (kt % 3) * (STAGE_H * 2);
        const uint32_t Bs = As + 16384;

        #pragma unroll
        for (int j = 0; j < 4; ++j) {
            const uint32_t ck = (uint32_t)((((2 * j + lk) ^ lsub)) * 16);
            uint32_t a[4][4], bb[4][4];
            #pragma unroll
            for (int mi = 0; mi < 4; ++mi)
                LDMX4(a[mi], As + (uint32_t)((wm + mi * 16) * 128) + rowoff + ck);
            #pragma unroll
            for (int np = 0; np < 4; ++np)
                LDMX4(bb[np], Bs + (uint32_t)((wn + np * 16) * 128) + rowoff + ck);
            #pragma unroll
            for (int mi = 0; mi < 4; ++mi) {
                #pragma unroll
                for (int np = 0; np < 4; ++np) {
                    uint32_t b0[2] = { bb[np][0], bb[np][2] };
                    uint32_t b1[2] = { bb[np][1], bb[np][3] };
                    mma_f16(acc[mi][2 * np],     a[mi], b0);
                    mma_f16(acc[mi][2 * np + 1], a[mi], b1);
                }
            }
        }
    }

    // epilogue
    #pragma unroll
    for (int mi = 0; mi < 4; ++mi) {
        #pragma unroll
        for (int ni = 0; ni < 8; ++ni) {
            int c = bn + wn + ni * 8 + tq * 2;
            float2 bv = *(const float2*)(bias + c);
            #pragma unroll
            for (int half = 0; half < 2; ++half) {
                int r = bm + wm + mi * 16 + g + half * 8;
                float v0 = acc[mi][ni][half * 2 + 0] + bv.x;
                float v1 = acc[mi][ni][half * 2 + 1] + bv.y;
                if (MODE == 0) {
                    *(float2*)((float*)outv + (size_t)r * N + c) = make_float2(v0, v1);
                } else if (MODE == 1) {
                    *(__half2*)((__half*)outv + (size_t)r * N + c) =
                        __floats2half2_rn(gelu_exact(v0), gelu_exact(v1));
                } else if (MODE == 2) {
                    float2 rv = *(const float2*)(res + (size_t)r * N + c);
                    *(float2*)((float*)outv + (size_t)r * N + c) =
                        make_float2(v0 + rv.x, v1 + rv.y);
                } else {
                    float2 rv = *(const float2*)(res + (size_t)r * N + c);
                    v0 += rv.x; v1 += rv.y;
                    float* out = (float*)outv;
                    int wi = r >> 4, tt = r & 15;
                    int bb2 = wi >> 6, wh = (wi >> 3) & 7, ww = wi & 7;
                    int hh = wh * 4 + (tt >> 2), wc = ww * 4 + (tt & 3);
                    out[(((size_t)bb2 * C_ + c)     * H_ + hh) * W_ + wc] = v0;
                    out[(((size_t)bb2 * C_ + c + 1) * H_ + hh) * W_ + wc] = v1;
                }
            }
        }
    }
}

// ===================================================================
// Kernel 1: transpose [B,C,H,W] -> token rows (window-major), LN1
// xh fp32 residual; xn fp16 GEMM input
// ===================================================================
__global__ void __launch_bounds__(256) ln1_kernel(
    const float* __restrict__ x, const float* __restrict__ nw,
    const float* __restrict__ nb, float* __restrict__ xh, __half* __restrict__ xn)
{
    extern __shared__ float tile[];  // [32][513]
    __shared__ float s_sum[32], s_sq[32], s_mean[32], s_rstd[32];
    int bidx = blockIdx.x;
    int bb = bidx >> 5, h = bidx & 31;
    int t = threadIdx.x;
    if (t < 32) { s_sum[t] = 0.f; s_sq[t] = 0.f; }
    __syncthreads();

    const float* xp = x + ((size_t)bb * C_) * (H_ * W_) + (size_t)h * W_;
    float lsum = 0.f, lsq = 0.f;
    for (int idx = t; idx < C_ * 32; idx += 256) {
        int c = idx >> 5, ww = idx & 31;
        float v = xp[(size_t)c * (H_ * W_) + ww];
        tile[ww * 513 + c] = v;
        lsum += v; lsq += v * v;
    }
    atomicAdd(&s_sum[t & 31], lsum);
    atomicAdd(&s_sq [t & 31], lsq);
    __syncthreads();
    if (t < 32) {
        float m = s_sum[t] * (1.f / C_);
        float v = s_sq[t] * (1.f / C_) - m * m;
        s_mean[t] = m; s_rstd[t] = rsqrtf(v + EPS_);
    }
    __syncthreads();

    int wh = h >> 2, i = h & 3;
    for (int idx = t; idx < 32 * C_; idx += 256) {
        int ww = idx >> 9, c = idx & (C_ - 1);
        int wwi = ww >> 2, j = ww & 3;
        int wid = (bb * 8 + wh) * 8 + wwi;
        size_t r = (size_t)wid * NTOK + i * 4 + j;
        float v = tile[ww * 513 + c];
        xh[r * C_ + c] = v;
        xn[r * C_ + c] = __float2half((v - s_mean[ww]) * s_rstd[ww] * nw[c] + nb[c]);
    }
}

// ===================================================================
// windowed attention: reads fp32 qkv, writes fp16 ctx
// ===================================================================
__global__ void __launch_bounds__(128) attn_kernel(
    const float* __restrict__ qkv, const float* __restrict__ rpb,
    __half* __restrict__ ctx)
{
    int w    = blockIdx.x;
    int lane = threadIdx.x & 31;
    int warp = threadIdx.x >> 5;
    int n    = lane & 15;
    int hh   = lane >> 4;
    const float scale = 0.17677669529663687f;
    size_t base = (size_t)w * NTOK * (3 * C_);

    #pragma unroll
    for (int it = 0; it < 2; ++it) {
        int head = warp * 4 + it * 2 + hh;
        float4 q[8];
        const float4* qp = (const float4*)(qkv + base + (size_t)n * (3 * C_) + head * HD_);
        #pragma unroll
        for (int i = 0; i < 8; ++i) {
            q[i] = qp[i];
            q[i].x *= scale; q[i].y *= scale; q[i].z *= scale; q[i].w *= scale;
        }
        float s[16];
        int i1 = n >> 2, j1 = n & 3;
        #pragma unroll
        for (int m = 0; m < 16; ++m) {
            const float4* kp = (const float4*)(qkv + base + (size_t)m * (3 * C_) + C_ + head * HD_);
            float acc = 0.f;
            #pragma unroll
            for (int i = 0; i < 8; ++i) {
                float4 kv = kp[i];
                acc += q[i].x * kv.x + q[i].y * kv.y + q[i].z * kv.z + q[i].w * kv.w;
            }
            int i2 = m >> 2, j2 = m & 3;
            int ridx = (i1 - i2 + 3) * 7 + (j1 - j2 + 3);
            s[m] = acc + rpb[ridx * NH_ + head];
        }
        float mx = s[0];
        #pragma unroll
        for (int m = 1; m < 16; ++m) mx = fmaxf(mx, s[m]);
        float sum = 0.f;
        #pragma unroll
        for (int m = 0; m < 16; ++m) { s[m] = expf(s[m] - mx); sum += s[m]; }
        float inv = 1.f / sum;
        float4 o[8];
        #pragma unroll
        for (int i = 0; i < 8; ++i) { o[i].x = 0.f; o[i].y = 0.f; o[i].z = 0.f; o[i].w = 0.f; }
        #pragma unroll
        for (int m = 0; m < 16; ++m) {
            float p = s[m] * inv;
            const float4* vp = (const float4*)(qkv + base + (size_t)m * (3 * C_) + 2 * C_ + head * HD_);
            #pragma unroll
            for (int i = 0; i < 8; ++i) {
                float4 vv = vp[i];
                o[i].x += p * vv.x; o[i].y += p * vv.y; o[i].z += p * vv.z; o[i].w += p * vv.w;
            }
        }
        __half2* op = (__half2*)(ctx + (size_t)(w * NTOK + n) * C_ + head * HD_);
        #pragma unroll
        for (int i = 0; i < 8; ++i) {
            op[2 * i]     = __floats2half2_rn(o[i].x, o[i].y);
            op[2 * i + 1] = __floats2half2_rn(o[i].z, o[i].w);
        }
    }
}

// ===================================================================
// LN2: fp32 in, fp16 out
// ===================================================================
__global__ void __launch_bounds__(128) ln2_kernel(
    const float* __restrict__ in, const float* __restrict__ nw,
    const float* __restrict__ nb, __half* __restrict__ outp)
{
    int r = blockIdx.x;
    int t = threadIdx.x;
    int lane = t & 31, warp = t >> 5;
    float4 v = ((const float4*)(in + (size_t)r * C_))[t];
    float ls = v.x + v.y + v.z + v.w;
    float lq = v.x*v.x + v.y*v.y + v.z*v.z + v.w*v.w;
    #pragma unroll
    for (int off = 16; off; off >>= 1) {
        ls += __shfl_down_sync(0xffffffffu, ls, off);
        lq += __shfl_down_sync(0xffffffffu, lq, off);
    }
    __shared__ float ss[4], sq2[4];
    __shared__ float sm, sr;
    if (lane == 0) { ss[warp] = ls; sq2[warp] = lq; }
    __syncthreads();
    if (t == 0) {
        float S = ss[0] + ss[1] + ss[2] + ss[3];
        float Q = sq2[0] + sq2[1] + sq2[2] + sq2[3];
        float m = S * (1.f / C_);
        float var = Q * (1.f / C_) - m * m;
        sm = m; sr = rsqrtf(var + EPS_);
    }
    __syncthreads();
    float m = sm, rs = sr;
    float4 wv = ((const float4*)nw)[t];
    float4 bv = ((const float4*)nb)[t];
    float o0 = (v.x - m) * rs * wv.x + bv.x;
    float o1 = (v.y - m) * rs * wv.y + bv.y;
    float o2 = (v.z - m) * rs * wv.z + bv.z;
    float o3 = (v.w - m) * rs * wv.w + bv.w;
    __half2* op = (__half2*)(outp + (size_t)r * C_ + t * 4);
    op[0] = __floats2half2_rn(o0, o1);
    op[1] = __floats2half2_rn(o2, o3);
}

// ===================================================================
// host launch
// ===================================================================
extern "C" void kernel_launch(void* const* d_in, const int* in_sizes, int n_in,
                              void* d_out, int out_size)
{
    const float* x     = (const float*)d_in[0];
    const float* n1w   = (const float*)d_in[1];
    const float* n1b   = (const float*)d_in[2];
    const float* qkvw  = (const float*)d_in[3];
    const float* qkvb  = (const float*)d_in[4];
    const float* rpb   = (const float*)d_in[5];
    const float* projw = (const float*)d_in[6];
    const float* projb = (const float*)d_in[7];
    const float* n2w   = (const float*)d_in[8];
    const float* n2b   = (const float*)d_in[9];
    const float* w1    = (const float*)d_in[10];
    const float* b1    = (const float*)d_in[11];
    const float* w2    = (const float*)d_in[12];
    const float* b2    = (const float*)d_in[13];
    float* out = (float*)d_out;

    float *xh, *qkvp, *xh2;
    __half *xn_h, *ctx_h, *hn_h, *h1_h, *wq_h, *wp_h, *w1_h, *w2_h;
    cudaGetSymbolAddress((void**)&xh,    g_xh);
    cudaGetSymbolAddress((void**)&qkvp,  g_qkv);
    cudaGetSymbolAddress((void**)&xh2,   g_xh2);
    cudaGetSymbolAddress((void**)&xn_h,  g_xn_h);
    cudaGetSymbolAddress((void**)&ctx_h, g_ctx_h);
    cudaGetSymbolAddress((void**)&hn_h,  g_hn_h);
    cudaGetSymbolAddress((void**)&h1_h,  g_h1_h);
    cudaGetSymbolAddress((void**)&wq_h,  g_wq_h);
    cudaGetSymbolAddress((void**)&wp_h,  g_wp_h);
    cudaGetSymbolAddress((void**)&w1_h,  g_w1_h);
    cudaGetSymbolAddress((void**)&w2_h,  g_w2_h);

    int ln1_smem = 32 * 513 * 4;
    cudaFuncSetAttribute(ln1_kernel, cudaFuncAttributeMaxDynamicSharedMemorySize, ln1_smem);
    cudaFuncSetAttribute(gemm_h<0>, cudaFuncAttributeMaxDynamicSharedMemorySize, GSMEM);
    cudaFuncSetAttribute(gemm_h<1>, cudaFuncAttributeMaxDynamicSharedMemorySize, GSMEM);
    cudaFuncSetAttribute(gemm_h<2>, cudaFuncAttributeMaxDynamicSharedMemorySize, GSMEM);
    cudaFuncSetAttribute(gemm_h<3>, cudaFuncAttributeMaxDynamicSharedMemorySize, GSMEM);

    // 0. weight conversion fp32 -> fp16
    f2h_kernel<<<(3 * C_ * C_ / 4 + 255) / 256, 256>>>(qkvw, wq_h, 3 * C_ * C_);
    f2h_kernel<<<(C_ * C_ / 4 + 255) / 256, 256>>>(projw, wp_h, C_ * C_);
    f2h_kernel<<<(MLPH * C_ / 4 + 255) / 256, 256>>>(w1, w1_h, MLPH * C_);
    f2h_kernel<<<(C_ * MLPH / 4 + 255) / 256, 256>>>(w2, w2_h, C_ * MLPH);

    // 1. transpose + LN1
    ln1_kernel<<<B_ * H_, 256, ln1_smem>>>(x, n1w, n1b, xh, xn_h);

    // 2. QKV projection -> fp32 qkv
    gemm_h<0><<<dim3((3 * C_) / 128, T_ / 128), 128, GSMEM>>>(
        xn_h, wq_h, qkvb, nullptr, qkvp, T_, 3 * C_, C_);

    // 3. window attention -> fp16 ctx
    attn_kernel<<<T_ / NTOK, 128>>>(qkvp, rpb, ctx_h);

    // 4. proj + bias + residual -> fp32 xh2
    gemm_h<2><<<dim3(C_ / 128, T_ / 128), 128, GSMEM>>>(
        ctx_h, wp_h, projb, xh, xh2, T_, C_, C_);

    // 5. LN2 -> fp16 hn
    ln2_kernel<<<T_, 128>>>(xh2, n2w, n2b, hn_h);

    // 6. MLP1 + bias + GELU -> fp16 h1
    gemm_h<1><<<dim3(MLPH / 128, T_ / 128), 128, GSMEM>>>(
        hn_h, w1_h, b1, nullptr, h1_h, T_, MLPH, C_);

    // 7. MLP2 + bias + residual + un-permute to [B,C,H,W]
    gemm_h<3><<<dim3(C_ / 128, T_ / 128), 128, GSMEM>>>(
        h1_h, w2_h, b2, xh2, out, T_, C_, MLPH);
}

// round 7
// speedup vs baseline: 3.1919x; 1.0101x over previous
#include <cuda_runtime.h>
#include <cuda_fp16.h>
#include <cstdint>
#include <cstdio>

// ---------------- problem constants ----------------
#define B_   32
#define C_   512
#define H_   32
#define W_   32
#define NH_  16
#define WS_  4
#define HD_  32
#define NTOK 16
#define T_   32768
#define MLPH 2048
#define EPS_ 1e-5f

// ---------------- scratch (device globals; no allocs allowed) ----------------
__device__ float  g_xh  [ (size_t)T_ * C_ ];      // residual (window-major)
__device__ float  g_xh2 [ (size_t)T_ * C_ ];      // after proj + residual
__device__ __half g_qkv_h[ (size_t)T_ * 3 * C_ ]; // fp16 qkv
__device__ __half g_xn_h [ (size_t)T_ * C_ ];     // LN1 out (fp16)
__device__ __half g_ctx_h[ (size_t)T_ * C_ ];     // attn context (fp16)
__device__ __half g_hn_h [ (size_t)T_ * C_ ];     // LN2 out (fp16)
__device__ __half g_h1_h [ (size_t)T_ * MLPH ];   // MLP hidden (fp16)
__device__ __half g_wq_h [ (size_t)3 * C_ * C_ ];
__device__ __half g_wp_h [ (size_t)C_ * C_ ];
__device__ __half g_w1_h [ (size_t)MLPH * C_ ];
__device__ __half g_w2_h [ (size_t)C_ * MLPH ];

// ---------------- helpers ----------------
__device__ __forceinline__ void mma_f16(float* c, const uint32_t* a, const uint32_t* b) {
    asm volatile("mma.sync.aligned.m16n8k16.row.col.f32.f16.f16.f32 "
        "{%0,%1,%2,%3}, {%4,%5,%6,%7}, {%8,%9}, {%0,%1,%2,%3};\n"
        : "+f"(c[0]), "+f"(c[1]), "+f"(c[2]), "+f"(c[3])
        : "r"(a[0]), "r"(a[1]), "r"(a[2]), "r"(a[3]),
          "r"(b[0]), "r"(b[1]));
}

#define LDMX4(r, addr) \
    asm volatile("ldmatrix.sync.aligned.m8n8.x4.shared.b16 {%0,%1,%2,%3}, [%4];" \
        : "=r"((r)[0]), "=r"((r)[1]), "=r"((r)[2]), "=r"((r)[3]) : "r"(addr))

__device__ __forceinline__ void cp16(const void* sdst, const void* gsrc) {
    uint32_t s = (uint32_t)__cvta_generic_to_shared(sdst);
    asm volatile("cp.async.cg.shared.global [%0], [%1], 16;\n" :: "r"(s), "l"(gsrc));
}
#define CP_COMMIT() asm volatile("cp.async.commit_group;\n" ::: "memory")
#define CP_WAIT1()  asm volatile("cp.async.wait_group 1;\n" ::: "memory")

__device__ __forceinline__ float gelu_exact(float x) {
    return 0.5f * x * (1.0f + erff(x * 0.7071067811865475f));
}

// load 32 halves (64B) -> 32 floats
__device__ __forceinline__ void ld32h(const __half* p, float* f) {
    const uint4* u = (const uint4*)p;
    #pragma unroll
    for (int c = 0; c < 4; ++c) {
        uint4 x = u[c];
        uint32_t w[4] = { x.x, x.y, x.z, x.w };
        #pragma unroll
        for (int k = 0; k < 4; ++k) {
            float2 d = __half22float2(*(__half2*)&w[k]);
            f[c * 8 + k * 2 + 0] = d.x;
            f[c * 8 + k * 2 + 1] = d.y;
        }
    }
}

// ===================================================================
// fp32 -> fp16 conversion (weights)
// ===================================================================
__global__ void f2h_kernel(const float* __restrict__ s, __half* __restrict__ d, int n) {
    int i = (blockIdx.x * blockDim.x + threadIdx.x) * 4;
    if (i < n) {
        float4 v = *(const float4*)(s + i);
        __half2* dp = (__half2*)(d + i);
        dp[0] = __floats2half2_rn(v.x, v.y);
        dp[1] = __floats2half2_rn(v.z, v.w);
    }
}

// ===================================================================
// fp16 GEMM: Out[M,N] = A[M,K] @ W[N,K]^T + epilogue
// CTA 128x128, 256 thr = 8 warps (2m x 4n), warp tile 64x32.
// BK=64 halves (128B rows), SW128 chunk-XOR swizzle, 3-stage cp.async
// ring, ldmatrix.x4 fragment loads, mma.m16n8k16.f16 (fp32 accum).
// MODE 0:+bias fp32 | 1:gelu(+bias) fp16 | 2:+bias+res fp32 |
//      3:+bias+res permuted fp32 | 4:+bias fp16
// ===================================================================
#define STAGE_H 16384            // halves per stage: A 8192 + B 8192 (32 KB)
#define GSMEM   (3 * STAGE_H * 2)    // 96 KB

template<int MODE>
__global__ void __launch_bounds__(256, 2) gemm_h(
    const __half* __restrict__ A, const __half* __restrict__ Wm,
    const float* __restrict__ bias, const float* __restrict__ res,
    void* __restrict__ outv, int M, int N, int K)
{
    extern __shared__ __half smem[];

    const int tid  = threadIdx.x;
    const int lane = tid & 31, warp = tid >> 5;
    const int bm   = blockIdx.y * 128;
    const int bn   = blockIdx.x * 128;
    const int wm   = (warp & 1) * 64;
    const int wn   = (warp >> 1) * 32;
    const int tq   = lane & 3, g = lane >> 2;
    const int nK   = K >> 6;

    // cp.async store mapping: rows r0+32i (i<4), logical 16B-chunk c8
    const int r0 = tid >> 3, c8 = tid & 7;
    const int physc = c8 ^ (r0 & 7);     // row parity const across i (32i % 8 == 0)

    // ldmatrix lane decomposition
    const int lsub = lane & 7;
    const int lh   = (lane >> 3) & 1;
    const int lk   = lane >> 4;
    const uint32_t sbase = (uint32_t)__cvta_generic_to_shared(smem);
    const uint32_t rowoff = (uint32_t)((lh * 8 + lsub) * 128);

    float acc[4][4][4];
    #pragma unroll
    for (int i = 0; i < 4; ++i)
        #pragma unroll
        for (int j = 0; j < 4; ++j)
            #pragma unroll
            for (int e = 0; e < 4; ++e) acc[i][j][e] = 0.f;

    auto issue = [&](int st, int kt) {
        __half* sb = smem + st * STAGE_H;
        #pragma unroll
        for (int i = 0; i < 4; ++i) {
            int r = r0 + i * 32;
            cp16(sb + r * 64 + physc * 8,
                 A  + (size_t)(bm + r) * K + kt * 64 + c8 * 8);
            cp16(sb + 8192 + r * 64 + physc * 8,
                 Wm + (size_t)(bn + r) * K + kt * 64 + c8 * 8);
        }
    };

    issue(0, 0); CP_COMMIT();
    issue(1, 1); CP_COMMIT();

    for (int kt = 0; kt < nK; ++kt) {
        CP_WAIT1();
        __syncthreads();
        int kn = kt + 2;
        if (kn < nK) issue(kn % 3, kn);
        CP_COMMIT();

        const uint32_t As = sbase + (kt % 3) * (STAGE_H * 2);
        const uint32_t Bs = As + 16384;

        #pragma unroll
        for (int j = 0; j < 4; ++j) {
            const uint32_t ck = (uint32_t)((((2 * j + lk) ^ lsub)) * 16);
            uint32_t a[4][4], bb[2][4];
            #pragma unroll
            for (int mi = 0; mi < 4; ++mi)
                LDMX4(a[mi], As + (uint32_t)((wm + mi * 16) * 128) + rowoff + ck);
            #pragma unroll
            for (int np = 0; np < 2; ++np)
                LDMX4(bb[np], Bs + (uint32_t)((wn + np * 16) * 128) + rowoff + ck);
            #pragma unroll
            for (int mi = 0; mi < 4; ++mi) {
                #pragma unroll
                for (int np = 0; np < 2; ++np) {
                    uint32_t b0[2] = { bb[np][0], bb[np][2] };
                    uint32_t b1[2] = { bb[np][1], bb[np][3] };
                    mma_f16(acc[mi][2 * np],     a[mi], b0);
                    mma_f16(acc[mi][2 * np + 1], a[mi], b1);
                }
            }
        }
    }

    // epilogue
    #pragma unroll
    for (int mi = 0; mi < 4; ++mi) {
        #pragma unroll
        for (int ni = 0; ni < 4; ++ni) {
            int c = bn + wn + ni * 8 + tq * 2;
            float2 bv = *(const float2*)(bias + c);
            #pragma unroll
            for (int half = 0; half < 2; ++half) {
                int r = bm + wm + mi * 16 + g + half * 8;
                float v0 = acc[mi][ni][half * 2 + 0] + bv.x;
                float v1 = acc[mi][ni][half * 2 + 1] + bv.y;
                if (MODE == 0) {
                    *(float2*)((float*)outv + (size_t)r * N + c) = make_float2(v0, v1);
                } else if (MODE == 1) {
                    *(__half2*)((__half*)outv + (size_t)r * N + c) =
                        __floats2half2_rn(gelu_exact(v0), gelu_exact(v1));
                } else if (MODE == 2) {
                    float2 rv = *(const float2*)(res + (size_t)r * N + c);
                    *(float2*)((float*)outv + (size_t)r * N + c) =
                        make_float2(v0 + rv.x, v1 + rv.y);
                } else if (MODE == 4) {
                    *(__half2*)((__half*)outv + (size_t)r * N + c) =
                        __floats2half2_rn(v0, v1);
                } else {
                    float2 rv = *(const float2*)(res + (size_t)r * N + c);
                    v0 += rv.x; v1 += rv.y;
                    float* out = (float*)outv;
                    int wi = r >> 4, tt = r & 15;
                    int bb2 = wi >> 6, wh = (wi >> 3) & 7, ww = wi & 7;
                    int hh = wh * 4 + (tt >> 2), wc = ww * 4 + (tt & 3);
                    out[(((size_t)bb2 * C_ + c)     * H_ + hh) * W_ + wc] = v0;
                    out[(((size_t)bb2 * C_ + c + 1) * H_ + hh) * W_ + wc] = v1;
                }
            }
        }
    }
}

// ===================================================================
// Kernel 1: transpose [B,C,H,W] -> token rows (window-major), LN1
// ===================================================================
__global__ void __launch_bounds__(256) ln1_kernel(
    const float* __restrict__ x, const float* __restrict__ nw,
    const float* __restrict__ nb, float* __restrict__ xh, __half* __restrict__ xn)
{
    extern __shared__ float tile[];  // [32][513]
    __shared__ float s_sum[32], s_sq[32], s_mean[32], s_rstd[32];
    int bidx = blockIdx.x;
    int bb = bidx >> 5, h = bidx & 31;
    int t = threadIdx.x;
    if (t < 32) { s_sum[t] = 0.f; s_sq[t] = 0.f; }
    __syncthreads();

    const float* xp = x + ((size_t)bb * C_) * (H_ * W_) + (size_t)h * W_;
    float lsum = 0.f, lsq = 0.f;
    for (int idx = t; idx < C_ * 32; idx += 256) {
        int c = idx >> 5, ww = idx & 31;
        float v = xp[(size_t)c * (H_ * W_) + ww];
        tile[ww * 513 + c] = v;
        lsum += v; lsq += v * v;
    }
    atomicAdd(&s_sum[t & 31], lsum);
    atomicAdd(&s_sq [t & 31], lsq);
    __syncthreads();
    if (t < 32) {
        float m = s_sum[t] * (1.f / C_);
        float v = s_sq[t] * (1.f / C_) - m * m;
        s_mean[t] = m; s_rstd[t] = rsqrtf(v + EPS_);
    }
    __syncthreads();

    int wh = h >> 2, i = h & 3;
    for (int idx = t; idx < 32 * C_; idx += 256) {
        int ww = idx >> 9, c = idx & (C_ - 1);
        int wwi = ww >> 2, j = ww & 3;
        int wid = (bb * 8 + wh) * 8 + wwi;
        size_t r = (size_t)wid * NTOK + i * 4 + j;
        float v = tile[ww * 513 + c];
        xh[r * C_ + c] = v;
        xn[r * C_ + c] = __float2half((v - s_mean[ww]) * s_rstd[ww] * nw[c] + nb[c]);
    }
}

// ===================================================================
// windowed attention: fp16 qkv in, fp16 ctx out, fp32 math
// ===================================================================
__global__ void __launch_bounds__(128) attn_kernel(
    const __half* __restrict__ qkv, const float* __restrict__ rpb,
    __half* __restrict__ ctx)
{
    int w    = blockIdx.x;
    int lane = threadIdx.x & 31;
    int warp = threadIdx.x >> 5;
    int n    = lane & 15;
    int hh   = lane >> 4;
    const float scale = 0.17677669529663687f;
    size_t base = (size_t)w * NTOK * (3 * C_);

    #pragma unroll
    for (int it = 0; it < 2; ++it) {
        int head = warp * 4 + it * 2 + hh;

        float q[32];
        ld32h(qkv + base + (size_t)n * (3 * C_) + head * HD_, q);
        #pragma unroll
        for (int i = 0; i < 32; ++i) q[i] *= scale;

        float s[16];
        int i1 = n >> 2, j1 = n & 3;
        #pragma unroll
        for (int m = 0; m < 16; ++m) {
            float kf[32];
            ld32h(qkv + base + (size_t)m * (3 * C_) + C_ + head * HD_, kf);
            float acc = 0.f;
            #pragma unroll
            for (int i = 0; i < 32; ++i) acc += q[i] * kf[i];
            int i2 = m >> 2, j2 = m & 3;
            int ridx = (i1 - i2 + 3) * 7 + (j1 - j2 + 3);
            s[m] = acc + rpb[ridx * NH_ + head];
        }

        float mx = s[0];
        #pragma unroll
        for (int m = 1; m < 16; ++m) mx = fmaxf(mx, s[m]);
        float sum = 0.f;
        #pragma unroll
        for (int m = 0; m < 16; ++m) { s[m] = expf(s[m] - mx); sum += s[m]; }
        float inv = 1.f / sum;

        float o[32];
        #pragma unroll
        for (int i = 0; i < 32; ++i) o[i] = 0.f;
        #pragma unroll
        for (int m = 0; m < 16; ++m) {
            float p = s[m] * inv;
            float vf[32];
            ld32h(qkv + base + (size_t)m * (3 * C_) + 2 * C_ + head * HD_, vf);
            #pragma unroll
            for (int i = 0; i < 32; ++i) o[i] += p * vf[i];
        }
        __half2* op = (__half2*)(ctx + (size_t)(w * NTOK + n) * C_ + head * HD_);
        #pragma unroll
        for (int i = 0; i < 16; ++i)
            op[i] = __floats2half2_rn(o[2 * i], o[2 * i + 1]);
    }
}

// ===================================================================
// LN2: fp32 in, fp16 out
// ===================================================================
__global__ void __launch_bounds__(128) ln2_kernel(
    const float* __restrict__ in, const float* __restrict__ nw,
    const float* __restrict__ nb, __half* __restrict__ outp)
{
    int r = blockIdx.x;
    int t = threadIdx.x;
    int lane = t & 31, warp = t >> 5;
    float4 v = ((const float4*)(in + (size_t)r * C_))[t];
    float ls = v.x + v.y + v.z + v.w;
    float lq = v.x*v.x + v.y*v.y + v.z*v.z + v.w*v.w;
    #pragma unroll
    for (int off = 16; off; off >>= 1) {
        ls += __shfl_down_sync(0xffffffffu, ls, off);
        lq += __shfl_down_sync(0xffffffffu, lq, off);
    }
    __shared__ float ss[4], sq2[4];
    __shared__ float sm, sr;
    if (lane == 0) { ss[warp] = ls; sq2[warp] = lq; }
    __syncthreads();
    if (t == 0) {
        float S = ss[0] + ss[1] + ss[2] + ss[3];
        float Q = sq2[0] + sq2[1] + sq2[2] + sq2[3];
        float m = S * (1.f / C_);
        float var = Q * (1.f / C_) - m * m;
        sm = m; sr = rsqrtf(var + EPS_);
    }
    __syncthreads();
    float m = sm, rs = sr;
    float4 wv = ((const float4*)nw)[t];
    float4 bv = ((const float4*)nb)[t];
    float o0 = (v.x - m) * rs * wv.x + bv.x;
    float o1 = (v.y - m) * rs * wv.y + bv.y;
    float o2 = (v.z - m) * rs * wv.z + bv.z;
    float o3 = (v.w - m) * rs * wv.w + bv.w;
    __half2* op = (__half2*)(outp + (size_t)r * C_ + t * 4);
    op[0] = __floats2half2_rn(o0, o1);
    op[1] = __floats2half2_rn(o2, o3);
}

// ===================================================================
// host launch
// ===================================================================
extern "C" void kernel_launch(void* const* d_in, const int* in_sizes, int n_in,
                              void* d_out, int out_size)
{
    const float* x     = (const float*)d_in[0];
    const float* n1w   = (const float*)d_in[1];
    const float* n1b   = (const float*)d_in[2];
    const float* qkvw  = (const float*)d_in[3];
    const float* qkvb  = (const float*)d_in[4];
    const float* rpb   = (const float*)d_in[5];
    const float* projw = (const float*)d_in[6];
    const float* projb = (const float*)d_in[7];
    const float* n2w   = (const float*)d_in[8];
    const float* n2b   = (const float*)d_in[9];
    const float* w1    = (const float*)d_in[10];
    const float* b1    = (const float*)d_in[11];
    const float* w2    = (const float*)d_in[12];
    const float* b2    = (const float*)d_in[13];
    float* out = (float*)d_out;

    float *xh, *xh2;
    __half *qkv_h, *xn_h, *ctx_h, *hn_h, *h1_h, *wq_h, *wp_h, *w1_h, *w2_h;
    cudaGetSymbolAddress((void**)&xh,    g_xh);
    cudaGetSymbolAddress((void**)&xh2,   g_xh2);
    cudaGetSymbolAddress((void**)&qkv_h, g_qkv_h);
    cudaGetSymbolAddress((void**)&xn_h,  g_xn_h);
    cudaGetSymbolAddress((void**)&ctx_h, g_ctx_h);
    cudaGetSymbolAddress((void**)&hn_h,  g_hn_h);
    cudaGetSymbolAddress((void**)&h1_h,  g_h1_h);
    cudaGetSymbolAddress((void**)&wq_h,  g_wq_h);
    cudaGetSymbolAddress((void**)&wp_h,  g_wp_h);
    cudaGetSymbolAddress((void**)&w1_h,  g_w1_h);
    cudaGetSymbolAddress((void**)&w2_h,  g_w2_h);

    int ln1_smem = 32 * 513 * 4;
    cudaFuncSetAttribute(ln1_kernel, cudaFuncAttributeMaxDynamicSharedMemorySize, ln1_smem);
    cudaFuncSetAttribute(gemm_h<1>, cudaFuncAttributeMaxDynamicSharedMemorySize, GSMEM);
    cudaFuncSetAttribute(gemm_h<2>, cudaFuncAttributeMaxDynamicSharedMemorySize, GSMEM);
    cudaFuncSetAttribute(gemm_h<3>, cudaFuncAttributeMaxDynamicSharedMemorySize, GSMEM);
    cudaFuncSetAttribute(gemm_h<4>, cudaFuncAttributeMaxDynamicSharedMemorySize, GSMEM);

    // 0. weight conversion fp32 -> fp16
    f2h_kernel<<<(3 * C_ * C_ / 4 + 255) / 256, 256>>>(qkvw, wq_h, 3 * C_ * C_);
    f2h_kernel<<<(C_ * C_ / 4 + 255) / 256, 256>>>(projw, wp_h, C_ * C_);
    f2h_kernel<<<(MLPH * C_ / 4 + 255) / 256, 256>>>(w1, w1_h, MLPH * C_);
    f2h_kernel<<<(C_ * MLPH / 4 + 255) / 256, 256>>>(w2, w2_h, C_ * MLPH);

    // 1. transpose + LN1
    ln1_kernel<<<B_ * H_, 256, ln1_smem>>>(x, n1w, n1b, xh, xn_h);

    // 2. QKV projection -> fp16 qkv
    gemm_h<4><<<dim3((3 * C_) / 128, T_ / 128), 256, GSMEM>>>(
        xn_h, wq_h, qkvb, nullptr, qkv_h, T_, 3 * C_, C_);

    // 3. window attention -> fp16 ctx
    attn_kernel<<<T_ / NTOK, 128>>>(qkv_h, rpb, ctx_h);

    // 4. proj + bias + residual -> fp32 xh2
    gemm_h<2><<<dim3(C_ / 128, T_ / 128), 256, GSMEM>>>(
        ctx_h, wp_h, projb, xh, xh2, T_, C_, C_);

    // 5. LN2 -> fp16 hn
    ln2_kernel<<<T_, 128>>>(xh2, n2w, n2b, hn_h);

    // 6. MLP1 + bias + GELU -> fp16 h1
    gemm_h<1><<<dim3(MLPH / 128, T_ / 128), 256, GSMEM>>>(
        hn_h, w1_h, b1, nullptr, h1_h, T_, MLPH, C_);

    // 7. MLP2 + bias + residual + un-permute to [B,C,H,W]
    gemm_h<3><<<dim3(C_ / 128, T_ / 128), 256, GSMEM>>>(
        h1_h, w2_h, b2, xh2, out, T_, C_, MLPH);
}

// round 8
// speedup vs baseline: 3.2377x; 1.0144x over previous
#include <cuda_runtime.h>
#include <cuda_fp16.h>
#include <cstdint>
#include <cstdio>

// ---------------- problem constants ----------------
#define B_   32
#define C_   512
#define H_   32
#define W_   32
#define NH_  16
#define WS_  4
#define HD_  32
#define NTOK 16
#define T_   32768
#define MLPH 2048
#define EPS_ 1e-5f

// ---------------- scratch (device globals; no allocs allowed) ----------------
__device__ float  g_xh  [ (size_t)T_ * C_ ];      // residual (window-major)
__device__ float  g_xh2 [ (size_t)T_ * C_ ];      // after proj + residual
__device__ __half g_qkv_h[ (size_t)T_ * 3 * C_ ]; // fp16 qkv
__device__ __half g_xn_h [ (size_t)T_ * C_ ];     // LN1 out (fp16)
__device__ __half g_ctx_h[ (size_t)T_ * C_ ];     // attn context (fp16)
__device__ __half g_hn_h [ (size_t)T_ * C_ ];     // LN2 out (fp16)
__device__ __half g_h1_h [ (size_t)T_ * MLPH ];   // MLP hidden (fp16)
__device__ __half g_wq_h [ (size_t)3 * C_ * C_ ];
__device__ __half g_wp_h [ (size_t)C_ * C_ ];
__device__ __half g_w1_h [ (size_t)MLPH * C_ ];
__device__ __half g_w2_h [ (size_t)C_ * MLPH ];

// ---------------- helpers ----------------
__device__ __forceinline__ void mma_f16(float* c, const uint32_t* a, const uint32_t* b) {
    asm volatile("mma.sync.aligned.m16n8k16.row.col.f32.f16.f16.f32 "
        "{%0,%1,%2,%3}, {%4,%5,%6,%7}, {%8,%9}, {%0,%1,%2,%3};\n"
        : "+f"(c[0]), "+f"(c[1]), "+f"(c[2]), "+f"(c[3])
        : "r"(a[0]), "r"(a[1]), "r"(a[2]), "r"(a[3]),
          "r"(b[0]), "r"(b[1]));
}

#define LDMX4(r, addr) \
    asm volatile("ldmatrix.sync.aligned.m8n8.x4.shared.b16 {%0,%1,%2,%3}, [%4];" \
        : "=r"((r)[0]), "=r"((r)[1]), "=r"((r)[2]), "=r"((r)[3]) : "r"(addr))

__device__ __forceinline__ void cp16(const void* sdst, const void* gsrc) {
    uint32_t s = (uint32_t)__cvta_generic_to_shared(sdst);
    asm volatile("cp.async.cg.shared.global [%0], [%1], 16;\n" :: "r"(s), "l"(gsrc));
}
#define CP_COMMIT() asm volatile("cp.async.commit_group;\n" ::: "memory")
#define CP_WAIT1()  asm volatile("cp.async.wait_group 1;\n" ::: "memory")

__device__ __forceinline__ float gelu_exact(float x) {
    return 0.5f * x * (1.0f + erff(x * 0.7071067811865475f));
}

// load 32 halves (64B) -> 32 floats
__device__ __forceinline__ void ld32h(const __half* p, float* f) {
    const uint4* u = (const uint4*)p;
    #pragma unroll
    for (int c = 0; c < 4; ++c) {
        uint4 x = u[c];
        uint32_t w[4] = { x.x, x.y, x.z, x.w };
        #pragma unroll
        for (int k = 0; k < 4; ++k) {
            float2 d = __half22float2(*(__half2*)&w[k]);
            f[c * 8 + k * 2 + 0] = d.x;
            f[c * 8 + k * 2 + 1] = d.y;
        }
    }
}

// ===================================================================
// fp32 -> fp16 conversion (weights)
// ===================================================================
__global__ void f2h_kernel(const float* __restrict__ s, __half* __restrict__ d, int n) {
    int i = (blockIdx.x * blockDim.x + threadIdx.x) * 4;
    if (i < n) {
        float4 v = *(const float4*)(s + i);
        __half2* dp = (__half2*)(d + i);
        dp[0] = __floats2half2_rn(v.x, v.y);
        dp[1] = __floats2half2_rn(v.z, v.w);
    }
}

// ===================================================================
// fp16 GEMM: Out[M,N] = A[M,K] @ W[N,K]^T + epilogue
// CTA 128x128, 128 thr = 4 warps (2m x 2n), warp tile 64x64.
// BK=64 halves (128B rows), SW128 chunk-XOR swizzle, 3-stage cp.async
// ring, ldmatrix.x4 with FRAGMENT DOUBLE-BUFFERING across the j-loop
// (prefetch j+1 fragments while issuing j's 32 HMMAs), fp32 accum.
// MODE 0:+bias fp32 | 1:gelu(+bias) fp16 | 2:+bias+res fp32 |
//      3:+bias+res permuted fp32 | 4:+bias fp16
// ===================================================================
#define STAGE_H 16384            // halves per stage: A 8192 + B 8192 (32 KB)
#define GSMEM   (3 * STAGE_H * 2)    // 96 KB

template<int MODE>
__global__ void __launch_bounds__(128, 2) gemm_h(
    const __half* __restrict__ A, const __half* __restrict__ Wm,
    const float* __restrict__ bias, const float* __restrict__ res,
    void* __restrict__ outv, int M, int N, int K)
{
    extern __shared__ __half smem[];

    const int tid  = threadIdx.x;
    const int lane = tid & 31, warp = tid >> 5;
    const int bm   = blockIdx.y * 128;
    const int bn   = blockIdx.x * 128;
    const int wm   = (warp & 1) * 64;
    const int wn   = (warp >> 1) * 64;
    const int tq   = lane & 3, g = lane >> 2;
    const int nK   = K >> 6;

    // cp.async store mapping: rows r0+16i (i<8), logical 16B-chunk c8
    const int r0 = tid >> 3, c8 = tid & 7;
    const int physc = c8 ^ (r0 & 7);     // row parity const across i (16i % 8 == 0)

    // ldmatrix lane decomposition
    const int lsub = lane & 7;
    const int lh   = (lane >> 3) & 1;
    const int lk   = lane >> 4;
    const uint32_t sbase = (uint32_t)__cvta_generic_to_shared(smem);
    const uint32_t rowoff = (uint32_t)((lh * 8 + lsub) * 128);

    float acc[4][8][4];
    #pragma unroll
    for (int i = 0; i < 4; ++i)
        #pragma unroll
        for (int j = 0; j < 8; ++j)
            #pragma unroll
            for (int e = 0; e < 4; ++e) acc[i][j][e] = 0.f;

    auto issue = [&](int st, int kt) {
        __half* sb = smem + st * STAGE_H;
        #pragma unroll
        for (int i = 0; i < 8; ++i) {
            int r = r0 + i * 16;
            cp16(sb + r * 64 + physc * 8,
                 A  + (size_t)(bm + r) * K + kt * 64 + c8 * 8);
            cp16(sb + 8192 + r * 64 + physc * 8,
                 Wm + (size_t)(bn + r) * K + kt * 64 + c8 * 8);
        }
    };

    issue(0, 0); CP_COMMIT();
    issue(1, 1); CP_COMMIT();

    uint32_t afr[2][4][4], bfr[2][4][4];

    for (int kt = 0; kt < nK; ++kt) {
        CP_WAIT1();
        __syncthreads();
        int kn = kt + 2;
        if (kn < nK) issue(kn % 3, kn);
        CP_COMMIT();

        const uint32_t As = sbase + (kt % 3) * (STAGE_H * 2);
        const uint32_t Bs = As + 16384;

        // prologue fragments (j = 0)
        {
            const uint32_t ck = (uint32_t)(((0 + lk) ^ lsub) * 16);
            #pragma unroll
            for (int mi = 0; mi < 4; ++mi)
                LDMX4(afr[0][mi], As + (uint32_t)((wm + mi * 16) * 128) + rowoff + ck);
            #pragma unroll
            for (int np = 0; np < 4; ++np)
                LDMX4(bfr[0][np], Bs + (uint32_t)((wn + np * 16) * 128) + rowoff + ck);
        }

        #pragma unroll
        for (int j = 0; j < 4; ++j) {
            const int cur = j & 1, nxt = cur ^ 1;
            if (j < 3) {
                const uint32_t ck = (uint32_t)((((2 * (j + 1)) + lk) ^ lsub) * 16);
                #pragma unroll
                for (int mi = 0; mi < 4; ++mi)
                    LDMX4(afr[nxt][mi], As + (uint32_t)((wm + mi * 16) * 128) + rowoff + ck);
                #pragma unroll
                for (int np = 0; np < 4; ++np)
                    LDMX4(bfr[nxt][np], Bs + (uint32_t)((wn + np * 16) * 128) + rowoff + ck);
            }
            #pragma unroll
            for (int mi = 0; mi < 4; ++mi) {
                #pragma unroll
                for (int np = 0; np < 4; ++np) {
                    uint32_t b0[2] = { bfr[cur][np][0], bfr[cur][np][2] };
                    uint32_t b1[2] = { bfr[cur][np][1], bfr[cur][np][3] };
                    mma_f16(acc[mi][2 * np],     afr[cur][mi], b0);
                    mma_f16(acc[mi][2 * np + 1], afr[cur][mi], b1);
                }
            }
        }
    }

    // epilogue
    #pragma unroll
    for (int mi = 0; mi < 4; ++mi) {
        #pragma unroll
        for (int ni = 0; ni < 8; ++ni) {
            int c = bn + wn + ni * 8 + tq * 2;
            float2 bv = *(const float2*)(bias + c);
            #pragma unroll
            for (int half = 0; half < 2; ++half) {
                int r = bm + wm + mi * 16 + g + half * 8;
                float v0 = acc[mi][ni][half * 2 + 0] + bv.x;
                float v1 = acc[mi][ni][half * 2 + 1] + bv.y;
                if (MODE == 0) {
                    *(float2*)((float*)outv + (size_t)r * N + c) = make_float2(v0, v1);
                } else if (MODE == 1) {
                    *(__half2*)((__half*)outv + (size_t)r * N + c) =
                        __floats2half2_rn(gelu_exact(v0), gelu_exact(v1));
                } else if (MODE == 2) {
                    float2 rv = *(const float2*)(res + (size_t)r * N + c);
                    *(float2*)((float*)outv + (size_t)r * N + c) =
                        make_float2(v0 + rv.x, v1 + rv.y);
                } else if (MODE == 4) {
                    *(__half2*)((__half*)outv + (size_t)r * N + c) =
                        __floats2half2_rn(v0, v1);
                } else {
                    float2 rv = *(const float2*)(res + (size_t)r * N + c);
                    v0 += rv.x; v1 += rv.y;
                    float* out = (float*)outv;
                    int wi = r >> 4, tt = r & 15;
                    int bb2 = wi >> 6, wh = (wi >> 3) & 7, ww = wi & 7;
                    int hh = wh * 4 + (tt >> 2), wc = ww * 4 + (tt & 3);
                    out[(((size_t)bb2 * C_ + c)     * H_ + hh) * W_ + wc] = v0;
                    out[(((size_t)bb2 * C_ + c + 1) * H_ + hh) * W_ + wc] = v1;
                }
            }
        }
    }
}

// ===================================================================
// Kernel 1: transpose [B,C,H,W] -> token rows (window-major), LN1
// ===================================================================
__global__ void __launch_bounds__(256) ln1_kernel(
    const float* __restrict__ x, const float* __restrict__ nw,
    const float* __restrict__ nb, float* __restrict__ xh, __half* __restrict__ xn)
{
    extern __shared__ float tile[];  // [32][513]
    __shared__ float s_sum[32], s_sq[32], s_mean[32], s_rstd[32];
    int bidx = blockIdx.x;
    int bb = bidx >> 5, h = bidx & 31;
    int t = threadIdx.x;
    if (t < 32) { s_sum[t] = 0.f; s_sq[t] = 0.f; }
    __syncthreads();

    const float* xp = x + ((size_t)bb * C_) * (H_ * W_) + (size_t)h * W_;
    float lsum = 0.f, lsq = 0.f;
    for (int idx = t; idx < C_ * 32; idx += 256) {
        int c = idx >> 5, ww = idx & 31;
        float v = xp[(size_t)c * (H_ * W_) + ww];
        tile[ww * 513 + c] = v;
        lsum += v; lsq += v * v;
    }
    atomicAdd(&s_sum[t & 31], lsum);
    atomicAdd(&s_sq [t & 31], lsq);
    __syncthreads();
    if (t < 32) {
        float m = s_sum[t] * (1.f / C_);
        float v = s_sq[t] * (1.f / C_) - m * m;
        s_mean[t] = m; s_rstd[t] = rsqrtf(v + EPS_);
    }
    __syncthreads();

    int wh = h >> 2, i = h & 3;
    for (int idx = t; idx < 32 * C_; idx += 256) {
        int ww = idx >> 9, c = idx & (C_ - 1);
        int wwi = ww >> 2, j = ww & 3;
        int wid = (bb * 8 + wh) * 8 + wwi;
        size_t r = (size_t)wid * NTOK + i * 4 + j;
        float v = tile[ww * 513 + c];
        xh[r * C_ + c] = v;
        xn[r * C_ + c] = __float2half((v - s_mean[ww]) * s_rstd[ww] * nw[c] + nb[c]);
    }
}

// ===================================================================
// windowed attention: fp16 qkv in, fp16 ctx out, fp32 math
// ===================================================================
__global__ void __launch_bounds__(128) attn_kernel(
    const __half* __restrict__ qkv, const float* __restrict__ rpb,
    __half* __restrict__ ctx)
{
    int w    = blockIdx.x;
    int lane = threadIdx.x & 31;
    int warp = threadIdx.x >> 5;
    int n    = lane & 15;
    int hh   = lane >> 4;
    const float scale = 0.17677669529663687f;
    size_t base = (size_t)w * NTOK * (3 * C_);

    #pragma unroll
    for (int it = 0; it < 2; ++it) {
        int head = warp * 4 + it * 2 + hh;

        float q[32];
        ld32h(qkv + base + (size_t)n * (3 * C_) + head * HD_, q);
        #pragma unroll
        for (int i = 0; i < 32; ++i) q[i] *= scale;

        float s[16];
        int i1 = n >> 2, j1 = n & 3;
        #pragma unroll
        for (int m = 0; m < 16; ++m) {
            float kf[32];
            ld32h(qkv + base + (size_t)m * (3 * C_) + C_ + head * HD_, kf);
            float acc = 0.f;
            #pragma unroll
            for (int i = 0; i < 32; ++i) acc += q[i] * kf[i];
            int i2 = m >> 2, j2 = m & 3;
            int ridx = (i1 - i2 + 3) * 7 + (j1 - j2 + 3);
            s[m] = acc + rpb[ridx * NH_ + head];
        }

        float mx = s[0];
        #pragma unroll
        for (int m = 1; m < 16; ++m) mx = fmaxf(mx, s[m]);
        float sum = 0.f;
        #pragma unroll
        for (int m = 0; m < 16; ++m) { s[m] = expf(s[m] - mx); sum += s[m]; }
        float inv = 1.f / sum;

        float o[32];
        #pragma unroll
        for (int i = 0; i < 32; ++i) o[i] = 0.f;
        #pragma unroll
        for (int m = 0; m < 16; ++m) {
            float p = s[m] * inv;
            float vf[32];
            ld32h(qkv + base + (size_t)m * (3 * C_) + 2 * C_ + head * HD_, vf);
            #pragma unroll
            for (int i = 0; i < 32; ++i) o[i] += p * vf[i];
        }
        __half2* op = (__half2*)(ctx + (size_t)(w * NTOK + n) * C_ + head * HD_);
        #pragma unroll
        for (int i = 0; i < 16; ++i)
            op[i] = __floats2half2_rn(o[2 * i], o[2 * i + 1]);
    }
}

// ===================================================================
// LN2: fp32 in, fp16 out
// ===================================================================
__global__ void __launch_bounds__(128) ln2_kernel(
    const float* __restrict__ in, const float* __restrict__ nw,
    const float* __restrict__ nb, __half* __restrict__ outp)
{
    int r = blockIdx.x;
    int t = threadIdx.x;
    int lane = t & 31, warp = t >> 5;
    float4 v = ((const float4*)(in + (size_t)r * C_))[t];
    float ls = v.x + v.y + v.z + v.w;
    float lq = v.x*v.x + v.y*v.y + v.z*v.z + v.w*v.w;
    #pragma unroll
    for (int off = 16; off; off >>= 1) {
        ls += __shfl_down_sync(0xffffffffu, ls, off);
        lq += __shfl_down_sync(0xffffffffu, lq, off);
    }
    __shared__ float ss[4], sq2[4];
    __shared__ float sm, sr;
    if (lane == 0) { ss[warp] = ls; sq2[warp] = lq; }
    __syncthreads();
    if (t == 0) {
        float S = ss[0] + ss[1] + ss[2] + ss[3];
        float Q = sq2[0] + sq2[1] + sq2[2] + sq2[3];
        float m = S * (1.f / C_);
        float var = Q * (1.f / C_) - m * m;
        sm = m; sr = rsqrtf(var + EPS_);
    }
    __syncthreads();
    float m = sm, rs = sr;
    float4 wv = ((const float4*)nw)[t];
    float4 bv = ((const float4*)nb)[t];
    float o0 = (v.x - m) * rs * wv.x + bv.x;
    float o1 = (v.y - m) * rs * wv.y + bv.y;
    float o2 = (v.z - m) * rs * wv.z + bv.z;
    float o3 = (v.w - m) * rs * wv.w + bv.w;
    __half2* op = (__half2*)(outp + (size_t)r * C_ + t * 4);
    op[0] = __floats2half2_rn(o0, o1);
    op[1] = __floats2half2_rn(o2, o3);
}

// ===================================================================
// host launch
// ===================================================================
extern "C" void kernel_launch(void* const* d_in, const int* in_sizes, int n_in,
                              void* d_out, int out_size)
{
    const float* x     = (const float*)d_in[0];
    const float* n1w   = (const float*)d_in[1];
    const float* n1b   = (const float*)d_in[2];
    const float* qkvw  = (const float*)d_in[3];
    const float* qkvb  = (const float*)d_in[4];
    const float* rpb   = (const float*)d_in[5];
    const float* projw = (const float*)d_in[6];
    const float* projb = (const float*)d_in[7];
    const float* n2w   = (const float*)d_in[8];
    const float* n2b   = (const float*)d_in[9];
    const float* w1    = (const float*)d_in[10];
    const float* b1    = (const float*)d_in[11];
    const float* w2    = (const float*)d_in[12];
    const float* b2    = (const float*)d_in[13];
    float* out = (float*)d_out;

    float *xh, *xh2;
    __half *qkv_h, *xn_h, *ctx_h, *hn_h, *h1_h, *wq_h, *wp_h, *w1_h, *w2_h;
    cudaGetSymbolAddress((void**)&xh,    g_xh);
    cudaGetSymbolAddress((void**)&xh2,   g_xh2);
    cudaGetSymbolAddress((void**)&qkv_h, g_qkv_h);
    cudaGetSymbolAddress((void**)&xn_h,  g_xn_h);
    cudaGetSymbolAddress((void**)&ctx_h, g_ctx_h);
    cudaGetSymbolAddress((void**)&hn_h,  g_hn_h);
    cudaGetSymbolAddress((void**)&h1_h,  g_h1_h);
    cudaGetSymbolAddress((void**)&wq_h,  g_wq_h);
    cudaGetSymbolAddress((void**)&wp_h,  g_wp_h);
    cudaGetSymbolAddress((void**)&w1_h,  g_w1_h);
    cudaGetSymbolAddress((void**)&w2_h,  g_w2_h);

    int ln1_smem = 32 * 513 * 4;
    cudaFuncSetAttribute(ln1_kernel, cudaFuncAttributeMaxDynamicSharedMemorySize, ln1_smem);
    cudaFuncSetAttribute(gemm_h<1>, cudaFuncAttributeMaxDynamicSharedMemorySize, GSMEM);
    cudaFuncSetAttribute(gemm_h<2>, cudaFuncAttributeMaxDynamicSharedMemorySize, GSMEM);
    cudaFuncSetAttribute(gemm_h<3>, cudaFuncAttributeMaxDynamicSharedMemorySize, GSMEM);
    cudaFuncSetAttribute(gemm_h<4>, cudaFuncAttributeMaxDynamicSharedMemorySize, GSMEM);

    // 1. transpose + LN1 (first so ncu -s 5 lands on the QKV GEMM)
    ln1_kernel<<<B_ * H_, 256, ln1_smem>>>(x, n1w, n1b, xh, xn_h);

    // 0. weight conversion fp32 -> fp16
    f2h_kernel<<<(3 * C_ * C_ / 4 + 255) / 256, 256>>>(qkvw, wq_h, 3 * C_ * C_);
    f2h_kernel<<<(C_ * C_ / 4 + 255) / 256, 256>>>(projw, wp_h, C_ * C_);
    f2h_kernel<<<(MLPH * C_ / 4 + 255) / 256, 256>>>(w1, w1_h, MLPH * C_);
    f2h_kernel<<<(C_ * MLPH / 4 + 255) / 256, 256>>>(w2, w2_h, C_ * MLPH);

    // 2. QKV projection -> fp16 qkv
    gemm_h<4><<<dim3((3 * C_) / 128, T_ / 128), 128, GSMEM>>>(
        xn_h, wq_h, qkvb, nullptr, qkv_h, T_, 3 * C_, C_);

    // 3. window attention -> fp16 ctx
    attn_kernel<<<T_ / NTOK, 128>>>(qkv_h, rpb, ctx_h);

    // 4. proj + bias + residual -> fp32 xh2
    gemm_h<2><<<dim3(C_ / 128, T_ / 128), 128, GSMEM>>>(
        ctx_h, wp_h, projb, xh, xh2, T_, C_, C_);

    // 5. LN2 -> fp16 hn
    ln2_kernel<<<T_, 128>>>(xh2, n2w, n2b, hn_h);

    // 6. MLP1 + bias + GELU -> fp16 h1
    gemm_h<1><<<dim3(MLPH / 128, T_ / 128), 128, GSMEM>>>(
        hn_h, w1_h, b1, nullptr, h1_h, T_, MLPH, C_);

    // 7. MLP2 + bias + residual + un-permute to [B,C,H,W]
    gemm_h<3><<<dim3(C_ / 128, T_ / 128), 128, GSMEM>>>(
        h1_h, w2_h, b2, xh2, out, T_, C_, MLPH);
}

// round 9
// speedup vs baseline: 3.3422x; 1.0322x over previous
#include <cuda_runtime.h>
#include <cuda.h>
#include <cuda_fp16.h>
#include <cstdint>
#include <cstdio>

// ---------------- problem constants ----------------
#define B_   32
#define C_   512
#define H_   32
#define W_   32
#define NH_  16
#define WS_  4
#define HD_  32
#define NTOK 16
#define T_   32768
#define MLPH 2048
#define EPS_ 1e-5f

// ---------------- scratch (device globals; no allocs allowed) ----------------
__device__ float  g_xh  [ (size_t)T_ * C_ ];      // residual (window-major)
__device__ float  g_xh2 [ (size_t)T_ * C_ ];      // after proj + residual
__device__ __half g_qkv_h[ (size_t)T_ * 3 * C_ ]; // fp16 qkv
__device__ __half g_xn_h [ (size_t)T_ * C_ ];     // LN1 out (fp16)
__device__ __half g_ctx_h[ (size_t)T_ * C_ ];     // attn context (fp16)
__device__ __half g_hn_h [ (size_t)T_ * C_ ];     // LN2 out (fp16)
__device__ __half g_h1_h [ (size_t)T_ * MLPH ];   // MLP hidden (fp16)
__device__ __half g_wq_h [ (size_t)3 * C_ * C_ ];
__device__ __half g_wp_h [ (size_t)C_ * C_ ];
__device__ __half g_w1_h [ (size_t)MLPH * C_ ];
__device__ __half g_w2_h [ (size_t)C_ * MLPH ];

// ---------------- mma / ldmatrix ----------------
__device__ __forceinline__ void mma_f16(float* c, const uint32_t* a, const uint32_t* b) {
    asm volatile("mma.sync.aligned.m16n8k16.row.col.f32.f16.f16.f32 "
        "{%0,%1,%2,%3}, {%4,%5,%6,%7}, {%8,%9}, {%0,%1,%2,%3};\n"
        : "+f"(c[0]), "+f"(c[1]), "+f"(c[2]), "+f"(c[3])
        : "r"(a[0]), "r"(a[1]), "r"(a[2]), "r"(a[3]),
          "r"(b[0]), "r"(b[1]));
}

#define LDMX4(r, addr) \
    asm volatile("ldmatrix.sync.aligned.m8n8.x4.shared.b16 {%0,%1,%2,%3}, [%4];" \
        : "=r"((r)[0]), "=r"((r)[1]), "=r"((r)[2]), "=r"((r)[3]) : "r"(addr))

// ---------------- TMA / mbarrier ----------------
#define MBARRIER_INIT(mbar, count) \
    asm volatile("mbarrier.init.shared.b64 [%0], %1;" \
        :: "r"((uint32_t)(mbar)), "r"((uint32_t)(count)) : "memory")
#define MBARRIER_EXPECT_TX(mbar, bytes) \
    asm volatile("mbarrier.arrive.expect_tx.shared.b64 _, [%0], %1;" \
        :: "r"((uint32_t)(mbar)), "r"((uint32_t)(bytes)) : "memory")

#define MBARRIER_WAIT_PARITY(mbar, parity) do { \
    uint32_t _m = (uint32_t)(mbar), _p = (uint32_t)(parity), _d; \
    asm volatile("{\n\t.reg .pred p;\n\t" \
        "mbarrier.try_wait.parity.acquire.cta.shared::cta.b64 p, [%1], %2;\n\t" \
        "selp.b32 %0, 1, 0, p;\n\t}" : "=r"(_d) : "r"(_m), "r"(_p) : "memory"); \
    if (!_d) { \
        asm volatile("{\n\t.reg .pred P1;\n\t" \
            "WAIT_LOOP_%=:\n\t" \
            "mbarrier.try_wait.parity.acquire.cta.shared::cta.b64 P1, [%0], %1, 0x989680;\n\t" \
            "@P1 bra.uni WAIT_DONE_%=;\n\t" \
            "bra.uni WAIT_LOOP_%=;\n\t" \
            "WAIT_DONE_%=:\n\t}" :: "r"(_m), "r"(_p) : "memory"); \
    } \
} while (0)

#define TMA2D(saddr, tmap, cx, cy, mbar) \
    asm volatile("cp.async.bulk.tensor.2d.shared::cta.global.tile.mbarrier::complete_tx::bytes " \
        "[%0], [%1, {%2, %3}], [%4];" \
        :: "r"((uint32_t)(saddr)), "l"(tmap), "r"((int32_t)(cx)), "r"((int32_t)(cy)), \
           "r"((uint32_t)(mbar)) : "memory")

__device__ __forceinline__ float gelu_exact(float x) {
    return 0.5f * x * (1.0f + erff(x * 0.7071067811865475f));
}

// load 32 halves (64B) -> 32 floats
__device__ __forceinline__ void ld32h(const __half* p, float* f) {
    const uint4* u = (const uint4*)p;
    #pragma unroll
    for (int c = 0; c < 4; ++c) {
        uint4 x = u[c];
        uint32_t w[4] = { x.x, x.y, x.z, x.w };
        #pragma unroll
        for (int k = 0; k < 4; ++k) {
            float2 d = __half22float2(*(__half2*)&w[k]);
            f[c * 8 + k * 2 + 0] = d.x;
            f[c * 8 + k * 2 + 1] = d.y;
        }
    }
}

// ===================================================================
// single fused fp32 -> fp16 conversion of all 4 weight matrices
// ===================================================================
#define NQ (3 * C_ * C_)
#define NP (C_ * C_)
#define N1 (MLPH * C_)
#define N2 (C_ * MLPH)
__global__ void f2h_all_kernel(const float* __restrict__ wq, const float* __restrict__ wp,
                               const float* __restrict__ w1, const float* __restrict__ w2,
                               __half* __restrict__ dq, __half* __restrict__ dp,
                               __half* __restrict__ d1, __half* __restrict__ d2) {
    int i = (blockIdx.x * blockDim.x + threadIdx.x) * 4;
    const float* s; __half* d; int off;
    if (i < NQ)                     { s = wq; d = dq; off = i; }
    else if (i < NQ + NP)           { s = wp; d = dp; off = i - NQ; }
    else if (i < NQ + NP + N1)      { s = w1; d = d1; off = i - NQ - NP; }
    else if (i < NQ + NP + N1 + N2) { s = w2; d = d2; off = i - NQ - NP - N1; }
    else return;
    float4 v = *(const float4*)(s + off);
    __half2* dpp = (__half2*)(d + off);
    dpp[0] = __floats2half2_rn(v.x, v.y);
    dpp[1] = __floats2half2_rn(v.z, v.w);
}

// ===================================================================
// fp16 GEMM: Out[M,N] = A[M,K] @ W[N,K]^T + epilogue
// CTA 128x128, 128 thr = 4 warps (2m x 2n), warp tile 64x64.
// TMA (SW128) fills a 3-stage ring; mbarrier expect_tx completion;
// ldmatrix.x4 fragment double-buffering; mma.m16n8k16 fp32 accum.
// MODE 0:+bias fp32 | 1:gelu(+bias) fp16 | 2:+bias+res fp32 |
//      3:+bias+res permuted fp32 | 4:+bias fp16
// ===================================================================
#define STAGE_B  32768                 // bytes per stage: A 16KB + B 16KB
#define MB_OFF   (3 * STAGE_B)         // barriers after stages
#define GSMEM    (MB_OFF + 128)

template<int MODE>
__global__ void __launch_bounds__(128, 2) gemm_h(
    const __grid_constant__ CUtensorMap tmA,
    const __grid_constant__ CUtensorMap tmB,
    const float* __restrict__ bias, const float* __restrict__ res,
    void* __restrict__ outv, int N, int K)
{
    extern __shared__ __align__(1024) char smem[];
    const uint32_t sbase = (uint32_t)__cvta_generic_to_shared(smem);
    const uint32_t mb = sbase + MB_OFF;

    const int tid  = threadIdx.x;
    const int lane = tid & 31, warp = tid >> 5;
    const int bm   = blockIdx.y * 128;
    const int bn   = blockIdx.x * 128;
    const int wm   = (warp & 1) * 64;
    const int wn   = (warp >> 1) * 64;
    const int tq   = lane & 3, g = lane >> 2;
    const int nK   = K >> 6;

    // ldmatrix lane decomposition
    const int lsub = lane & 7;
    const int lh   = (lane >> 3) & 1;
    const int lk   = lane >> 4;
    const uint32_t rowoff = (uint32_t)((lh * 8 + lsub) * 128);

    if (tid == 0) {
        MBARRIER_INIT(mb,      1);
        MBARRIER_INIT(mb + 8,  1);
        MBARRIER_INIT(mb + 16, 1);
    }
    __syncthreads();

    float acc[4][8][4];
    #pragma unroll
    for (int i = 0; i < 4; ++i)
        #pragma unroll
        for (int j = 0; j < 8; ++j)
            #pragma unroll
            for (int e = 0; e < 4; ++e) acc[i][j][e] = 0.f;

    // prologue: fill stages 0,1
    if (tid == 0) {
        #pragma unroll
        for (int s = 0; s < 2; ++s) {
            MBARRIER_EXPECT_TX(mb + 8 * s, STAGE_B);
            TMA2D(sbase + s * STAGE_B,         &tmA, s * 64, bm, mb + 8 * s);
            TMA2D(sbase + s * STAGE_B + 16384, &tmB, s * 64, bn, mb + 8 * s);
        }
    }

    uint32_t afr[2][4][4], bfr[2][4][4];

    for (int kt = 0; kt < nK; ++kt) {
        const int st = kt % 3;
        MBARRIER_WAIT_PARITY(mb + 8 * st, (kt / 3) & 1);
        __syncthreads();   // all warps done reading stage (kt+2)%3 == (kt-1)%3

        if (tid == 0) {
            int kn = kt + 2;
            if (kn < nK) {
                int sn = kn % 3;
                MBARRIER_EXPECT_TX(mb + 8 * sn, STAGE_B);
                TMA2D(sbase + sn * STAGE_B,         &tmA, kn * 64, bm, mb + 8 * sn);
                TMA2D(sbase + sn * STAGE_B + 16384, &tmB, kn * 64, bn, mb + 8 * sn);
            }
        }

        const uint32_t As = sbase + st * STAGE_B;
        const uint32_t Bs = As + 16384;

        // prologue fragments (j = 0)
        {
            const uint32_t ck = (uint32_t)((lk ^ lsub) * 16);
            #pragma unroll
            for (int mi = 0; mi < 4; ++mi)
                LDMX4(afr[0][mi], As + (uint32_t)((wm + mi * 16) * 128) + rowoff + ck);
            #pragma unroll
            for (int np = 0; np < 4; ++np)
                LDMX4(bfr[0][np], Bs + (uint32_t)((wn + np * 16) * 128) + rowoff + ck);
        }

        #pragma unroll
        for (int j = 0; j < 4; ++j) {
            const int cur = j & 1, nxt = cur ^ 1;
            if (j < 3) {
                const uint32_t ck = (uint32_t)((((2 * (j + 1)) + lk) ^ lsub) * 16);
                #pragma unroll
                for (int mi = 0; mi < 4; ++mi)
                    LDMX4(afr[nxt][mi], As + (uint32_t)((wm + mi * 16) * 128) + rowoff + ck);
                #pragma unroll
                for (int np = 0; np < 4; ++np)
                    LDMX4(bfr[nxt][np], Bs + (uint32_t)((wn + np * 16) * 128) + rowoff + ck);
            }
            #pragma unroll
            for (int mi = 0; mi < 4; ++mi) {
                #pragma unroll
                for (int np = 0; np < 4; ++np) {
                    uint32_t b0[2] = { bfr[cur][np][0], bfr[cur][np][2] };
                    uint32_t b1[2] = { bfr[cur][np][1], bfr[cur][np][3] };
                    mma_f16(acc[mi][2 * np],     afr[cur][mi], b0);
                    mma_f16(acc[mi][2 * np + 1], afr[cur][mi], b1);
                }
            }
        }
    }

    // epilogue
    #pragma unroll
    for (int mi = 0; mi < 4; ++mi) {
        #pragma unroll
        for (int ni = 0; ni < 8; ++ni) {
            int c = bn + wn + ni * 8 + tq * 2;
            float2 bv = *(const float2*)(bias + c);
            #pragma unroll
            for (int half = 0; half < 2; ++half) {
                int r = bm + wm + mi * 16 + g + half * 8;
                float v0 = acc[mi][ni][half * 2 + 0] + bv.x;
                float v1 = acc[mi][ni][half * 2 + 1] + bv.y;
                if (MODE == 0) {
                    *(float2*)((float*)outv + (size_t)r * N + c) = make_float2(v0, v1);
                } else if (MODE == 1) {
                    *(__half2*)((__half*)outv + (size_t)r * N + c) =
                        __floats2half2_rn(gelu_exact(v0), gelu_exact(v1));
                } else if (MODE == 2) {
                    float2 rv = *(const float2*)(res + (size_t)r * N + c);
                    *(float2*)((float*)outv + (size_t)r * N + c) =
                        make_float2(v0 + rv.x, v1 + rv.y);
                } else if (MODE == 4) {
                    *(__half2*)((__half*)outv + (size_t)r * N + c) =
                        __floats2half2_rn(v0, v1);
                } else {
                    float2 rv = *(const float2*)(res + (size_t)r * N + c);
                    v0 += rv.x; v1 += rv.y;
                    float* out = (float*)outv;
                    int wi = r >> 4, tt = r & 15;
                    int bb2 = wi >> 6, wh = (wi >> 3) & 7, ww = wi & 7;
                    int hh = wh * 4 + (tt >> 2), wc = ww * 4 + (tt & 3);
                    out[(((size_t)bb2 * C_ + c)     * H_ + hh) * W_ + wc] = v0;
                    out[(((size_t)bb2 * C_ + c + 1) * H_ + hh) * W_ + wc] = v1;
                }
            }
        }
    }
}

// ===================================================================
// Kernel 1: transpose [B,C,H,W] -> token rows (window-major), LN1
// ===================================================================
__global__ void __launch_bounds__(256) ln1_kernel(
    const float* __restrict__ x, const float* __restrict__ nw,
    const float* __restrict__ nb, float* __restrict__ xh, __half* __restrict__ xn)
{
    extern __shared__ float tile[];  // [32][513]
    __shared__ float s_sum[32], s_sq[32], s_mean[32], s_rstd[32];
    int bidx = blockIdx.x;
    int bb = bidx >> 5, h = bidx & 31;
    int t = threadIdx.x;
    if (t < 32) { s_sum[t] = 0.f; s_sq[t] = 0.f; }
    __syncthreads();

    const float* xp = x + ((size_t)bb * C_) * (H_ * W_) + (size_t)h * W_;
    float lsum = 0.f, lsq = 0.f;
    for (int idx = t; idx < C_ * 32; idx += 256) {
        int c = idx >> 5, ww = idx & 31;
        float v = xp[(size_t)c * (H_ * W_) + ww];
        tile[ww * 513 + c] = v;
        lsum += v; lsq += v * v;
    }
    atomicAdd(&s_sum[t & 31], lsum);
    atomicAdd(&s_sq [t & 31], lsq);
    __syncthreads();
    if (t < 32) {
        float m = s_sum[t] * (1.f / C_);
        float v = s_sq[t] * (1.f / C_) - m * m;
        s_mean[t] = m; s_rstd[t] = rsqrtf(v + EPS_);
    }
    __syncthreads();

    int wh = h >> 2, i = h & 3;
    for (int idx = t; idx < 32 * C_; idx += 256) {
        int ww = idx >> 9, c = idx & (C_ - 1);
        int wwi = ww >> 2, j = ww & 3;
        int wid = (bb * 8 + wh) * 8 + wwi;
        size_t r = (size_t)wid * NTOK + i * 4 + j;
        float v = tile[ww * 513 + c];
        xh[r * C_ + c] = v;
        xn[r * C_ + c] = __float2half((v - s_mean[ww]) * s_rstd[ww] * nw[c] + nb[c]);
    }
}

// ===================================================================
// windowed attention: fp16 qkv in, fp16 ctx out, fp32 math
// ===================================================================
__global__ void __launch_bounds__(128) attn_kernel(
    const __half* __restrict__ qkv, const float* __restrict__ rpb,
    __half* __restrict__ ctx)
{
    int w    = blockIdx.x;
    int lane = threadIdx.x & 31;
    int warp = threadIdx.x >> 5;
    int n    = lane & 15;
    int hh   = lane >> 4;
    const float scale = 0.17677669529663687f;
    size_t base = (size_t)w * NTOK * (3 * C_);

    #pragma unroll
    for (int it = 0; it < 2; ++it) {
        int head = warp * 4 + it * 2 + hh;

        float q[32];
        ld32h(qkv + base + (size_t)n * (3 * C_) + head * HD_, q);
        #pragma unroll
        for (int i = 0; i < 32; ++i) q[i] *= scale;

        float s[16];
        int i1 = n >> 2, j1 = n & 3;
        #pragma unroll
        for (int m = 0; m < 16; ++m) {
            float kf[32];
            ld32h(qkv + base + (size_t)m * (3 * C_) + C_ + head * HD_, kf);
            float acc = 0.f;
            #pragma unroll
            for (int i = 0; i < 32; ++i) acc += q[i] * kf[i];
            int i2 = m >> 2, j2 = m & 3;
            int ridx = (i1 - i2 + 3) * 7 + (j1 - j2 + 3);
            s[m] = acc + rpb[ridx * NH_ + head];
        }

        float mx = s[0];
        #pragma unroll
        for (int m = 1; m < 16; ++m) mx = fmaxf(mx, s[m]);
        float sum = 0.f;
        #pragma unroll
        for (int m = 0; m < 16; ++m) { s[m] = expf(s[m] - mx); sum += s[m]; }
        float inv = 1.f / sum;

        float o[32];
        #pragma unroll
        for (int i = 0; i < 32; ++i) o[i] = 0.f;
        #pragma unroll
        for (int m = 0; m < 16; ++m) {
            float p = s[m] * inv;
            float vf[32];
            ld32h(qkv + base + (size_t)m * (3 * C_) + 2 * C_ + head * HD_, vf);
            #pragma unroll
            for (int i = 0; i < 32; ++i) o[i] += p * vf[i];
        }
        __half2* op = (__half2*)(ctx + (size_t)(w * NTOK + n) * C_ + head * HD_);
        #pragma unroll
        for (int i = 0; i < 16; ++i)
            op[i] = __floats2half2_rn(o[2 * i], o[2 * i + 1]);
    }
}

// ===================================================================
// LN2: fp32 in, fp16 out
// ===================================================================
__global__ void __launch_bounds__(128) ln2_kernel(
    const float* __restrict__ in, const float* __restrict__ nw,
    const float* __restrict__ nb, __half* __restrict__ outp)
{
    int r = blockIdx.x;
    int t = threadIdx.x;
    int lane = t & 31, warp = t >> 5;
    float4 v = ((const float4*)(in + (size_t)r * C_))[t];
    float ls = v.x + v.y + v.z + v.w;
    float lq = v.x*v.x + v.y*v.y + v.z*v.z + v.w*v.w;
    #pragma unroll
    for (int off = 16; off; off >>= 1) {
        ls += __shfl_down_sync(0xffffffffu, ls, off);
        lq += __shfl_down_sync(0xffffffffu, lq, off);
    }
    __shared__ float ss[4], sq2[4];
    __shared__ float sm, sr;
    if (lane == 0) { ss[warp] = ls; sq2[warp] = lq; }
    __syncthreads();
    if (t == 0) {
        float S = ss[0] + ss[1] + ss[2] + ss[3];
        float Q = sq2[0] + sq2[1] + sq2[2] + sq2[3];
        float m = S * (1.f / C_);
        float var = Q * (1.f / C_) - m * m;
        sm = m; sr = rsqrtf(var + EPS_);
    }
    __syncthreads();
    float m = sm, rs = sr;
    float4 wv = ((const float4*)nw)[t];
    float4 bv = ((const float4*)nb)[t];
    float o0 = (v.x - m) * rs * wv.x + bv.x;
    float o1 = (v.y - m) * rs * wv.y + bv.y;
    float o2 = (v.z - m) * rs * wv.z + bv.z;
    float o3 = (v.w - m) * rs * wv.w + bv.w;
    __half2* op = (__half2*)(outp + (size_t)r * C_ + t * 4);
    op[0] = __floats2half2_rn(o0, o1);
    op[1] = __floats2half2_rn(o2, o3);
}

// ===================================================================
// host: tensormap creation via driver entry point
// ===================================================================
typedef CUresult (*PFN_encodeTiled)(
    CUtensorMap*, CUtensorMapDataType, cuuint32_t, void*,
    const cuuint64_t*, const cuuint64_t*, const cuuint32_t*, const cuuint32_t*,
    CUtensorMapInterleave, CUtensorMapSwizzle, CUtensorMapL2promotion,
    CUtensorMapFloatOOBfill);

static PFN_encodeTiled get_encoder() {
    static PFN_encodeTiled fn = nullptr;
    if (!fn) {
        void* p = nullptr;
        cudaDriverEntryPointQueryResult qr;
        cudaGetDriverEntryPointByVersion("cuTensorMapEncodeTiled", &p, 12000,
                                         cudaEnableDefault, &qr);
        fn = (PFN_encodeTiled)p;
    }
    return fn;
}

static void make_tm(CUtensorMap* tm, const void* ptr, uint64_t K, uint64_t Rows) {
    cuuint64_t dims[2]    = { K, Rows };
    cuuint64_t strides[1] = { K * 2 };
    cuuint32_t box[2]     = { 64, 128 };
    cuuint32_t es[2]      = { 1, 1 };
    get_encoder()(tm, CU_TENSOR_MAP_DATA_TYPE_UINT16, 2, (void*)ptr,
                  dims, strides, box, es,
                  CU_TENSOR_MAP_INTERLEAVE_NONE, CU_TENSOR_MAP_SWIZZLE_128B,
                  CU_TENSOR_MAP_L2_PROMOTION_L2_128B,
                  CU_TENSOR_MAP_FLOAT_OOB_FILL_NONE);
}

extern "C" void kernel_launch(void* const* d_in, const int* in_sizes, int n_in,
                              void* d_out, int out_size)
{
    const float* x     = (const float*)d_in[0];
    const float* n1w   = (const float*)d_in[1];
    const float* n1b   = (const float*)d_in[2];
    const float* qkvw  = (const float*)d_in[3];
    const float* qkvb  = (const float*)d_in[4];
    const float* rpb   = (const float*)d_in[5];
    const float* projw = (const float*)d_in[6];
    const float* projb = (const float*)d_in[7];
    const float* n2w   = (const float*)d_in[8];
    const float* n2b   = (const float*)d_in[9];
    const float* w1    = (const float*)d_in[10];
    const float* b1    = (const float*)d_in[11];
    const float* w2    = (const float*)d_in[12];
    const float* b2    = (const float*)d_in[13];
    float* out = (float*)d_out;

    float *xh, *xh2;
    __half *qkv_h, *xn_h, *ctx_h, *hn_h, *h1_h, *wq_h, *wp_h, *w1_h, *w2_h;
    cudaGetSymbolAddress((void**)&xh,    g_xh);
    cudaGetSymbolAddress((void**)&xh2,   g_xh2);
    cudaGetSymbolAddress((void**)&qkv_h, g_qkv_h);
    cudaGetSymbolAddress((void**)&xn_h,  g_xn_h);
    cudaGetSymbolAddress((void**)&ctx_h, g_ctx_h);
    cudaGetSymbolAddress((void**)&hn_h,  g_hn_h);
    cudaGetSymbolAddress((void**)&h1_h,  g_h1_h);
    cudaGetSymbolAddress((void**)&wq_h,  g_wq_h);
    cudaGetSymbolAddress((void**)&wp_h,  g_wp_h);
    cudaGetSymbolAddress((void**)&w1_h,  g_w1_h);
    cudaGetSymbolAddress((void**)&w2_h,  g_w2_h);

    static CUtensorMap tmA_xn, tmB_wq, tmA_ctx, tmB_wp, tmA_hn, tmB_w1, tmA_h1, tmB_w2;
    make_tm(&tmA_xn,  xn_h,  C_,   T_);
    make_tm(&tmB_wq,  wq_h,  C_,   3 * C_);
    make_tm(&tmA_ctx, ctx_h, C_,   T_);
    make_tm(&tmB_wp,  wp_h,  C_,   C_);
    make_tm(&tmA_hn,  hn_h,  C_,   T_);
    make_tm(&tmB_w1,  w1_h,  C_,   MLPH);
    make_tm(&tmA_h1,  h1_h,  MLPH, T_);
    make_tm(&tmB_w2,  w2_h,  MLPH, C_);

    int ln1_smem = 32 * 513 * 4;
    cudaFuncSetAttribute(ln1_kernel, cudaFuncAttributeMaxDynamicSharedMemorySize, ln1_smem);
    cudaFuncSetAttribute(gemm_h<1>, cudaFuncAttributeMaxDynamicSharedMemorySize, GSMEM);
    cudaFuncSetAttribute(gemm_h<2>, cudaFuncAttributeMaxDynamicSharedMemorySize, GSMEM);
    cudaFuncSetAttribute(gemm_h<3>, cudaFuncAttributeMaxDynamicSharedMemorySize, GSMEM);
    cudaFuncSetAttribute(gemm_h<4>, cudaFuncAttributeMaxDynamicSharedMemorySize, GSMEM);

    // 1. transpose + LN1
    ln1_kernel<<<B_ * H_, 256, ln1_smem>>>(x, n1w, n1b, xh, xn_h);

    // 0. fused weight conversion fp32 -> fp16 (one launch)
    {
        int total = (NQ + NP + N1 + N2) / 4;
        f2h_all_kernel<<<(total + 255) / 256, 256>>>(qkvw, projw, w1, w2,
                                                     wq_h, wp_h, w1_h, w2_h);
    }

    // 2. QKV projection -> fp16 qkv
    gemm_h<4><<<dim3((3 * C_) / 128, T_ / 128), 128, GSMEM>>>(
        tmA_xn, tmB_wq, qkvb, nullptr, qkv_h, 3 * C_, C_);

    // 3. window attention -> fp16 ctx
    attn_kernel<<<T_ / NTOK, 128>>>(qkv_h, rpb, ctx_h);

    // 4. proj + bias + residual -> fp32 xh2
    gemm_h<2><<<dim3(C_ / 128, T_ / 128), 128, GSMEM>>>(
        tmA_ctx, tmB_wp, projb, xh, xh2, C_, C_);

    // 5. LN2 -> fp16 hn
    ln2_kernel<<<T_, 128>>>(xh2, n2w, n2b, hn_h);

    // 6. MLP1 + bias + GELU -> fp16 h1
    gemm_h<1><<<dim3(MLPH / 128, T_ / 128), 128, GSMEM>>>(
        tmA_hn, tmB_w1, b1, nullptr, h1_h, MLPH, C_);

    // 7. MLP2 + bias + residual + un-permute to [B,C,H,W]
    gemm_h<3><<<dim3(C_ / 128, T_ / 128), 128, GSMEM>>>(
        tmA_h1, tmB_w2, b2, xh2, out, C_, MLPH);
}

// round 10
// speedup vs baseline: 3.5263x; 1.0551x over previous
#include <cuda_runtime.h>
#include <cuda.h>
#include <cuda_fp16.h>
#include <cstdint>
#include <cstdio>

// ---------------- problem constants ----------------
#define B_   32
#define C_   512
#define H_   32
#define W_   32
#define NH_  16
#define WS_  4
#define HD_  32
#define NTOK 16
#define T_   32768
#define MLPH 2048
#define EPS_ 1e-5f

// ---------------- scratch (device globals; no allocs allowed) ----------------
__device__ float  g_xh  [ (size_t)T_ * C_ ];      // residual (window-major)
__device__ float  g_xh2 [ (size_t)T_ * C_ ];      // after proj + residual
__device__ __half g_qkv_h[ (size_t)T_ * 3 * C_ ]; // fp16 qkv
__device__ __half g_xn_h [ (size_t)T_ * C_ ];     // LN1 out (fp16)
__device__ __half g_ctx_h[ (size_t)T_ * C_ ];     // attn context (fp16)
__device__ __half g_hn_h [ (size_t)T_ * C_ ];     // LN2 out (fp16)
__device__ __half g_h1_h [ (size_t)T_ * MLPH ];   // MLP hidden (fp16)
__device__ __half g_wq_h [ (size_t)3 * C_ * C_ ];
__device__ __half g_wp_h [ (size_t)C_ * C_ ];
__device__ __half g_w1_h [ (size_t)MLPH * C_ ];
__device__ __half g_w2_h [ (size_t)C_ * MLPH ];

// ---------------- mma / ldmatrix ----------------
__device__ __forceinline__ void mma_f16(float* c, const uint32_t* a, const uint32_t* b) {
    asm volatile("mma.sync.aligned.m16n8k16.row.col.f32.f16.f16.f32 "
        "{%0,%1,%2,%3}, {%4,%5,%6,%7}, {%8,%9}, {%0,%1,%2,%3};\n"
        : "+f"(c[0]), "+f"(c[1]), "+f"(c[2]), "+f"(c[3])
        : "r"(a[0]), "r"(a[1]), "r"(a[2]), "r"(a[3]),
          "r"(b[0]), "r"(b[1]));
}

#define LDMX4(r, addr) \
    asm volatile("ldmatrix.sync.aligned.m8n8.x4.shared.b16 {%0,%1,%2,%3}, [%4];" \
        : "=r"((r)[0]), "=r"((r)[1]), "=r"((r)[2]), "=r"((r)[3]) : "r"(addr))

// ---------------- TMA / mbarrier ----------------
#define MBARRIER_INIT(mbar, count) \
    asm volatile("mbarrier.init.shared.b64 [%0], %1;" \
        :: "r"((uint32_t)(mbar)), "r"((uint32_t)(count)) : "memory")
#define MBARRIER_EXPECT_TX(mbar, bytes) \
    asm volatile("mbarrier.arrive.expect_tx.shared.b64 _, [%0], %1;" \
        :: "r"((uint32_t)(mbar)), "r"((uint32_t)(bytes)) : "memory")

#define MBARRIER_WAIT_PARITY(mbar, parity) do { \
    uint32_t _m = (uint32_t)(mbar), _p = (uint32_t)(parity), _d; \
    asm volatile("{\n\t.reg .pred p;\n\t" \
        "mbarrier.try_wait.parity.acquire.cta.shared::cta.b64 p, [%1], %2;\n\t" \
        "selp.b32 %0, 1, 0, p;\n\t}" : "=r"(_d) : "r"(_m), "r"(_p) : "memory"); \
    if (!_d) { \
        asm volatile("{\n\t.reg .pred P1;\n\t" \
            "WAIT_LOOP_%=:\n\t" \
            "mbarrier.try_wait.parity.acquire.cta.shared::cta.b64 P1, [%0], %1, 0x989680;\n\t" \
            "@P1 bra.uni WAIT_DONE_%=;\n\t" \
            "bra.uni WAIT_LOOP_%=;\n\t" \
            "WAIT_DONE_%=:\n\t}" :: "r"(_m), "r"(_p) : "memory"); \
    } \
} while (0)

#define TMA2D(saddr, tmap, cx, cy, mbar) \
    asm volatile("cp.async.bulk.tensor.2d.shared::cta.global.tile.mbarrier::complete_tx::bytes " \
        "[%0], [%1, {%2, %3}], [%4];" \
        :: "r"((uint32_t)(saddr)), "l"(tmap), "r"((int32_t)(cx)), "r"((int32_t)(cy)), \
           "r"((uint32_t)(mbar)) : "memory")

__device__ __forceinline__ float gelu_exact(float x) {
    return 0.5f * x * (1.0f + erff(x * 0.7071067811865475f));
}

// load 32 halves (64B) -> 32 floats (works for global or shared src)
__device__ __forceinline__ void ld32h(const __half* p, float* f) {
    const uint4* u = (const uint4*)p;
    #pragma unroll
    for (int c = 0; c < 4; ++c) {
        uint4 x = u[c];
        uint32_t w[4] = { x.x, x.y, x.z, x.w };
        #pragma unroll
        for (int k = 0; k < 4; ++k) {
            float2 d = __half22float2(*(__half2*)&w[k]);
            f[c * 8 + k * 2 + 0] = d.x;
            f[c * 8 + k * 2 + 1] = d.y;
        }
    }
}

// ===================================================================
// single fused fp32 -> fp16 conversion of all 4 weight matrices
// ===================================================================
#define NQ (3 * C_ * C_)
#define NP (C_ * C_)
#define N1 (MLPH * C_)
#define N2 (C_ * MLPH)
__global__ void f2h_all_kernel(const float* __restrict__ wq, const float* __restrict__ wp,
                               const float* __restrict__ w1, const float* __restrict__ w2,
                               __half* __restrict__ dq, __half* __restrict__ dp,
                               __half* __restrict__ d1, __half* __restrict__ d2) {
    int i = (blockIdx.x * blockDim.x + threadIdx.x) * 4;
    const float* s; __half* d; int off;
    if (i < NQ)                     { s = wq; d = dq; off = i; }
    else if (i < NQ + NP)           { s = wp; d = dp; off = i - NQ; }
    else if (i < NQ + NP + N1)      { s = w1; d = d1; off = i - NQ - NP; }
    else if (i < NQ + NP + N1 + N2) { s = w2; d = d2; off = i - NQ - NP - N1; }
    else return;
    float4 v = *(const float4*)(s + off);
    __half2* dpp = (__half2*)(d + off);
    dpp[0] = __floats2half2_rn(v.x, v.y);
    dpp[1] = __floats2half2_rn(v.z, v.w);
}

// ===================================================================
// fp16 GEMM: Out[M,N] = A[M,K] @ W[N,K]^T + epilogue
// CTA 128x128, 128 thr = 4 warps (2m x 2n), warp tile 64x64.
// TMA (SW128) fills a 3-stage ring; mbarrier expect_tx completion;
// ldmatrix.x4 fragment double-buffering; mma.m16n8k16 fp32 accum.
// MODE 0:+bias fp32 | 1:gelu(+bias) fp16 | 2:+bias+res fp32 |
//      3:+bias+res permuted fp32 | 4:+bias fp16
// ===================================================================
#define STAGE_B  32768                 // bytes per stage: A 16KB + B 16KB
#define MB_OFF   (3 * STAGE_B)         // barriers after stages
#define GSMEM    (MB_OFF + 128)

template<int MODE>
__global__ void __launch_bounds__(128, 2) gemm_h(
    const __grid_constant__ CUtensorMap tmA,
    const __grid_constant__ CUtensorMap tmB,
    const float* __restrict__ bias, const float* __restrict__ res,
    void* __restrict__ outv, int N, int K)
{
    extern __shared__ __align__(1024) char smem[];
    const uint32_t sbase = (uint32_t)__cvta_generic_to_shared(smem);
    const uint32_t mb = sbase + MB_OFF;

    const int tid  = threadIdx.x;
    const int lane = tid & 31, warp = tid >> 5;
    const int bm   = blockIdx.y * 128;
    const int bn   = blockIdx.x * 128;
    const int wm   = (warp & 1) * 64;
    const int wn   = (warp >> 1) * 64;
    const int tq   = lane & 3, g = lane >> 2;
    const int nK   = K >> 6;

    // ldmatrix lane decomposition
    const int lsub = lane & 7;
    const int lh   = (lane >> 3) & 1;
    const int lk   = lane >> 4;
    const uint32_t rowoff = (uint32_t)((lh * 8 + lsub) * 128);

    if (tid == 0) {
        MBARRIER_INIT(mb,      1);
        MBARRIER_INIT(mb + 8,  1);
        MBARRIER_INIT(mb + 16, 1);
    }
    __syncthreads();

    float acc[4][8][4];
    #pragma unroll
    for (int i = 0; i < 4; ++i)
        #pragma unroll
        for (int j = 0; j < 8; ++j)
            #pragma unroll
            for (int e = 0; e < 4; ++e) acc[i][j][e] = 0.f;

    // prologue: fill stages 0,1
    if (tid == 0) {
        #pragma unroll
        for (int s = 0; s < 2; ++s) {
            MBARRIER_EXPECT_TX(mb + 8 * s, STAGE_B);
            TMA2D(sbase + s * STAGE_B,         &tmA, s * 64, bm, mb + 8 * s);
            TMA2D(sbase + s * STAGE_B + 16384, &tmB, s * 64, bn, mb + 8 * s);
        }
    }

    uint32_t afr[2][4][4], bfr[2][4][4];

    for (int kt = 0; kt < nK; ++kt) {
        const int st = kt % 3;
        MBARRIER_WAIT_PARITY(mb + 8 * st, (kt / 3) & 1);
        __syncthreads();

        if (tid == 0) {
            int kn = kt + 2;
            if (kn < nK) {
                int sn = kn % 3;
                MBARRIER_EXPECT_TX(mb + 8 * sn, STAGE_B);
                TMA2D(sbase + sn * STAGE_B,         &tmA, kn * 64, bm, mb + 8 * sn);
                TMA2D(sbase + sn * STAGE_B + 16384, &tmB, kn * 64, bn, mb + 8 * sn);
            }
        }

        const uint32_t As = sbase + st * STAGE_B;
        const uint32_t Bs = As + 16384;

        // prologue fragments (j = 0)
        {
            const uint32_t ck = (uint32_t)((lk ^ lsub) * 16);
            #pragma unroll
            for (int mi = 0; mi < 4; ++mi)
                LDMX4(afr[0][mi], As + (uint32_t)((wm + mi * 16) * 128) + rowoff + ck);
            #pragma unroll
            for (int np = 0; np < 4; ++np)
                LDMX4(bfr[0][np], Bs + (uint32_t)((wn + np * 16) * 128) + rowoff + ck);
        }

        #pragma unroll
        for (int j = 0; j < 4; ++j) {
            const int cur = j & 1, nxt = cur ^ 1;
            if (j < 3) {
                const uint32_t ck = (uint32_t)((((2 * (j + 1)) + lk) ^ lsub) * 16);
                #pragma unroll
                for (int mi = 0; mi < 4; ++mi)
                    LDMX4(afr[nxt][mi], As + (uint32_t)((wm + mi * 16) * 128) + rowoff + ck);
                #pragma unroll
                for (int np = 0; np < 4; ++np)
                    LDMX4(bfr[nxt][np], Bs + (uint32_t)((wn + np * 16) * 128) + rowoff + ck);
            }
            #pragma unroll
            for (int mi = 0; mi < 4; ++mi) {
                #pragma unroll
                for (int np = 0; np < 4; ++np) {
                    uint32_t b0[2] = { bfr[cur][np][0], bfr[cur][np][2] };
                    uint32_t b1[2] = { bfr[cur][np][1], bfr[cur][np][3] };
                    mma_f16(acc[mi][2 * np],     afr[cur][mi], b0);
                    mma_f16(acc[mi][2 * np + 1], afr[cur][mi], b1);
                }
            }
        }
    }

    // epilogue
    #pragma unroll
    for (int mi = 0; mi < 4; ++mi) {
        #pragma unroll
        for (int ni = 0; ni < 8; ++ni) {
            int c = bn + wn + ni * 8 + tq * 2;
            float2 bv = *(const float2*)(bias + c);
            #pragma unroll
            for (int half = 0; half < 2; ++half) {
                int r = bm + wm + mi * 16 + g + half * 8;
                float v0 = acc[mi][ni][half * 2 + 0] + bv.x;
                float v1 = acc[mi][ni][half * 2 + 1] + bv.y;
                if (MODE == 0) {
                    *(float2*)((float*)outv + (size_t)r * N + c) = make_float2(v0, v1);
                } else if (MODE == 1) {
                    *(__half2*)((__half*)outv + (size_t)r * N + c) =
                        __floats2half2_rn(gelu_exact(v0), gelu_exact(v1));
                } else if (MODE == 2) {
                    float2 rv = *(const float2*)(res + (size_t)r * N + c);
                    *(float2*)((float*)outv + (size_t)r * N + c) =
                        make_float2(v0 + rv.x, v1 + rv.y);
                } else if (MODE == 4) {
                    *(__half2*)((__half*)outv + (size_t)r * N + c) =
                        __floats2half2_rn(v0, v1);
                } else {
                    float2 rv = *(const float2*)(res + (size_t)r * N + c);
                    v0 += rv.x; v1 += rv.y;
                    float* out = (float*)outv;
                    int wi = r >> 4, tt = r & 15;
                    int bb2 = wi >> 6, wh = (wi >> 3) & 7, ww = wi & 7;
                    int hh = wh * 4 + (tt >> 2), wc = ww * 4 + (tt & 3);
                    out[(((size_t)bb2 * C_ + c)     * H_ + hh) * W_ + wc] = v0;
                    out[(((size_t)bb2 * C_ + c + 1) * H_ + hh) * W_ + wc] = v1;
                }
            }
        }
    }
}

// ===================================================================
// Kernel 1: transpose [B,C,H,W] -> token rows (window-major), LN1
// ===================================================================
__global__ void __launch_bounds__(256) ln1_kernel(
    const float* __restrict__ x, const float* __restrict__ nw,
    const float* __restrict__ nb, float* __restrict__ xh, __half* __restrict__ xn)
{
    extern __shared__ float tile[];  // [32][513]
    __shared__ float s_sum[32], s_sq[32], s_mean[32], s_rstd[32];
    int bidx = blockIdx.x;
    int bb = bidx >> 5, h = bidx & 31;
    int t = threadIdx.x;
    if (t < 32) { s_sum[t] = 0.f; s_sq[t] = 0.f; }
    __syncthreads();

    const float* xp = x + ((size_t)bb * C_) * (H_ * W_) + (size_t)h * W_;
    float lsum = 0.f, lsq = 0.f;
    for (int idx = t; idx < C_ * 32; idx += 256) {
        int c = idx >> 5, ww = idx & 31;
        float v = xp[(size_t)c * (H_ * W_) + ww];
        tile[ww * 513 + c] = v;
        lsum += v; lsq += v * v;
    }
    atomicAdd(&s_sum[t & 31], lsum);
    atomicAdd(&s_sq [t & 31], lsq);
    __syncthreads();
    if (t < 32) {
        float m = s_sum[t] * (1.f / C_);
        float v = s_sq[t] * (1.f / C_) - m * m;
        s_mean[t] = m; s_rstd[t] = rsqrtf(v + EPS_);
    }
    __syncthreads();

    int wh = h >> 2, i = h & 3;
    for (int idx = t; idx < 32 * C_; idx += 256) {
        int ww = idx >> 9, c = idx & (C_ - 1);
        int wwi = ww >> 2, j = ww & 3;
        int wid = (bb * 8 + wh) * 8 + wwi;
        size_t r = (size_t)wid * NTOK + i * 4 + j;
        float v = tile[ww * 513 + c];
        xh[r * C_ + c] = v;
        xn[r * C_ + c] = __float2half((v - s_mean[ww]) * s_rstd[ww] * nw[c] + nb[c]);
    }
}

// ===================================================================
// windowed attention: block = 1 window; K+V staged in smem (fp16),
// then per-warp head-pair compute with LDS broadcasts. fp32 math.
// ===================================================================
#define ATTN_SMEM (NTOK * 1024 * 2)   // 16 tokens x (512 K + 512 V) halves = 32 KB

__global__ void __launch_bounds__(128) attn_kernel(
    const __half* __restrict__ qkv, const float* __restrict__ rpb,
    __half* __restrict__ ctx)
{
    extern __shared__ __half skv[];   // [16][1024]: cols 0-511 K, 512-1023 V
    int w    = blockIdx.x;
    int tid  = threadIdx.x;
    int lane = tid & 31;
    int warp = tid >> 5;
    int n    = lane & 15;
    int hh   = lane >> 4;
    const float scale = 0.17677669529663687f;
    size_t base = (size_t)w * NTOK * (3 * C_);

    // stage K+V: 16 tokens x 1024 halves = 2048 uint4, coalesced
    {
        const __half* kvsrc = qkv + base + C_;   // K starts at col 512 of each token row
        #pragma unroll
        for (int u = tid; u < 2048; u += 128) {
            int tok = u >> 7;          // 128 uint4 per token
            int c   = u & 127;
            ((uint4*)(skv + tok * 1024))[c] =
                *(const uint4*)(kvsrc + (size_t)tok * (3 * C_) + c * 8);
        }
    }
    __syncthreads();

    #pragma unroll
    for (int it = 0; it < 2; ++it) {
        int head = warp * 4 + it * 2 + hh;
        int hc   = head * HD_;

        float q[32];
        ld32h(qkv + base + (size_t)n * (3 * C_) + hc, q);
        #pragma unroll
        for (int i = 0; i < 32; ++i) q[i] *= scale;

        float s[16];
        int i1 = n >> 2, j1 = n & 3;
        #pragma unroll
        for (int m = 0; m < 16; ++m) {
            float kf[32];
            ld32h(skv + m * 1024 + hc, kf);
            float acc = 0.f;
            #pragma unroll
            for (int i = 0; i < 32; ++i) acc += q[i] * kf[i];
            int i2 = m >> 2, j2 = m & 3;
            int ridx = (i1 - i2 + 3) * 7 + (j1 - j2 + 3);
            s[m] = acc + rpb[ridx * NH_ + head];
        }

        float mx = s[0];
        #pragma unroll
        for (int m = 1; m < 16; ++m) mx = fmaxf(mx, s[m]);
        float sum = 0.f;
        #pragma unroll
        for (int m = 0; m < 16; ++m) { s[m] = expf(s[m] - mx); sum += s[m]; }
        float inv = 1.f / sum;

        float o[32];
        #pragma unroll
        for (int i = 0; i < 32; ++i) o[i] = 0.f;
        #pragma unroll
        for (int m = 0; m < 16; ++m) {
            float p = s[m] * inv;
            float vf[32];
            ld32h(skv + m * 1024 + 512 + hc, vf);
            #pragma unroll
            for (int i = 0; i < 32; ++i) o[i] += p * vf[i];
        }
        __half2* op = (__half2*)(ctx + (size_t)(w * NTOK + n) * C_ + hc);
        #pragma unroll
        for (int i = 0; i < 16; ++i)
            op[i] = __floats2half2_rn(o[2 * i], o[2 * i + 1]);
    }
}

// ===================================================================
// LN2: fp32 in, fp16 out
// ===================================================================
__global__ void __launch_bounds__(128) ln2_kernel(
    const float* __restrict__ in, const float* __restrict__ nw,
    const float* __restrict__ nb, __half* __restrict__ outp)
{
    int r = blockIdx.x;
    int t = threadIdx.x;
    int lane = t & 31, warp = t >> 5;
    float4 v = ((const float4*)(in + (size_t)r * C_))[t];
    float ls = v.x + v.y + v.z + v.w;
    float lq = v.x*v.x + v.y*v.y + v.z*v.z + v.w*v.w;
    #pragma unroll
    for (int off = 16; off; off >>= 1) {
        ls += __shfl_down_sync(0xffffffffu, ls, off);
        lq += __shfl_down_sync(0xffffffffu, lq, off);
    }
    __shared__ float ss[4], sq2[4];
    __shared__ float sm, sr;
    if (lane == 0) { ss[warp] = ls; sq2[warp] = lq; }
    __syncthreads();
    if (t == 0) {
        float S = ss[0] + ss[1] + ss[2] + ss[3];
        float Q = sq2[0] + sq2[1] + sq2[2] + sq2[3];
        float m = S * (1.f / C_);
        float var = Q * (1.f / C_) - m * m;
        sm = m; sr = rsqrtf(var + EPS_);
    }
    __syncthreads();
    float m = sm, rs = sr;
    float4 wv = ((const float4*)nw)[t];
    float4 bv = ((const float4*)nb)[t];
    float o0 = (v.x - m) * rs * wv.x + bv.x;
    float o1 = (v.y - m) * rs * wv.y + bv.y;
    float o2 = (v.z - m) * rs * wv.z + bv.z;
    float o3 = (v.w - m) * rs * wv.w + bv.w;
    __half2* op = (__half2*)(outp + (size_t)r * C_ + t * 4);
    op[0] = __floats2half2_rn(o0, o1);
    op[1] = __floats2half2_rn(o2, o3);
}

// ===================================================================
// host: tensormap creation via driver entry point
// ===================================================================
typedef CUresult (*PFN_encodeTiled)(
    CUtensorMap*, CUtensorMapDataType, cuuint32_t, void*,
    const cuuint64_t*, const cuuint64_t*, const cuuint32_t*, const cuuint32_t*,
    CUtensorMapInterleave, CUtensorMapSwizzle, CUtensorMapL2promotion,
    CUtensorMapFloatOOBfill);

static PFN_encodeTiled get_encoder() {
    static PFN_encodeTiled fn = nullptr;
    if (!fn) {
        void* p = nullptr;
        cudaDriverEntryPointQueryResult qr;
        cudaGetDriverEntryPointByVersion("cuTensorMapEncodeTiled", &p, 12000,
                                         cudaEnableDefault, &qr);
        fn = (PFN_encodeTiled)p;
    }
    return fn;
}

static void make_tm(CUtensorMap* tm, const void* ptr, uint64_t K, uint64_t Rows) {
    cuuint64_t dims[2]    = { K, Rows };
    cuuint64_t strides[1] = { K * 2 };
    cuuint32_t box[2]     = { 64, 128 };
    cuuint32_t es[2]      = { 1, 1 };
    get_encoder()(tm, CU_TENSOR_MAP_DATA_TYPE_UINT16, 2, (void*)ptr,
                  dims, strides, box, es,
                  CU_TENSOR_MAP_INTERLEAVE_NONE, CU_TENSOR_MAP_SWIZZLE_128B,
                  CU_TENSOR_MAP_L2_PROMOTION_L2_128B,
                  CU_TENSOR_MAP_FLOAT_OOB_FILL_NONE);
}

extern "C" void kernel_launch(void* const* d_in, const int* in_sizes, int n_in,
                              void* d_out, int out_size)
{
    const float* x     = (const float*)d_in[0];
    const float* n1w   = (const float*)d_in[1];
    const float* n1b   = (const float*)d_in[2];
    const float* qkvw  = (const float*)d_in[3];
    const float* qkvb  = (const float*)d_in[4];
    const float* rpb   = (const float*)d_in[5];
    const float* projw = (const float*)d_in[6];
    const float* projb = (const float*)d_in[7];
    const float* n2w   = (const float*)d_in[8];
    const float* n2b   = (const float*)d_in[9];
    const float* w1    = (const float*)d_in[10];
    const float* b1    = (const float*)d_in[11];
    const float* w2    = (const float*)d_in[12];
    const float* b2    = (const float*)d_in[13];
    float* out = (float*)d_out;

    float *xh, *xh2;
    __half *qkv_h, *xn_h, *ctx_h, *hn_h, *h1_h, *wq_h, *wp_h, *w1_h, *w2_h;
    cudaGetSymbolAddress((void**)&xh,    g_xh);
    cudaGetSymbolAddress((void**)&xh2,   g_xh2);
    cudaGetSymbolAddress((void**)&qkv_h, g_qkv_h);
    cudaGetSymbolAddress((void**)&xn_h,  g_xn_h);
    cudaGetSymbolAddress((void**)&ctx_h, g_ctx_h);
    cudaGetSymbolAddress((void**)&hn_h,  g_hn_h);
    cudaGetSymbolAddress((void**)&h1_h,  g_h1_h);
    cudaGetSymbolAddress((void**)&wq_h,  g_wq_h);
    cudaGetSymbolAddress((void**)&wp_h,  g_wp_h);
    cudaGetSymbolAddress((void**)&w1_h,  g_w1_h);
    cudaGetSymbolAddress((void**)&w2_h,  g_w2_h);

    static CUtensorMap tmA_xn, tmB_wq, tmA_ctx, tmB_wp, tmA_hn, tmB_w1, tmA_h1, tmB_w2;
    make_tm(&tmA_xn,  xn_h,  C_,   T_);
    make_tm(&tmB_wq,  wq_h,  C_,   3 * C_);
    make_tm(&tmA_ctx, ctx_h, C_,   T_);
    make_tm(&tmB_wp,  wp_h,  C_,   C_);
    make_tm(&tmA_hn,  hn_h,  C_,   T_);
    make_tm(&tmB_w1,  w1_h,  C_,   MLPH);
    make_tm(&tmA_h1,  h1_h,  MLPH, T_);
    make_tm(&tmB_w2,  w2_h,  MLPH, C_);

    int ln1_smem = 32 * 513 * 4;
    cudaFuncSetAttribute(ln1_kernel,  cudaFuncAttributeMaxDynamicSharedMemorySize, ln1_smem);
    cudaFuncSetAttribute(attn_kernel, cudaFuncAttributeMaxDynamicSharedMemorySize, ATTN_SMEM);
    cudaFuncSetAttribute(gemm_h<1>, cudaFuncAttributeMaxDynamicSharedMemorySize, GSMEM);
    cudaFuncSetAttribute(gemm_h<2>, cudaFuncAttributeMaxDynamicSharedMemorySize, GSMEM);
    cudaFuncSetAttribute(gemm_h<3>, cudaFuncAttributeMaxDynamicSharedMemorySize, GSMEM);
    cudaFuncSetAttribute(gemm_h<4>, cudaFuncAttributeMaxDynamicSharedMemorySize, GSMEM);

    // 1. transpose + LN1
    ln1_kernel<<<B_ * H_, 256, ln1_smem>>>(x, n1w, n1b, xh, xn_h);

    // 0. fused weight conversion fp32 -> fp16 (one launch)
    {
        int total = (NQ + NP + N1 + N2) / 4;
        f2h_all_kernel<<<(total + 255) / 256, 256>>>(qkvw, projw, w1, w2,
                                                     wq_h, wp_h, w1_h, w2_h);
    }

    // 2. QKV projection -> fp16 qkv
    gemm_h<4><<<dim3((3 * C_) / 128, T_ / 128), 128, GSMEM>>>(
        tmA_xn, tmB_wq, qkvb, nullptr, qkv_h, 3 * C_, C_);

    // 3. window attention -> fp16 ctx (smem-staged K/V)
    attn_kernel<<<T_ / NTOK, 128, ATTN_SMEM>>>(qkv_h, rpb, ctx_h);

    // 4. proj + bias + residual -> fp32 xh2
    gemm_h<2><<<dim3(C_ / 128, T_ / 128), 128, GSMEM>>>(
        tmA_ctx, tmB_wp, projb, xh, xh2, C_, C_);

    // 5. LN2 -> fp16 hn
    ln2_kernel<<<T_, 128>>>(xh2, n2w, n2b, hn_h);

    // 6. MLP1 + bias + GELU -> fp16 h1
    gemm_h<1><<<dim3(MLPH / 128, T_ / 128), 128, GSMEM>>>(
        tmA_hn, tmB_w1, b1, nullptr, h1_h, MLPH, C_);

    // 7. MLP2 + bias + residual + un-permute to [B,C,H,W]
    gemm_h<3><<<dim3(C_ / 128, T_ / 128), 128, GSMEM>>>(
        tmA_h1, tmB_w2, b2, xh2, out, C_, MLPH);
}

// round 13
// speedup vs baseline: 3.6472x; 1.0343x over previous
#include <cuda_runtime.h>
#include <cuda.h>
#include <cuda_fp16.h>
#include <cstdint>
#include <cstdio>
#include <cstring>

// ---------------- problem constants ----------------
#define B_   32
#define C_   512
#define H_   32
#define W_   32
#define NH_  16
#define WS_  4
#define HD_  32
#define NTOK 16
#define T_   32768
#define MLPH 2048
#define EPS_ 1e-5f

// ---------------- scratch (device globals; no allocs allowed) ----------------
__device__ float  g_xh  [ (size_t)T_ * C_ ];      // residual (window-major)
__device__ float  g_xh2 [ (size_t)T_ * C_ ];      // after proj + residual
__device__ __half g_qkv_h[ (size_t)T_ * 3 * C_ ]; // fp16 qkv
__device__ __half g_xn_h [ (size_t)T_ * C_ ];     // LN1 out (fp16)
__device__ __half g_ctx_h[ (size_t)T_ * C_ ];     // attn context (fp16)
__device__ __half g_hn_h [ (size_t)T_ * C_ ];     // LN2 out (fp16)
__device__ __half g_h1_h [ (size_t)T_ * MLPH ];   // MLP hidden (fp16)
__device__ __half g_wq_h [ (size_t)3 * C_ * C_ ];
__device__ __half g_wp_h [ (size_t)C_ * C_ ];
__device__ __half g_w1_h [ (size_t)MLPH * C_ ];
__device__ __half g_w2_h [ (size_t)C_ * MLPH ];

// ---------------- mma / ldmatrix ----------------
__device__ __forceinline__ void mma_f16(float* c, const uint32_t* a, const uint32_t* b) {
    asm volatile("mma.sync.aligned.m16n8k16.row.col.f32.f16.f16.f32 "
        "{%0,%1,%2,%3}, {%4,%5,%6,%7}, {%8,%9}, {%0,%1,%2,%3};\n"
        : "+f"(c[0]), "+f"(c[1]), "+f"(c[2]), "+f"(c[3])
        : "r"(a[0]), "r"(a[1]), "r"(a[2]), "r"(a[3]),
          "r"(b[0]), "r"(b[1]));
}

#define LDMX4(r, addr) \
    asm volatile("ldmatrix.sync.aligned.m8n8.x4.shared.b16 {%0,%1,%2,%3}, [%4];" \
        : "=r"((r)[0]), "=r"((r)[1]), "=r"((r)[2]), "=r"((r)[3]) : "r"(addr))

#define LDMX4T(r, addr) \
    asm volatile("ldmatrix.sync.aligned.m8n8.x4.trans.shared.b16 {%0,%1,%2,%3}, [%4];" \
        : "=r"((r)[0]), "=r"((r)[1]), "=r"((r)[2]), "=r"((r)[3]) : "r"(addr))

// bit-cast __half2 -> uint32_t (the intrinsic __half2_as_uint does not exist)
__device__ __forceinline__ uint32_t h2u(__half2 h) {
    uint32_t u;
    memcpy(&u, &h, 4);
    return u;
}

// ---------------- TMA / mbarrier ----------------
#define MBARRIER_INIT(mbar, count) \
    asm volatile("mbarrier.init.shared.b64 [%0], %1;" \
        :: "r"((uint32_t)(mbar)), "r"((uint32_t)(count)) : "memory")
#define MBARRIER_EXPECT_TX(mbar, bytes) \
    asm volatile("mbarrier.arrive.expect_tx.shared.b64 _, [%0], %1;" \
        :: "r"((uint32_t)(mbar)), "r"((uint32_t)(bytes)) : "memory")

#define MBARRIER_WAIT_PARITY(mbar, parity) do { \
    uint32_t _m = (uint32_t)(mbar), _p = (uint32_t)(parity), _d; \
    asm volatile("{\n\t.reg .pred p;\n\t" \
        "mbarrier.try_wait.parity.acquire.cta.shared::cta.b64 p, [%1], %2;\n\t" \
        "selp.b32 %0, 1, 0, p;\n\t}" : "=r"(_d) : "r"(_m), "r"(_p) : "memory"); \
    if (!_d) { \
        asm volatile("{\n\t.reg .pred P1;\n\t" \
            "WAIT_LOOP_%=:\n\t" \
            "mbarrier.try_wait.parity.acquire.cta.shared::cta.b64 P1, [%0], %1, 0x989680;\n\t" \
            "@P1 bra.uni WAIT_DONE_%=;\n\t" \
            "bra.uni WAIT_LOOP_%=;\n\t" \
            "WAIT_DONE_%=:\n\t}" :: "r"(_m), "r"(_p) : "memory"); \
    } \
} while (0)

#define TMA2D(saddr, tmap, cx, cy, mbar) \
    asm volatile("cp.async.bulk.tensor.2d.shared::cta.global.tile.mbarrier::complete_tx::bytes " \
        "[%0], [%1, {%2, %3}], [%4];" \
        :: "r"((uint32_t)(saddr)), "l"(tmap), "r"((int32_t)(cx)), "r"((int32_t)(cy)), \
           "r"((uint32_t)(mbar)) : "memory")

__device__ __forceinline__ float gelu_exact(float x) {
    return 0.5f * x * (1.0f + erff(x * 0.7071067811865475f));
}

// ===================================================================
// single fused fp32 -> fp16 conversion of all 4 weight matrices
// ===================================================================
#define NQ (3 * C_ * C_)
#define NP (C_ * C_)
#define N1 (MLPH * C_)
#define N2 (C_ * MLPH)
__global__ void f2h_all_kernel(const float* __restrict__ wq, const float* __restrict__ wp,
                               const float* __restrict__ w1, const float* __restrict__ w2,
                               __half* __restrict__ dq, __half* __restrict__ dp,
                               __half* __restrict__ d1, __half* __restrict__ d2) {
    int i = (blockIdx.x * blockDim.x + threadIdx.x) * 4;
    const float* s; __half* d; int off;
    if (i < NQ)                     { s = wq; d = dq; off = i; }
    else if (i < NQ + NP)           { s = wp; d = dp; off = i - NQ; }
    else if (i < NQ + NP + N1)      { s = w1; d = d1; off = i - NQ - NP; }
    else if (i < NQ + NP + N1 + N2) { s = w2; d = d2; off = i - NQ - NP - N1; }
    else return;
    float4 v = *(const float4*)(s + off);
    __half2* dpp = (__half2*)(d + off);
    dpp[0] = __floats2half2_rn(v.x, v.y);
    dpp[1] = __floats2half2_rn(v.z, v.w);
}

// ===================================================================
// fp16 GEMM (unchanged): TMA + ldmatrix + mma, 128 thr
// ===================================================================
#define STAGE_B  32768
#define MB_OFF   (3 * STAGE_B)
#define GSMEM    (MB_OFF + 128)

template<int MODE>
__global__ void __launch_bounds__(128, 2) gemm_h(
    const __grid_constant__ CUtensorMap tmA,
    const __grid_constant__ CUtensorMap tmB,
    const float* __restrict__ bias, const float* __restrict__ res,
    void* __restrict__ outv, int N, int K)
{
    extern __shared__ __align__(1024) char smem[];
    const uint32_t sbase = (uint32_t)__cvta_generic_to_shared(smem);
    const uint32_t mb = sbase + MB_OFF;

    const int tid  = threadIdx.x;
    const int lane = tid & 31, warp = tid >> 5;
    const int bm   = blockIdx.y * 128;
    const int bn   = blockIdx.x * 128;
    const int wm   = (warp & 1) * 64;
    const int wn   = (warp >> 1) * 64;
    const int tq   = lane & 3, g = lane >> 2;
    const int nK   = K >> 6;

    const int lsub = lane & 7;
    const int lh   = (lane >> 3) & 1;
    const int lk   = lane >> 4;
    const uint32_t rowoff = (uint32_t)((lh * 8 + lsub) * 128);

    if (tid == 0) {
        MBARRIER_INIT(mb,      1);
        MBARRIER_INIT(mb + 8,  1);
        MBARRIER_INIT(mb + 16, 1);
    }
    __syncthreads();

    float acc[4][8][4];
    #pragma unroll
    for (int i = 0; i < 4; ++i)
        #pragma unroll
        for (int j = 0; j < 8; ++j)
            #pragma unroll
            for (int e = 0; e < 4; ++e) acc[i][j][e] = 0.f;

    if (tid == 0) {
        #pragma unroll
        for (int s = 0; s < 2; ++s) {
            MBARRIER_EXPECT_TX(mb + 8 * s, STAGE_B);
            TMA2D(sbase + s * STAGE_B,         &tmA, s * 64, bm, mb + 8 * s);
            TMA2D(sbase + s * STAGE_B + 16384, &tmB, s * 64, bn, mb + 8 * s);
        }
    }

    uint32_t afr[2][4][4], bfr[2][4][4];

    for (int kt = 0; kt < nK; ++kt) {
        const int st = kt % 3;
        MBARRIER_WAIT_PARITY(mb + 8 * st, (kt / 3) & 1);
        __syncthreads();

        if (tid == 0) {
            int kn = kt + 2;
            if (kn < nK) {
                int sn = kn % 3;
                MBARRIER_EXPECT_TX(mb + 8 * sn, STAGE_B);
                TMA2D(sbase + sn * STAGE_B,         &tmA, kn * 64, bm, mb + 8 * sn);
                TMA2D(sbase + sn * STAGE_B + 16384, &tmB, kn * 64, bn, mb + 8 * sn);
            }
        }

        const uint32_t As = sbase + st * STAGE_B;
        const uint32_t Bs = As + 16384;

        {
            const uint32_t ck = (uint32_t)((lk ^ lsub) * 16);
            #pragma unroll
            for (int mi = 0; mi < 4; ++mi)
                LDMX4(afr[0][mi], As + (uint32_t)((wm + mi * 16) * 128) + rowoff + ck);
            #pragma unroll
            for (int np = 0; np < 4; ++np)
                LDMX4(bfr[0][np], Bs + (uint32_t)((wn + np * 16) * 128) + rowoff + ck);
        }

        #pragma unroll
        for (int j = 0; j < 4; ++j) {
            const int cur = j & 1, nxt = cur ^ 1;
            if (j < 3) {
                const uint32_t ck = (uint32_t)((((2 * (j + 1)) + lk) ^ lsub) * 16);
                #pragma unroll
                for (int mi = 0; mi < 4; ++mi)
                    LDMX4(afr[nxt][mi], As + (uint32_t)((wm + mi * 16) * 128) + rowoff + ck);
                #pragma unroll
                for (int np = 0; np < 4; ++np)
                    LDMX4(bfr[nxt][np], Bs + (uint32_t)((wn + np * 16) * 128) + rowoff + ck);
            }
            #pragma unroll
            for (int mi = 0; mi < 4; ++mi) {
                #pragma unroll
                for (int np = 0; np < 4; ++np) {
                    uint32_t b0[2] = { bfr[cur][np][0], bfr[cur][np][2] };
                    uint32_t b1[2] = { bfr[cur][np][1], bfr[cur][np][3] };
                    mma_f16(acc[mi][2 * np],     afr[cur][mi], b0);
                    mma_f16(acc[mi][2 * np + 1], afr[cur][mi], b1);
                }
            }
        }
    }

    #pragma unroll
    for (int mi = 0; mi < 4; ++mi) {
        #pragma unroll
        for (int ni = 0; ni < 8; ++ni) {
            int c = bn + wn + ni * 8 + tq * 2;
            float2 bv = *(const float2*)(bias + c);
            #pragma unroll
            for (int half = 0; half < 2; ++half) {
                int r = bm + wm + mi * 16 + g + half * 8;
                float v0 = acc[mi][ni][half * 2 + 0] + bv.x;
                float v1 = acc[mi][ni][half * 2 + 1] + bv.y;
                if (MODE == 0) {
                    *(float2*)((float*)outv + (size_t)r * N + c) = make_float2(v0, v1);
                } else if (MODE == 1) {
                    *(__half2*)((__half*)outv + (size_t)r * N + c) =
                        __floats2half2_rn(gelu_exact(v0), gelu_exact(v1));
                } else if (MODE == 2) {
                    float2 rv = *(const float2*)(res + (size_t)r * N + c);
                    *(float2*)((float*)outv + (size_t)r * N + c) =
                        make_float2(v0 + rv.x, v1 + rv.y);
                } else if (MODE == 4) {
                    *(__half2*)((__half*)outv + (size_t)r * N + c) =
                        __floats2half2_rn(v0, v1);
                } else {
                    float2 rv = *(const float2*)(res + (size_t)r * N + c);
                    v0 += rv.x; v1 += rv.y;
                    float* out = (float*)outv;
                    int wi = r >> 4, tt = r & 15;
                    int bb2 = wi >> 6, wh = (wi >> 3) & 7, ww = wi & 7;
                    int hh = wh * 4 + (tt >> 2), wc = ww * 4 + (tt & 3);
                    out[(((size_t)bb2 * C_ + c)     * H_ + hh) * W_ + wc] = v0;
                    out[(((size_t)bb2 * C_ + c + 1) * H_ + hh) * W_ + wc] = v1;
                }
            }
        }
    }
}

// ===================================================================
// Kernel 1: transpose [B,C,H,W] -> token rows (window-major), LN1
// ===================================================================
__global__ void __launch_bounds__(256) ln1_kernel(
    const float* __restrict__ x, const float* __restrict__ nw,
    const float* __restrict__ nb, float* __restrict__ xh, __half* __restrict__ xn)
{
    extern __shared__ float tile[];  // [32][513]
    __shared__ float s_sum[32], s_sq[32], s_mean[32], s_rstd[32];
    int bidx = blockIdx.x;
    int bb = bidx >> 5, h = bidx & 31;
    int t = threadIdx.x;
    if (t < 32) { s_sum[t] = 0.f; s_sq[t] = 0.f; }
    __syncthreads();

    const float* xp = x + ((size_t)bb * C_) * (H_ * W_) + (size_t)h * W_;
    float lsum = 0.f, lsq = 0.f;
    for (int idx = t; idx < C_ * 32; idx += 256) {
        int c = idx >> 5, ww = idx & 31;
        float v = xp[(size_t)c * (H_ * W_) + ww];
        tile[ww * 513 + c] = v;
        lsum += v; lsq += v * v;
    }
    atomicAdd(&s_sum[t & 31], lsum);
    atomicAdd(&s_sq [t & 31], lsq);
    __syncthreads();
    if (t < 32) {
        float m = s_sum[t] * (1.f / C_);
        float v = s_sq[t] * (1.f / C_) - m * m;
        s_mean[t] = m; s_rstd[t] = rsqrtf(v + EPS_);
    }
    __syncthreads();

    int wh = h >> 2, i = h & 3;
    for (int idx = t; idx < 32 * C_; idx += 256) {
        int ww = idx >> 9, c = idx & (C_ - 1);
        int wwi = ww >> 2, j = ww & 3;
        int wid = (bb * 8 + wh) * 8 + wwi;
        size_t r = (size_t)wid * NTOK + i * 4 + j;
        float v = tile[ww * 513 + c];
        xh[r * C_ + c] = v;
        xn[r * C_ + c] = __float2half((v - s_mean[ww]) * s_rstd[ww] * nw[c] + nb[c]);
    }
}

// ===================================================================
// MMA windowed attention: block = 1 window, 4 warps, warp = 4 heads.
// QKV staged to smem rows of 1544 halves (stride 3088B: ldmatrix
// conflict-free). S = Q·K^T via 4 HMMA; softmax fp32 in-fragment;
// P packed fp16 (C->A layout identity); PV via 4 HMMA (V .trans).
// ===================================================================
#define AROW 1544                      // halves per staged row (1536 + 8 pad)
#define ATTN_SMEM (NTOK * AROW * 2)    // 49408 B

__global__ void __launch_bounds__(128) attn_kernel(
    const __half* __restrict__ qkv, const float* __restrict__ rpb,
    __half* __restrict__ ctx)
{
    extern __shared__ __half skv[];    // [16][1544]: Q 0-511, K 512-1023, V 1024-1535
    const int w    = blockIdx.x;
    const int tid  = threadIdx.x;
    const int lane = tid & 31;
    const int warp = tid >> 5;
    const int tq   = lane & 3, g = lane >> 2;
    const int lsub = lane & 7, sel = lane >> 3;
    const float scale = 0.17677669529663687f;
    const size_t base = (size_t)w * NTOK * (3 * C_);

    // stage all QKV rows: 16 rows x 192 uint4, 8 threads per row
    {
        const int rr = tid >> 3, cb = tid & 7;
        const __half* src = qkv + base + (size_t)rr * (3 * C_);
        __half* dst = skv + rr * AROW;
        #pragma unroll
        for (int j = 0; j < 24; ++j) {
            int c = cb + j * 8;
            *(uint4*)(dst + c * 8) = *(const uint4*)(src + c * 8);
        }
    }
    __syncthreads();

    const uint32_t sb = (uint32_t)__cvta_generic_to_shared(skv);
    // ldmatrix x4 per-lane address parts: row = (sel&1)*8 + lsub, k-chunk + (sel>>1)*8
    const uint32_t ldrow = (uint32_t)(((sel & 1) * 8 + lsub) * (AROW * 2));
    const uint32_t kadd  = (uint32_t)((sel >> 1) * 16);   // bytes

    // rel-pos bias indices (head-independent); m: 2tq,2tq+1,2tq+8,2tq+9 / rows g,g+8
    auto mkr = [&](int r, int m) {
        return (((r >> 2) - (m >> 2) + 3) * 7 + ((r & 3) - (m & 3) + 3)) * NH_;
    };
    const int m0 = 2 * tq, m1 = 2 * tq + 1, m2 = 2 * tq + 8, m3 = 2 * tq + 9;
    const int bA0 = mkr(g, m0),     bA1 = mkr(g, m1);
    const int bA2 = mkr(g + 8, m0), bA3 = mkr(g + 8, m1);
    const int bB0 = mkr(g, m2),     bB1 = mkr(g, m3);
    const int bB2 = mkr(g + 8, m2), bB3 = mkr(g + 8, m3);

    #pragma unroll
    for (int hi = 0; hi < 4; ++hi) {
        const int head = warp * 4 + hi;
        const uint32_t hb = (uint32_t)(head * HD_ * 2);   // byte offset of head cols

        // ---- S = Q K^T ----
        float sc0[4] = {0.f, 0.f, 0.f, 0.f};   // cols 0-7  (tokens m)
        float sc1[4] = {0.f, 0.f, 0.f, 0.f};   // cols 8-15
        #pragma unroll
        for (int kc = 0; kc < 2; ++kc) {
            uint32_t aq[4], bk[4];
            LDMX4(aq, sb + ldrow + hb + kc * 32 + kadd);
            LDMX4(bk, sb + ldrow + 1024 + hb + kc * 32 + kadd);
            uint32_t b0[2] = { bk[0], bk[2] };
            uint32_t b1[2] = { bk[1], bk[3] };
            mma_f16(sc0, aq, b0);
            mma_f16(sc1, aq, b1);
        }

        // ---- scale + rel-pos bias ----
        sc0[0] = sc0[0] * scale + rpb[bA0 + head];
        sc0[1] = sc0[1] * scale + rpb[bA1 + head];
        sc0[2] = sc0[2] * scale + rpb[bA2 + head];
        sc0[3] = sc0[3] * scale + rpb[bA3 + head];
        sc1[0] = sc1[0] * scale + rpb[bB0 + head];
        sc1[1] = sc1[1] * scale + rpb[bB1 + head];
        sc1[2] = sc1[2] * scale + rpb[bB2 + head];
        sc1[3] = sc1[3] * scale + rpb[bB3 + head];

        // ---- softmax (row g uses c0,c1 of both tiles; row g+8 uses c2,c3) ----
        float mx0 = fmaxf(fmaxf(sc0[0], sc0[1]), fmaxf(sc1[0], sc1[1]));
        float mx1 = fmaxf(fmaxf(sc0[2], sc0[3]), fmaxf(sc1[2], sc1[3]));
        mx0 = fmaxf(mx0, __shfl_xor_sync(0xffffffffu, mx0, 1));
        mx0 = fmaxf(mx0, __shfl_xor_sync(0xffffffffu, mx0, 2));
        mx1 = fmaxf(mx1, __shfl_xor_sync(0xffffffffu, mx1, 1));
        mx1 = fmaxf(mx1, __shfl_xor_sync(0xffffffffu, mx1, 2));
        sc0[0] = expf(sc0[0] - mx0); sc0[1] = expf(sc0[1] - mx0);
        sc1[0] = expf(sc1[0] - mx0); sc1[1] = expf(sc1[1] - mx0);
        sc0[2] = expf(sc0[2] - mx1); sc0[3] = expf(sc0[3] - mx1);
        sc1[2] = expf(sc1[2] - mx1); sc1[3] = expf(sc1[3] - mx1);
        float sm0 = sc0[0] + sc0[1] + sc1[0] + sc1[1];
        float sm1 = sc0[2] + sc0[3] + sc1[2] + sc1[3];
        sm0 += __shfl_xor_sync(0xffffffffu, sm0, 1);
        sm0 += __shfl_xor_sync(0xffffffffu, sm0, 2);
        sm1 += __shfl_xor_sync(0xffffffffu, sm1, 1);
        sm1 += __shfl_xor_sync(0xffffffffu, sm1, 2);
        float inv0 = 1.f / sm0, inv1 = 1.f / sm1;

        // ---- pack P to fp16 A-fragment (C->A layout identity) ----
        uint32_t pa[4];
        pa[0] = h2u(__floats2half2_rn(sc0[0] * inv0, sc0[1] * inv0));
        pa[1] = h2u(__floats2half2_rn(sc0[2] * inv1, sc0[3] * inv1));
        pa[2] = h2u(__floats2half2_rn(sc1[0] * inv0, sc1[1] * inv0));
        pa[3] = h2u(__floats2half2_rn(sc1[2] * inv1, sc1[3] * inv1));

        // ---- O = P V  (V via trans ldmatrix) ----
        uint32_t v0[4], v1[4];
        LDMX4T(v0, sb + ldrow + 2048 + hb + kadd);        // dims 0-15
        LDMX4T(v1, sb + ldrow + 2048 + hb + 32 + kadd);   // dims 16-31
        float oc[4][4];
        #pragma unroll
        for (int t2 = 0; t2 < 4; ++t2)
            #pragma unroll
            for (int e = 0; e < 4; ++e) oc[t2][e] = 0.f;
        { uint32_t b[2] = { v0[0], v0[1] }; mma_f16(oc[0], pa, b); }
        { uint32_t b[2] = { v0[2], v0[3] }; mma_f16(oc[1], pa, b); }
        { uint32_t b[2] = { v1[0], v1[1] }; mma_f16(oc[2], pa, b); }
        { uint32_t b[2] = { v1[2], v1[3] }; mma_f16(oc[3], pa, b); }

        // ---- store ctx (fp16) ----
        __half2* o0 = (__half2*)(ctx + (size_t)(w * NTOK + g)     * C_ + head * HD_);
        __half2* o1 = (__half2*)(ctx + (size_t)(w * NTOK + g + 8) * C_ + head * HD_);
        #pragma unroll
        for (int t2 = 0; t2 < 4; ++t2) {
            o0[t2 * 4 + tq] = __floats2half2_rn(oc[t2][0], oc[t2][1]);
            o1[t2 * 4 + tq] = __floats2half2_rn(oc[t2][2], oc[t2][3]);
        }
    }
}

// ===================================================================
// LN2: fp32 in, fp16 out
// ===================================================================
__global__ void __launch_bounds__(128) ln2_kernel(
    const float* __restrict__ in, const float* __restrict__ nw,
    const float* __restrict__ nb, __half* __restrict__ outp)
{
    int r = blockIdx.x;
    int t = threadIdx.x;
    int lane = t & 31, warp = t >> 5;
    float4 v = ((const float4*)(in + (size_t)r * C_))[t];
    float ls = v.x + v.y + v.z + v.w;
    float lq = v.x*v.x + v.y*v.y + v.z*v.z + v.w*v.w;
    #pragma unroll
    for (int off = 16; off; off >>= 1) {
        ls += __shfl_down_sync(0xffffffffu, ls, off);
        lq += __shfl_down_sync(0xffffffffu, lq, off);
    }
    __shared__ float ss[4], sq2[4];
    __shared__ float sm, sr;
    if (lane == 0) { ss[warp] = ls; sq2[warp] = lq; }
    __syncthreads();
    if (t == 0) {
        float S = ss[0] + ss[1] + ss[2] + ss[3];
        float Q = sq2[0] + sq2[1] + sq2[2] + sq2[3];
        float m = S * (1.f / C_);
        float var = Q * (1.f / C_) - m * m;
        sm = m; sr = rsqrtf(var + EPS_);
    }
    __syncthreads();
    float m = sm, rs = sr;
    float4 wv = ((const float4*)nw)[t];
    float4 bv = ((const float4*)nb)[t];
    float o0 = (v.x - m) * rs * wv.x + bv.x;
    float o1 = (v.y - m) * rs * wv.y + bv.y;
    float o2 = (v.z - m) * rs * wv.z + bv.z;
    float o3 = (v.w - m) * rs * wv.w + bv.w;
    __half2* op = (__half2*)(outp + (size_t)r * C_ + t * 4);
    op[0] = __floats2half2_rn(o0, o1);
    op[1] = __floats2half2_rn(o2, o3);
}

// ===================================================================
// host: tensormap creation via driver entry point
// ===================================================================
typedef CUresult (*PFN_encodeTiled)(
    CUtensorMap*, CUtensorMapDataType, cuuint32_t, void*,
    const cuuint64_t*, const cuuint64_t*, const cuuint32_t*, const cuuint32_t*,
    CUtensorMapInterleave, CUtensorMapSwizzle, CUtensorMapL2promotion,
    CUtensorMapFloatOOBfill);

static PFN_encodeTiled get_encoder() {
    static PFN_encodeTiled fn = nullptr;
    if (!fn) {
        void* p = nullptr;
        cudaDriverEntryPointQueryResult qr;
        cudaGetDriverEntryPointByVersion("cuTensorMapEncodeTiled", &p, 12000,
                                         cudaEnableDefault, &qr);
        fn = (PFN_encodeTiled)p;
    }
    return fn;
}

static void make_tm(CUtensorMap* tm, const void* ptr, uint64_t K, uint64_t Rows) {
    cuuint64_t dims[2]    = { K, Rows };
    cuuint64_t strides[1] = { K * 2 };
    cuuint32_t box[2]     = { 64, 128 };
    cuuint32_t es[2]      = { 1, 1 };
    get_encoder()(tm, CU_TENSOR_MAP_DATA_TYPE_UINT16, 2, (void*)ptr,
                  dims, strides, box, es,
                  CU_TENSOR_MAP_INTERLEAVE_NONE, CU_TENSOR_MAP_SWIZZLE_128B,
                  CU_TENSOR_MAP_L2_PROMOTION_L2_128B,
                  CU_TENSOR_MAP_FLOAT_OOB_FILL_NONE);
}

extern "C" void kernel_launch(void* const* d_in, const int* in_sizes, int n_in,
                              void* d_out, int out_size)
{
    const float* x     = (const float*)d_in[0];
    const float* n1w   = (const float*)d_in[1];
    const float* n1b   = (const float*)d_in[2];
    const float* qkvw  = (const float*)d_in[3];
    const float* qkvb  = (const float*)d_in[4];
    const float* rpb   = (const float*)d_in[5];
    const float* projw = (const float*)d_in[6];
    const float* projb = (const float*)d_in[7];
    const float* n2w   = (const float*)d_in[8];
    const float* n2b   = (const float*)d_in[9];
    const float* w1    = (const float*)d_in[10];
    const float* b1    = (const float*)d_in[11];
    const float* w2    = (const float*)d_in[12];
    const float* b2    = (const float*)d_in[13];
    float* out = (float*)d_out;

    float *xh, *xh2;
    __half *qkv_h, *xn_h, *ctx_h, *hn_h, *h1_h, *wq_h, *wp_h, *w1_h, *w2_h;
    cudaGetSymbolAddress((void**)&xh,    g_xh);
    cudaGetSymbolAddress((void**)&xh2,   g_xh2);
    cudaGetSymbolAddress((void**)&qkv_h, g_qkv_h);
    cudaGetSymbolAddress((void**)&xn_h,  g_xn_h);
    cudaGetSymbolAddress((void**)&ctx_h, g_ctx_h);
    cudaGetSymbolAddress((void**)&hn_h,  g_hn_h);
    cudaGetSymbolAddress((void**)&h1_h,  g_h1_h);
    cudaGetSymbolAddress((void**)&wq_h,  g_wq_h);
    cudaGetSymbolAddress((void**)&wp_h,  g_wp_h);
    cudaGetSymbolAddress((void**)&w1_h,  g_w1_h);
    cudaGetSymbolAddress((void**)&w2_h,  g_w2_h);

    static CUtensorMap tmA_xn, tmB_wq, tmA_ctx, tmB_wp, tmA_hn, tmB_w1, tmA_h1, tmB_w2;
    make_tm(&tmA_xn,  xn_h,  C_,   T_);
    make_tm(&tmB_wq,  wq_h,  C_,   3 * C_);
    make_tm(&tmA_ctx, ctx_h, C_,   T_);
    make_tm(&tmB_wp,  wp_h,  C_,   C_);
    make_tm(&tmA_hn,  hn_h,  C_,   T_);
    make_tm(&tmB_w1,  w1_h,  C_,   MLPH);
    make_tm(&tmA_h1,  h1_h,  MLPH, T_);
    make_tm(&tmB_w2,  w2_h,  MLPH, C_);

    int ln1_smem = 32 * 513 * 4;
    cudaFuncSetAttribute(ln1_kernel,  cudaFuncAttributeMaxDynamicSharedMemorySize, ln1_smem);
    cudaFuncSetAttribute(attn_kernel, cudaFuncAttributeMaxDynamicSharedMemorySize, ATTN_SMEM);
    cudaFuncSetAttribute(gemm_h<1>, cudaFuncAttributeMaxDynamicSharedMemorySize, GSMEM);
    cudaFuncSetAttribute(gemm_h<2>, cudaFuncAttributeMaxDynamicSharedMemorySize, GSMEM);
    cudaFuncSetAttribute(gemm_h<3>, cudaFuncAttributeMaxDynamicSharedMemorySize, GSMEM);
    cudaFuncSetAttribute(gemm_h<4>, cudaFuncAttributeMaxDynamicSharedMemorySize, GSMEM);

    // 1. transpose + LN1
    ln1_kernel<<<B_ * H_, 256, ln1_smem>>>(x, n1w, n1b, xh, xn_h);

    // 0. fused weight conversion fp32 -> fp16 (one launch)
    {
        int total = (NQ + NP + N1 + N2) / 4;
        f2h_all_kernel<<<(total + 255) / 256, 256>>>(qkvw, projw, w1, w2,
                                                     wq_h, wp_h, w1_h, w2_h);
    }

    // 2. QKV projection -> fp16 qkv
    gemm_h<4><<<dim3((3 * C_) / 128, T_ / 128), 128, GSMEM>>>(
        tmA_xn, tmB_wq, qkvb, nullptr, qkv_h, 3 * C_, C_);

    // 3. window attention -> fp16 ctx (MMA path)
    attn_kernel<<<T_ / NTOK, 128, ATTN_SMEM>>>(qkv_h, rpb, ctx_h);

    // 4. proj + bias + residual -> fp32 xh2
    gemm_h<2><<<dim3(C_ / 128, T_ / 128), 128, GSMEM>>>(
        tmA_ctx, tmB_wp, projb, xh, xh2, C_, C_);

    // 5. LN2 -> fp16 hn
    ln2_kernel<<<T_, 128>>>(xh2, n2w, n2b, hn_h);

    // 6. MLP1 + bias + GELU -> fp16 h1
    gemm_h<1><<<dim3(MLPH / 128, T_ / 128), 128, GSMEM>>>(
        tmA_hn, tmB_w1, b1, nullptr, h1_h, MLPH, C_);

    // 7. MLP2 + bias + residual + un-permute to [B,C,H,W]
    gemm_h<3><<<dim3(C_ / 128, T_ / 128), 128, GSMEM>>>(
        tmA_h1, tmB_w2, b2, xh2, out, C_, MLPH);
}

// round 14
// speedup vs baseline: 3.6991x; 1.0142x over previous
#include <cuda_runtime.h>
#include <cuda.h>
#include <cuda_fp16.h>
#include <cstdint>
#include <cstdio>
#include <cstring>

// ---------------- problem constants ----------------
#define B_   32
#define C_   512
#define H_   32
#define W_   32
#define NH_  16
#define WS_  4
#define HD_  32
#define NTOK 16
#define T_   32768
#define MLPH 2048
#define EPS_ 1e-5f

// ---------------- scratch (device globals; no allocs allowed) ----------------
__device__ __half g_xh_h [ (size_t)T_ * C_ ];     // residual (fp16, window-major)
__device__ __half g_xh2_h[ (size_t)T_ * C_ ];     // after proj + residual (fp16)
__device__ __half g_qkv_h[ (size_t)T_ * 3 * C_ ]; // fp16 qkv
__device__ __half g_xn_h [ (size_t)T_ * C_ ];     // LN1 out (fp16)
__device__ __half g_ctx_h[ (size_t)T_ * C_ ];     // attn context (fp16)
__device__ __half g_hn_h [ (size_t)T_ * C_ ];     // LN2 out (fp16)
__device__ __half g_h1_h [ (size_t)T_ * MLPH ];   // MLP hidden (fp16)
__device__ __half g_wq_h [ (size_t)3 * C_ * C_ ];
__device__ __half g_wp_h [ (size_t)C_ * C_ ];
__device__ __half g_w1_h [ (size_t)MLPH * C_ ];
__device__ __half g_w2_h [ (size_t)C_ * MLPH ];

// ---------------- mma / ldmatrix ----------------
__device__ __forceinline__ void mma_f16(float* c, const uint32_t* a, const uint32_t* b) {
    asm volatile("mma.sync.aligned.m16n8k16.row.col.f32.f16.f16.f32 "
        "{%0,%1,%2,%3}, {%4,%5,%6,%7}, {%8,%9}, {%0,%1,%2,%3};\n"
        : "+f"(c[0]), "+f"(c[1]), "+f"(c[2]), "+f"(c[3])
        : "r"(a[0]), "r"(a[1]), "r"(a[2]), "r"(a[3]),
          "r"(b[0]), "r"(b[1]));
}

#define LDMX4(r, addr) \
    asm volatile("ldmatrix.sync.aligned.m8n8.x4.shared.b16 {%0,%1,%2,%3}, [%4];" \
        : "=r"((r)[0]), "=r"((r)[1]), "=r"((r)[2]), "=r"((r)[3]) : "r"(addr))

#define LDMX4T(r, addr) \
    asm volatile("ldmatrix.sync.aligned.m8n8.x4.trans.shared.b16 {%0,%1,%2,%3}, [%4];" \
        : "=r"((r)[0]), "=r"((r)[1]), "=r"((r)[2]), "=r"((r)[3]) : "r"(addr))

// bit-cast __half2 -> uint32_t
__device__ __forceinline__ uint32_t h2u(__half2 h) {
    uint32_t u;
    memcpy(&u, &h, 4);
    return u;
}

// ---------------- TMA / mbarrier ----------------
#define MBARRIER_INIT(mbar, count) \
    asm volatile("mbarrier.init.shared.b64 [%0], %1;" \
        :: "r"((uint32_t)(mbar)), "r"((uint32_t)(count)) : "memory")
#define MBARRIER_EXPECT_TX(mbar, bytes) \
    asm volatile("mbarrier.arrive.expect_tx.shared.b64 _, [%0], %1;" \
        :: "r"((uint32_t)(mbar)), "r"((uint32_t)(bytes)) : "memory")

#define MBARRIER_WAIT_PARITY(mbar, parity) do { \
    uint32_t _m = (uint32_t)(mbar), _p = (uint32_t)(parity), _d; \
    asm volatile("{\n\t.reg .pred p;\n\t" \
        "mbarrier.try_wait.parity.acquire.cta.shared::cta.b64 p, [%1], %2;\n\t" \
        "selp.b32 %0, 1, 0, p;\n\t}" : "=r"(_d) : "r"(_m), "r"(_p) : "memory"); \
    if (!_d) { \
        asm volatile("{\n\t.reg .pred P1;\n\t" \
            "WAIT_LOOP_%=:\n\t" \
            "mbarrier.try_wait.parity.acquire.cta.shared::cta.b64 P1, [%0], %1, 0x989680;\n\t" \
            "@P1 bra.uni WAIT_DONE_%=;\n\t" \
            "bra.uni WAIT_LOOP_%=;\n\t" \
            "WAIT_DONE_%=:\n\t}" :: "r"(_m), "r"(_p) : "memory"); \
    } \
} while (0)

#define TMA2D(saddr, tmap, cx, cy, mbar) \
    asm volatile("cp.async.bulk.tensor.2d.shared::cta.global.tile.mbarrier::complete_tx::bytes " \
        "[%0], [%1, {%2, %3}], [%4];" \
        :: "r"((uint32_t)(saddr)), "l"(tmap), "r"((int32_t)(cx)), "r"((int32_t)(cy)), \
           "r"((uint32_t)(mbar)) : "memory")

__device__ __forceinline__ float gelu_exact(float x) {
    return 0.5f * x * (1.0f + erff(x * 0.7071067811865475f));
}

// ===================================================================
// single fused fp32 -> fp16 conversion of all 4 weight matrices
// ===================================================================
#define NQ (3 * C_ * C_)
#define NP (C_ * C_)
#define N1 (MLPH * C_)
#define N2 (C_ * MLPH)
__global__ void f2h_all_kernel(const float* __restrict__ wq, const float* __restrict__ wp,
                               const float* __restrict__ w1, const float* __restrict__ w2,
                               __half* __restrict__ dq, __half* __restrict__ dp,
                               __half* __restrict__ d1, __half* __restrict__ d2) {
    int i = (blockIdx.x * blockDim.x + threadIdx.x) * 4;
    const float* s; __half* d; int off;
    if (i < NQ)                     { s = wq; d = dq; off = i; }
    else if (i < NQ + NP)           { s = wp; d = dp; off = i - NQ; }
    else if (i < NQ + NP + N1)      { s = w1; d = d1; off = i - NQ - NP; }
    else if (i < NQ + NP + N1 + N2) { s = w2; d = d2; off = i - NQ - NP - N1; }
    else return;
    float4 v = *(const float4*)(s + off);
    __half2* dpp = (__half2*)(d + off);
    dpp[0] = __floats2half2_rn(v.x, v.y);
    dpp[1] = __floats2half2_rn(v.z, v.w);
}

// ===================================================================
// fp16 GEMM: TMA + ldmatrix + mma, 128 thr, CTA 128x128, warp 64x64.
// MODE 1: gelu(+bias) fp16 out
// MODE 2: +bias + fp16 res -> fp16 out
// MODE 3: +bias + fp16 res -> fp32 permuted [B,C,H,W] store
// MODE 4: +bias fp16 out
// ===================================================================
#define STAGE_B  32768
#define MB_OFF   (3 * STAGE_B)
#define GSMEM    (MB_OFF + 128)

template<int MODE>
__global__ void __launch_bounds__(128, 2) gemm_h(
    const __grid_constant__ CUtensorMap tmA,
    const __grid_constant__ CUtensorMap tmB,
    const float* __restrict__ bias, const void* __restrict__ resv,
    void* __restrict__ outv, int N, int K)
{
    extern __shared__ __align__(1024) char smem[];
    const uint32_t sbase = (uint32_t)__cvta_generic_to_shared(smem);
    const uint32_t mb = sbase + MB_OFF;

    const int tid  = threadIdx.x;
    const int lane = tid & 31, warp = tid >> 5;
    const int bm   = blockIdx.y * 128;
    const int bn   = blockIdx.x * 128;
    const int wm   = (warp & 1) * 64;
    const int wn   = (warp >> 1) * 64;
    const int tq   = lane & 3, g = lane >> 2;
    const int nK   = K >> 6;

    const int lsub = lane & 7;
    const int lh   = (lane >> 3) & 1;
    const int lk   = lane >> 4;
    const uint32_t rowoff = (uint32_t)((lh * 8 + lsub) * 128);

    if (tid == 0) {
        MBARRIER_INIT(mb,      1);
        MBARRIER_INIT(mb + 8,  1);
        MBARRIER_INIT(mb + 16, 1);
    }
    __syncthreads();

    float acc[4][8][4];
    #pragma unroll
    for (int i = 0; i < 4; ++i)
        #pragma unroll
        for (int j = 0; j < 8; ++j)
            #pragma unroll
            for (int e = 0; e < 4; ++e) acc[i][j][e] = 0.f;

    if (tid == 0) {
        #pragma unroll
        for (int s = 0; s < 2; ++s) {
            MBARRIER_EXPECT_TX(mb + 8 * s, STAGE_B);
            TMA2D(sbase + s * STAGE_B,         &tmA, s * 64, bm, mb + 8 * s);
            TMA2D(sbase + s * STAGE_B + 16384, &tmB, s * 64, bn, mb + 8 * s);
        }
    }

    uint32_t afr[2][4][4], bfr[2][4][4];

    for (int kt = 0; kt < nK; ++kt) {
        const int st = kt % 3;
        MBARRIER_WAIT_PARITY(mb + 8 * st, (kt / 3) & 1);
        __syncthreads();

        if (tid == 0) {
            int kn = kt + 2;
            if (kn < nK) {
                int sn = kn % 3;
                MBARRIER_EXPECT_TX(mb + 8 * sn, STAGE_B);
                TMA2D(sbase + sn * STAGE_B,         &tmA, kn * 64, bm, mb + 8 * sn);
                TMA2D(sbase + sn * STAGE_B + 16384, &tmB, kn * 64, bn, mb + 8 * sn);
            }
        }

        const uint32_t As = sbase + st * STAGE_B;
        const uint32_t Bs = As + 16384;

        {
            const uint32_t ck = (uint32_t)((lk ^ lsub) * 16);
            #pragma unroll
            for (int mi = 0; mi < 4; ++mi)
                LDMX4(afr[0][mi], As + (uint32_t)((wm + mi * 16) * 128) + rowoff + ck);
            #pragma unroll
            for (int np = 0; np < 4; ++np)
                LDMX4(bfr[0][np], Bs + (uint32_t)((wn + np * 16) * 128) + rowoff + ck);
        }

        #pragma unroll
        for (int j = 0; j < 4; ++j) {
            const int cur = j & 1, nxt = cur ^ 1;
            if (j < 3) {
                const uint32_t ck = (uint32_t)((((2 * (j + 1)) + lk) ^ lsub) * 16);
                #pragma unroll
                for (int mi = 0; mi < 4; ++mi)
                    LDMX4(afr[nxt][mi], As + (uint32_t)((wm + mi * 16) * 128) + rowoff + ck);
                #pragma unroll
                for (int np = 0; np < 4; ++np)
                    LDMX4(bfr[nxt][np], Bs + (uint32_t)((wn + np * 16) * 128) + rowoff + ck);
            }
            #pragma unroll
            for (int mi = 0; mi < 4; ++mi) {
                #pragma unroll
                for (int np = 0; np < 4; ++np) {
                    uint32_t b0[2] = { bfr[cur][np][0], bfr[cur][np][2] };
                    uint32_t b1[2] = { bfr[cur][np][1], bfr[cur][np][3] };
                    mma_f16(acc[mi][2 * np],     afr[cur][mi], b0);
                    mma_f16(acc[mi][2 * np + 1], afr[cur][mi], b1);
                }
            }
        }
    }

    #pragma unroll
    for (int mi = 0; mi < 4; ++mi) {
        #pragma unroll
        for (int ni = 0; ni < 8; ++ni) {
            int c = bn + wn + ni * 8 + tq * 2;
            float2 bv = *(const float2*)(bias + c);
            #pragma unroll
            for (int half = 0; half < 2; ++half) {
                int r = bm + wm + mi * 16 + g + half * 8;
                float v0 = acc[mi][ni][half * 2 + 0] + bv.x;
                float v1 = acc[mi][ni][half * 2 + 1] + bv.y;
                if (MODE == 1) {
                    *(__half2*)((__half*)outv + (size_t)r * N + c) =
                        __floats2half2_rn(gelu_exact(v0), gelu_exact(v1));
                } else if (MODE == 2) {
                    float2 rf = __half22float2(
                        *(const __half2*)((const __half*)resv + (size_t)r * N + c));
                    *(__half2*)((__half*)outv + (size_t)r * N + c) =
                        __floats2half2_rn(v0 + rf.x, v1 + rf.y);
                } else if (MODE == 4) {
                    *(__half2*)((__half*)outv + (size_t)r * N + c) =
                        __floats2half2_rn(v0, v1);
                } else {
                    float2 rf = __half22float2(
                        *(const __half2*)((const __half*)resv + (size_t)r * N + c));
                    v0 += rf.x; v1 += rf.y;
                    float* out = (float*)outv;
                    int wi = r >> 4, tt = r & 15;
                    int bb2 = wi >> 6, wh = (wi >> 3) & 7, ww = wi & 7;
                    int hh = wh * 4 + (tt >> 2), wc = ww * 4 + (tt & 3);
                    out[(((size_t)bb2 * C_ + c)     * H_ + hh) * W_ + wc] = v0;
                    out[(((size_t)bb2 * C_ + c + 1) * H_ + hh) * W_ + wc] = v1;
                }
            }
        }
    }
}

// ===================================================================
// Kernel 1: transpose [B,C,H,W] -> token rows (window-major), LN1
// xh (residual) now fp16
// ===================================================================
__global__ void __launch_bounds__(256) ln1_kernel(
    const float* __restrict__ x, const float* __restrict__ nw,
    const float* __restrict__ nb, __half* __restrict__ xh, __half* __restrict__ xn)
{
    extern __shared__ float tile[];  // [32][513]
    __shared__ float s_sum[32], s_sq[32], s_mean[32], s_rstd[32];
    int bidx = blockIdx.x;
    int bb = bidx >> 5, h = bidx & 31;
    int t = threadIdx.x;
    if (t < 32) { s_sum[t] = 0.f; s_sq[t] = 0.f; }
    __syncthreads();

    const float* xp = x + ((size_t)bb * C_) * (H_ * W_) + (size_t)h * W_;
    float lsum = 0.f, lsq = 0.f;
    for (int idx = t; idx < C_ * 32; idx += 256) {
        int c = idx >> 5, ww = idx & 31;
        float v = xp[(size_t)c * (H_ * W_) + ww];
        tile[ww * 513 + c] = v;
        lsum += v; lsq += v * v;
    }
    atomicAdd(&s_sum[t & 31], lsum);
    atomicAdd(&s_sq [t & 31], lsq);
    __syncthreads();
    if (t < 32) {
        float m = s_sum[t] * (1.f / C_);
        float v = s_sq[t] * (1.f / C_) - m * m;
        s_mean[t] = m; s_rstd[t] = rsqrtf(v + EPS_);
    }
    __syncthreads();

    int wh = h >> 2, i = h & 3;
    for (int idx = t; idx < 32 * C_; idx += 256) {
        int ww = idx >> 9, c = idx & (C_ - 1);
        int wwi = ww >> 2, j = ww & 3;
        int wid = (bb * 8 + wh) * 8 + wwi;
        size_t r = (size_t)wid * NTOK + i * 4 + j;
        float v = tile[ww * 513 + c];
        xh[r * C_ + c] = __float2half(v);
        xn[r * C_ + c] = __float2half((v - s_mean[ww]) * s_rstd[ww] * nw[c] + nb[c]);
    }
}

// ===================================================================
// MMA windowed attention (unchanged from R13)
// ===================================================================
#define AROW 1544
#define ATTN_SMEM (NTOK * AROW * 2)

__global__ void __launch_bounds__(128) attn_kernel(
    const __half* __restrict__ qkv, const float* __restrict__ rpb,
    __half* __restrict__ ctx)
{
    extern __shared__ __half skv[];
    const int w    = blockIdx.x;
    const int tid  = threadIdx.x;
    const int lane = tid & 31;
    const int warp = tid >> 5;
    const int tq   = lane & 3, g = lane >> 2;
    const int lsub = lane & 7, sel = lane >> 3;
    const float scale = 0.17677669529663687f;
    const size_t base = (size_t)w * NTOK * (3 * C_);

    {
        const int rr = tid >> 3, cb = tid & 7;
        const __half* src = qkv + base + (size_t)rr * (3 * C_);
        __half* dst = skv + rr * AROW;
        #pragma unroll
        for (int j = 0; j < 24; ++j) {
            int c = cb + j * 8;
            *(uint4*)(dst + c * 8) = *(const uint4*)(src + c * 8);
        }
    }
    __syncthreads();

    const uint32_t sb = (uint32_t)__cvta_generic_to_shared(skv);
    const uint32_t ldrow = (uint32_t)(((sel & 1) * 8 + lsub) * (AROW * 2));
    const uint32_t kadd  = (uint32_t)((sel >> 1) * 16);

    auto mkr = [&](int r, int m) {
        return (((r >> 2) - (m >> 2) + 3) * 7 + ((r & 3) - (m & 3) + 3)) * NH_;
    };
    const int m0 = 2 * tq, m1 = 2 * tq + 1, m2 = 2 * tq + 8, m3 = 2 * tq + 9;
    const int bA0 = mkr(g, m0),     bA1 = mkr(g, m1);
    const int bA2 = mkr(g + 8, m0), bA3 = mkr(g + 8, m1);
    const int bB0 = mkr(g, m2),     bB1 = mkr(g, m3);
    const int bB2 = mkr(g + 8, m2), bB3 = mkr(g + 8, m3);

    #pragma unroll
    for (int hi = 0; hi < 4; ++hi) {
        const int head = warp * 4 + hi;
        const uint32_t hb = (uint32_t)(head * HD_ * 2);

        float sc0[4] = {0.f, 0.f, 0.f, 0.f};
        float sc1[4] = {0.f, 0.f, 0.f, 0.f};
        #pragma unroll
        for (int kc = 0; kc < 2; ++kc) {
            uint32_t aq[4], bk[4];
            LDMX4(aq, sb + ldrow + hb + kc * 32 + kadd);
            LDMX4(bk, sb + ldrow + 1024 + hb + kc * 32 + kadd);
            uint32_t b0[2] = { bk[0], bk[2] };
            uint32_t b1[2] = { bk[1], bk[3] };
            mma_f16(sc0, aq, b0);
            mma_f16(sc1, aq, b1);
        }

        sc0[0] = sc0[0] * scale + rpb[bA0 + head];
        sc0[1] = sc0[1] * scale + rpb[bA1 + head];
        sc0[2] = sc0[2] * scale + rpb[bA2 + head];
        sc0[3] = sc0[3] * scale + rpb[bA3 + head];
        sc1[0] = sc1[0] * scale + rpb[bB0 + head];
        sc1[1] = sc1[1] * scale + rpb[bB1 + head];
        sc1[2] = sc1[2] * scale + rpb[bB2 + head];
        sc1[3] = sc1[3] * scale + rpb[bB3 + head];

        float mx0 = fmaxf(fmaxf(sc0[0], sc0[1]), fmaxf(sc1[0], sc1[1]));
        float mx1 = fmaxf(fmaxf(sc0[2], sc0[3]), fmaxf(sc1[2], sc1[3]));
        mx0 = fmaxf(mx0, __shfl_xor_sync(0xffffffffu, mx0, 1));
        mx0 = fmaxf(mx0, __shfl_xor_sync(0xffffffffu, mx0, 2));
        mx1 = fmaxf(mx1, __shfl_xor_sync(0xffffffffu, mx1, 1));
        mx1 = fmaxf(mx1, __shfl_xor_sync(0xffffffffu, mx1, 2));
        sc0[0] = expf(sc0[0] - mx0); sc0[1] = expf(sc0[1] - mx0);
        sc1[0] = expf(sc1[0] - mx0); sc1[1] = expf(sc1[1] - mx0);
        sc0[2] = expf(sc0[2] - mx1); sc0[3] = expf(sc0[3] - mx1);
        sc1[2] = expf(sc1[2] - mx1); sc1[3] = expf(sc1[3] - mx1);
        float sm0 = sc0[0] + sc0[1] + sc1[0] + sc1[1];
        float sm1 = sc0[2] + sc0[3] + sc1[2] + sc1[3];
        sm0 += __shfl_xor_sync(0xffffffffu, sm0, 1);
        sm0 += __shfl_xor_sync(0xffffffffu, sm0, 2);
        sm1 += __shfl_xor_sync(0xffffffffu, sm1, 1);
        sm1 += __shfl_xor_sync(0xffffffffu, sm1, 2);
        float inv0 = 1.f / sm0, inv1 = 1.f / sm1;

        uint32_t pa[4];
        pa[0] = h2u(__floats2half2_rn(sc0[0] * inv0, sc0[1] * inv0));
        pa[1] = h2u(__floats2half2_rn(sc0[2] * inv1, sc0[3] * inv1));
        pa[2] = h2u(__floats2half2_rn(sc1[0] * inv0, sc1[1] * inv0));
        pa[3] = h2u(__floats2half2_rn(sc1[2] * inv1, sc1[3] * inv1));

        uint32_t v0[4], v1[4];
        LDMX4T(v0, sb + ldrow + 2048 + hb + kadd);
        LDMX4T(v1, sb + ldrow + 2048 + hb + 32 + kadd);
        float oc[4][4];
        #pragma unroll
        for (int t2 = 0; t2 < 4; ++t2)
            #pragma unroll
            for (int e = 0; e < 4; ++e) oc[t2][e] = 0.f;
        { uint32_t b[2] = { v0[0], v0[1] }; mma_f16(oc[0], pa, b); }
        { uint32_t b[2] = { v0[2], v0[3] }; mma_f16(oc[1], pa, b); }
        { uint32_t b[2] = { v1[0], v1[1] }; mma_f16(oc[2], pa, b); }
        { uint32_t b[2] = { v1[2], v1[3] }; mma_f16(oc[3], pa, b); }

        __half2* o0 = (__half2*)(ctx + (size_t)(w * NTOK + g)     * C_ + head * HD_);
        __half2* o1 = (__half2*)(ctx + (size_t)(w * NTOK + g + 8) * C_ + head * HD_);
        #pragma unroll
        for (int t2 = 0; t2 < 4; ++t2) {
            o0[t2 * 4 + tq] = __floats2half2_rn(oc[t2][0], oc[t2][1]);
            o1[t2 * 4 + tq] = __floats2half2_rn(oc[t2][2], oc[t2][3]);
        }
    }
}

// ===================================================================
// LN2: fp16 in, fp16 out
// ===================================================================
__global__ void __launch_bounds__(128) ln2_kernel(
    const __half* __restrict__ in, const float* __restrict__ nw,
    const float* __restrict__ nb, __half* __restrict__ outp)
{
    int r = blockIdx.x;
    int t = threadIdx.x;
    int lane = t & 31, warp = t >> 5;
    const __half2* ip = (const __half2*)(in + (size_t)r * C_ + t * 4);
    float2 a = __half22float2(ip[0]);
    float2 b = __half22float2(ip[1]);
    float ls = a.x + a.y + b.x + b.y;
    float lq = a.x*a.x + a.y*a.y + b.x*b.x + b.y*b.y;
    #pragma unroll
    for (int off = 16; off; off >>= 1) {
        ls += __shfl_down_sync(0xffffffffu, ls, off);
        lq += __shfl_down_sync(0xffffffffu, lq, off);
    }
    __shared__ float ss[4], sq2[4];
    __shared__ float sm, sr;
    if (lane == 0) { ss[warp] = ls; sq2[warp] = lq; }
    __syncthreads();
    if (t == 0) {
        float S = ss[0] + ss[1] + ss[2] + ss[3];
        float Q = sq2[0] + sq2[1] + sq2[2] + sq2[3];
        float m = S * (1.f / C_);
        float var = Q * (1.f / C_) - m * m;
        sm = m; sr = rsqrtf(var + EPS_);
    }
    __syncthreads();
    float m = sm, rs = sr;
    float4 wv = ((const float4*)nw)[t];
    float4 bv = ((const float4*)nb)[t];
    float o0 = (a.x - m) * rs * wv.x + bv.x;
    float o1 = (a.y - m) * rs * wv.y + bv.y;
    float o2 = (b.x - m) * rs * wv.z + bv.z;
    float o3 = (b.y - m) * rs * wv.w + bv.w;
    __half2* op = (__half2*)(outp + (size_t)r * C_ + t * 4);
    op[0] = __floats2half2_rn(o0, o1);
    op[1] = __floats2half2_rn(o2, o3);
}

// ===================================================================
// host: tensormap creation via driver entry point
// ===================================================================
typedef CUresult (*PFN_encodeTiled)(
    CUtensorMap*, CUtensorMapDataType, cuuint32_t, void*,
    const cuuint64_t*, const cuuint64_t*, const cuuint32_t*, const cuuint32_t*,
    CUtensorMapInterleave, CUtensorMapSwizzle, CUtensorMapL2promotion,
    CUtensorMapFloatOOBfill);

static PFN_encodeTiled get_encoder() {
    static PFN_encodeTiled fn = nullptr;
    if (!fn) {
        void* p = nullptr;
        cudaDriverEntryPointQueryResult qr;
        cudaGetDriverEntryPointByVersion("cuTensorMapEncodeTiled", &p, 12000,
                                         cudaEnableDefault, &qr);
        fn = (PFN_encodeTiled)p;
    }
    return fn;
}

static void make_tm(CUtensorMap* tm, const void* ptr, uint64_t K, uint64_t Rows) {
    cuuint64_t dims[2]    = { K, Rows };
    cuuint64_t strides[1] = { K * 2 };
    cuuint32_t box[2]     = { 64, 128 };
    cuuint32_t es[2]      = { 1, 1 };
    get_encoder()(tm, CU_TENSOR_MAP_DATA_TYPE_UINT16, 2, (void*)ptr,
                  dims, strides, box, es,
                  CU_TENSOR_MAP_INTERLEAVE_NONE, CU_TENSOR_MAP_SWIZZLE_128B,
                  CU_TENSOR_MAP_L2_PROMOTION_L2_128B,
                  CU_TENSOR_MAP_FLOAT_OOB_FILL_NONE);
}

extern "C" void kernel_launch(void* const* d_in, const int* in_sizes, int n_in,
                              void* d_out, int out_size)
{
    const float* x     = (const float*)d_in[0];
    const float* n1w   = (const float*)d_in[1];
    const float* n1b   = (const float*)d_in[2];
    const float* qkvw  = (const float*)d_in[3];
    const float* qkvb  = (const float*)d_in[4];
    const float* rpb   = (const float*)d_in[5];
    const float* projw = (const float*)d_in[6];
    const float* projb = (const float*)d_in[7];
    const float* n2w   = (const float*)d_in[8];
    const float* n2b   = (const float*)d_in[9];
    const float* w1    = (const float*)d_in[10];
    const float* b1    = (const float*)d_in[11];
    const float* w2    = (const float*)d_in[12];
    const float* b2    = (const float*)d_in[13];
    float* out = (float*)d_out;

    __half *xh_h, *xh2_h, *qkv_h, *xn_h, *ctx_h, *hn_h, *h1_h, *wq_h, *wp_h, *w1_h, *w2_h;
    cudaGetSymbolAddress((void**)&xh_h,  g_xh_h);
    cudaGetSymbolAddress((void**)&xh2_h, g_xh2_h);
    cudaGetSymbolAddress((void**)&qkv_h, g_qkv_h);
    cudaGetSymbolAddress((void**)&xn_h,  g_xn_h);
    cudaGetSymbolAddress((void**)&ctx_h, g_ctx_h);
    cudaGetSymbolAddress((void**)&hn_h,  g_hn_h);
    cudaGetSymbolAddress((void**)&h1_h,  g_h1_h);
    cudaGetSymbolAddress((void**)&wq_h,  g_wq_h);
    cudaGetSymbolAddress((void**)&wp_h,  g_wp_h);
    cudaGetSymbolAddress((void**)&w1_h,  g_w1_h);
    cudaGetSymbolAddress((void**)&w2_h,  g_w2_h);

    static CUtensorMap tmA_xn, tmB_wq, tmA_ctx, tmB_wp, tmA_hn, tmB_w1, tmA_h1, tmB_w2;
    make_tm(&tmA_xn,  xn_h,  C_,   T_);
    make_tm(&tmB_wq,  wq_h,  C_,   3 * C_);
    make_tm(&tmA_ctx, ctx_h, C_,   T_);
    make_tm(&tmB_wp,  wp_h,  C_,   C_);
    make_tm(&tmA_hn,  hn_h,  C_,   T_);
    make_tm(&tmB_w1,  w1_h,  C_,   MLPH);
    make_tm(&tmA_h1,  h1_h,  MLPH, T_);
    make_tm(&tmB_w2,  w2_h,  MLPH, C_);

    int ln1_smem = 32 * 513 * 4;
    cudaFuncSetAttribute(ln1_kernel,  cudaFuncAttributeMaxDynamicSharedMemorySize, ln1_smem);
    cudaFuncSetAttribute(attn_kernel, cudaFuncAttributeMaxDynamicSharedMemorySize, ATTN_SMEM);
    cudaFuncSetAttribute(gemm_h<1>, cudaFuncAttributeMaxDynamicSharedMemorySize, GSMEM);
    cudaFuncSetAttribute(gemm_h<2>, cudaFuncAttributeMaxDynamicSharedMemorySize, GSMEM);
    cudaFuncSetAttribute(gemm_h<3>, cudaFuncAttributeMaxDynamicSharedMemorySize, GSMEM);
    cudaFuncSetAttribute(gemm_h<4>, cudaFuncAttributeMaxDynamicSharedMemorySize, GSMEM);

    // 1. transpose + LN1 (fp16 residual + fp16 LN out)
    ln1_kernel<<<B_ * H_, 256, ln1_smem>>>(x, n1w, n1b, xh_h, xn_h);

    // 0. fused weight conversion fp32 -> fp16 (one launch)
    {
        int total = (NQ + NP + N1 + N2) / 4;
        f2h_all_kernel<<<(total + 255) / 256, 256>>>(qkvw, projw, w1, w2,
                                                     wq_h, wp_h, w1_h, w2_h);
    }

    // 2. QKV projection -> fp16 qkv
    gemm_h<4><<<dim3((3 * C_) / 128, T_ / 128), 128, GSMEM>>>(
        tmA_xn, tmB_wq, qkvb, nullptr, qkv_h, 3 * C_, C_);

    // 3. window attention -> fp16 ctx (MMA path)
    attn_kernel<<<T_ / NTOK, 128, ATTN_SMEM>>>(qkv_h, rpb, ctx_h);

    // 4. proj + bias + fp16 residual -> fp16 xh2
    gemm_h<2><<<dim3(C_ / 128, T_ / 128), 128, GSMEM>>>(
        tmA_ctx, tmB_wp, projb, xh_h, xh2_h, C_, C_);

    // 5. LN2 (fp16 in) -> fp16 hn
    ln2_kernel<<<T_, 128>>>(xh2_h, n2w, n2b, hn_h);

    // 6. MLP1 + bias + GELU -> fp16 h1
    gemm_h<1><<<dim3(MLPH / 128, T_ / 128), 128, GSMEM>>>(
        tmA_hn, tmB_w1, b1, nullptr, h1_h, MLPH, C_);

    // 7. MLP2 + bias + fp16 residual -> fp32 permuted [B,C,H,W]
    gemm_h<3><<<dim3(C_ / 128, T_ / 128), 128, GSMEM>>>(
        tmA_h1, tmB_w2, b2, xh2_h, out, C_, MLPH);
}

// round 15
// speedup vs baseline: 3.7711x; 1.0195x over previous
#include <cuda_runtime.h>
#include <cuda.h>
#include <cuda_fp16.h>
#include <cstdint>
#include <cstdio>
#include <cstring>

// ---------------- problem constants ----------------
#define B_   32
#define C_   512
#define H_   32
#define W_   32
#define NH_  16
#define WS_  4
#define HD_  32
#define NTOK 16
#define T_   32768
#define MLPH 2048
#define EPS_ 1e-5f

// ---------------- scratch (device globals; no allocs allowed) ----------------
__device__ __half g_xh_h [ (size_t)T_ * C_ ];
__device__ __half g_xh2_h[ (size_t)T_ * C_ ];
__device__ __half g_qkv_h[ (size_t)T_ * 3 * C_ ];
__device__ __half g_xn_h [ (size_t)T_ * C_ ];
__device__ __half g_ctx_h[ (size_t)T_ * C_ ];
__device__ __half g_hn_h [ (size_t)T_ * C_ ];
__device__ __half g_h1_h [ (size_t)T_ * MLPH ];
__device__ __half g_wq_h [ (size_t)3 * C_ * C_ ];
__device__ __half g_wp_h [ (size_t)C_ * C_ ];
__device__ __half g_w1_h [ (size_t)MLPH * C_ ];
__device__ __half g_w2_h [ (size_t)C_ * MLPH ];

// ---------------- mma / ldmatrix ----------------
__device__ __forceinline__ void mma_f16(float* c, const uint32_t* a, const uint32_t* b) {
    asm volatile("mma.sync.aligned.m16n8k16.row.col.f32.f16.f16.f32 "
        "{%0,%1,%2,%3}, {%4,%5,%6,%7}, {%8,%9}, {%0,%1,%2,%3};\n"
        : "+f"(c[0]), "+f"(c[1]), "+f"(c[2]), "+f"(c[3])
        : "r"(a[0]), "r"(a[1]), "r"(a[2]), "r"(a[3]),
          "r"(b[0]), "r"(b[1]));
}

#define LDMX4(r, addr) \
    asm volatile("ldmatrix.sync.aligned.m8n8.x4.shared.b16 {%0,%1,%2,%3}, [%4];" \
        : "=r"((r)[0]), "=r"((r)[1]), "=r"((r)[2]), "=r"((r)[3]) : "r"(addr))

#define LDMX4T(r, addr) \
    asm volatile("ldmatrix.sync.aligned.m8n8.x4.trans.shared.b16 {%0,%1,%2,%3}, [%4];" \
        : "=r"((r)[0]), "=r"((r)[1]), "=r"((r)[2]), "=r"((r)[3]) : "r"(addr))

__device__ __forceinline__ uint32_t h2u(__half2 h) {
    uint32_t u;
    memcpy(&u, &h, 4);
    return u;
}

// ---------------- TMA / mbarrier ----------------
#define MBARRIER_INIT(mbar, count) \
    asm volatile("mbarrier.init.shared.b64 [%0], %1;" \
        :: "r"((uint32_t)(mbar)), "r"((uint32_t)(count)) : "memory")
#define MBARRIER_EXPECT_TX(mbar, bytes) \
    asm volatile("mbarrier.arrive.expect_tx.shared.b64 _, [%0], %1;" \
        :: "r"((uint32_t)(mbar)), "r"((uint32_t)(bytes)) : "memory")

#define MBARRIER_WAIT_PARITY(mbar, parity) do { \
    uint32_t _m = (uint32_t)(mbar), _p = (uint32_t)(parity), _d; \
    asm volatile("{\n\t.reg .pred p;\n\t" \
        "mbarrier.try_wait.parity.acquire.cta.shared::cta.b64 p, [%1], %2;\n\t" \
        "selp.b32 %0, 1, 0, p;\n\t}" : "=r"(_d) : "r"(_m), "r"(_p) : "memory"); \
    if (!_d) { \
        asm volatile("{\n\t.reg .pred P1;\n\t" \
            "WAIT_LOOP_%=:\n\t" \
            "mbarrier.try_wait.parity.acquire.cta.shared::cta.b64 P1, [%0], %1, 0x989680;\n\t" \
            "@P1 bra.uni WAIT_DONE_%=;\n\t" \
            "bra.uni WAIT_LOOP_%=;\n\t" \
            "WAIT_DONE_%=:\n\t}" :: "r"(_m), "r"(_p) : "memory"); \
    } \
} while (0)

#define TMA2D(saddr, tmap, cx, cy, mbar) \
    asm volatile("cp.async.bulk.tensor.2d.shared::cta.global.tile.mbarrier::complete_tx::bytes " \
        "[%0], [%1, {%2, %3}], [%4];" \
        :: "r"((uint32_t)(saddr)), "l"(tmap), "r"((int32_t)(cx)), "r"((int32_t)(cy)), \
           "r"((uint32_t)(mbar)) : "memory")

__device__ __forceinline__ float gelu_exact(float x) {
    return 0.5f * x * (1.0f + erff(x * 0.7071067811865475f));
}

// ===================================================================
// single fused fp32 -> fp16 conversion of all 4 weight matrices
// ===================================================================
#define NQ (3 * C_ * C_)
#define NP (C_ * C_)
#define N1 (MLPH * C_)
#define N2 (C_ * MLPH)
__global__ void f2h_all_kernel(const float* __restrict__ wq, const float* __restrict__ wp,
                               const float* __restrict__ w1, const float* __restrict__ w2,
                               __half* __restrict__ dq, __half* __restrict__ dp,
                               __half* __restrict__ d1, __half* __restrict__ d2) {
    int i = (blockIdx.x * blockDim.x + threadIdx.x) * 4;
    const float* s; __half* d; int off;
    if (i < NQ)                     { s = wq; d = dq; off = i; }
    else if (i < NQ + NP)           { s = wp; d = dp; off = i - NQ; }
    else if (i < NQ + NP + N1)      { s = w1; d = d1; off = i - NQ - NP; }
    else if (i < NQ + NP + N1 + N2) { s = w2; d = d2; off = i - NQ - NP - N1; }
    else return;
    float4 v = *(const float4*)(s + off);
    __half2* dpp = (__half2*)(d + off);
    dpp[0] = __floats2half2_rn(v.x, v.y);
    dpp[1] = __floats2half2_rn(v.z, v.w);
}

// ===================================================================
// fp16 GEMM: TMA + ldmatrix + mma, 128 thr, CTA 128x128, warp 64x64.
// 2-stage TMA ring (64 KB smem) + __launch_bounds__(128,3):
// 3 CTAs/SM = 12 warps/SM. Single-buffered fragments (reg budget).
// MODE 1: gelu(+bias) fp16 | 2: +bias+fp16 res fp16 |
// MODE 3: +bias+fp16 res -> fp32 permuted [B,C,H,W] | 4: +bias fp16
// ===================================================================
#define STAGE_B  32768
#define MB_OFF   (2 * STAGE_B)
#define GSMEM    (MB_OFF + 128)

template<int MODE>
__global__ void __launch_bounds__(128, 3) gemm_h(
    const __grid_constant__ CUtensorMap tmA,
    const __grid_constant__ CUtensorMap tmB,
    const float* __restrict__ bias, const void* __restrict__ resv,
    void* __restrict__ outv, int N, int K)
{
    extern __shared__ __align__(1024) char smem[];
    const uint32_t sbase = (uint32_t)__cvta_generic_to_shared(smem);
    const uint32_t mb = sbase + MB_OFF;

    const int tid  = threadIdx.x;
    const int lane = tid & 31, warp = tid >> 5;
    const int bm   = blockIdx.y * 128;
    const int bn   = blockIdx.x * 128;
    const int wm   = (warp & 1) * 64;
    const int wn   = (warp >> 1) * 64;
    const int tq   = lane & 3, g = lane >> 2;
    const int nK   = K >> 6;

    const int lsub = lane & 7;
    const int lh   = (lane >> 3) & 1;
    const int lk   = lane >> 4;
    const uint32_t rowoff = (uint32_t)((lh * 8 + lsub) * 128);

    if (tid == 0) {
        MBARRIER_INIT(mb,     1);
        MBARRIER_INIT(mb + 8, 1);
    }
    __syncthreads();

    float acc[4][8][4];
    #pragma unroll
    for (int i = 0; i < 4; ++i)
        #pragma unroll
        for (int j = 0; j < 8; ++j)
            #pragma unroll
            for (int e = 0; e < 4; ++e) acc[i][j][e] = 0.f;

    // prologue: fill stage 0
    if (tid == 0) {
        MBARRIER_EXPECT_TX(mb, STAGE_B);
        TMA2D(sbase,         &tmA, 0, bm, mb);
        TMA2D(sbase + 16384, &tmB, 0, bn, mb);
    }

    for (int kt = 0; kt < nK; ++kt) {
        const int st = kt & 1;
        MBARRIER_WAIT_PARITY(mb + 8 * st, (kt >> 1) & 1);
        __syncthreads();   // all warps finished reading stage st^1 (kt-1)

        if (tid == 0) {
            int kn = kt + 1;
            if (kn < nK) {
                int sn = kn & 1;
                MBARRIER_EXPECT_TX(mb + 8 * sn, STAGE_B);
                TMA2D(sbase + sn * STAGE_B,         &tmA, kn * 64, bm, mb + 8 * sn);
                TMA2D(sbase + sn * STAGE_B + 16384, &tmB, kn * 64, bn, mb + 8 * sn);
            }
        }

        const uint32_t As = sbase + st * STAGE_B;
        const uint32_t Bs = As + 16384;

        #pragma unroll
        for (int j = 0; j < 4; ++j) {
            const uint32_t ck = (uint32_t)((((2 * j) + lk) ^ lsub) * 16);
            uint32_t a[4][4], bb[4][4];
            #pragma unroll
            for (int mi = 0; mi < 4; ++mi)
                LDMX4(a[mi], As + (uint32_t)((wm + mi * 16) * 128) + rowoff + ck);
            #pragma unroll
            for (int np = 0; np < 4; ++np)
                LDMX4(bb[np], Bs + (uint32_t)((wn + np * 16) * 128) + rowoff + ck);
            #pragma unroll
            for (int mi = 0; mi < 4; ++mi) {
                #pragma unroll
                for (int np = 0; np < 4; ++np) {
                    uint32_t b0[2] = { bb[np][0], bb[np][2] };
                    uint32_t b1[2] = { bb[np][1], bb[np][3] };
                    mma_f16(acc[mi][2 * np],     a[mi], b0);
                    mma_f16(acc[mi][2 * np + 1], a[mi], b1);
                }
            }
        }
    }

    #pragma unroll
    for (int mi = 0; mi < 4; ++mi) {
        #pragma unroll
        for (int ni = 0; ni < 8; ++ni) {
            int c = bn + wn + ni * 8 + tq * 2;
            float2 bv = *(const float2*)(bias + c);
            #pragma unroll
            for (int half = 0; half < 2; ++half) {
                int r = bm + wm + mi * 16 + g + half * 8;
                float v0 = acc[mi][ni][half * 2 + 0] + bv.x;
                float v1 = acc[mi][ni][half * 2 + 1] + bv.y;
                if (MODE == 1) {
                    *(__half2*)((__half*)outv + (size_t)r * N + c) =
                        __floats2half2_rn(gelu_exact(v0), gelu_exact(v1));
                } else if (MODE == 2) {
                    float2 rf = __half22float2(
                        *(const __half2*)((const __half*)resv + (size_t)r * N + c));
                    *(__half2*)((__half*)outv + (size_t)r * N + c) =
                        __floats2half2_rn(v0 + rf.x, v1 + rf.y);
                } else if (MODE == 4) {
                    *(__half2*)((__half*)outv + (size_t)r * N + c) =
                        __floats2half2_rn(v0, v1);
                } else {
                    float2 rf = __half22float2(
                        *(const __half2*)((const __half*)resv + (size_t)r * N + c));
                    v0 += rf.x; v1 += rf.y;
                    float* out = (float*)outv;
                    int wi = r >> 4, tt = r & 15;
                    int bb2 = wi >> 6, wh = (wi >> 3) & 7, ww = wi & 7;
                    int hh = wh * 4 + (tt >> 2), wc = ww * 4 + (tt & 3);
                    out[(((size_t)bb2 * C_ + c)     * H_ + hh) * W_ + wc] = v0;
                    out[(((size_t)bb2 * C_ + c + 1) * H_ + hh) * W_ + wc] = v1;
                }
            }
        }
    }
}

// ===================================================================
// Kernel 1: transpose [B,C,H,W] -> token rows (window-major), LN1
// ===================================================================
__global__ void __launch_bounds__(256) ln1_kernel(
    const float* __restrict__ x, const float* __restrict__ nw,
    const float* __restrict__ nb, __half* __restrict__ xh, __half* __restrict__ xn)
{
    extern __shared__ float tile[];  // [32][513]
    __shared__ float s_sum[32], s_sq[32], s_mean[32], s_rstd[32];
    int bidx = blockIdx.x;
    int bb = bidx >> 5, h = bidx & 31;
    int t = threadIdx.x;
    if (t < 32) { s_sum[t] = 0.f; s_sq[t] = 0.f; }
    __syncthreads();

    const float* xp = x + ((size_t)bb * C_) * (H_ * W_) + (size_t)h * W_;
    float lsum = 0.f, lsq = 0.f;
    for (int idx = t; idx < C_ * 32; idx += 256) {
        int c = idx >> 5, ww = idx & 31;
        float v = xp[(size_t)c * (H_ * W_) + ww];
        tile[ww * 513 + c] = v;
        lsum += v; lsq += v * v;
    }
    atomicAdd(&s_sum[t & 31], lsum);
    atomicAdd(&s_sq [t & 31], lsq);
    __syncthreads();
    if (t < 32) {
        float m = s_sum[t] * (1.f / C_);
        float v = s_sq[t] * (1.f / C_) - m * m;
        s_mean[t] = m; s_rstd[t] = rsqrtf(v + EPS_);
    }
    __syncthreads();

    int wh = h >> 2, i = h & 3;
    for (int idx = t; idx < 32 * C_; idx += 256) {
        int ww = idx >> 9, c = idx & (C_ - 1);
        int wwi = ww >> 2, j = ww & 3;
        int wid = (bb * 8 + wh) * 8 + wwi;
        size_t r = (size_t)wid * NTOK + i * 4 + j;
        float v = tile[ww * 513 + c];
        xh[r * C_ + c] = __float2half(v);
        xn[r * C_ + c] = __float2half((v - s_mean[ww]) * s_rstd[ww] * nw[c] + nb[c]);
    }
}

// ===================================================================
// MMA windowed attention (unchanged)
// ===================================================================
#define AROW 1544
#define ATTN_SMEM (NTOK * AROW * 2)

__global__ void __launch_bounds__(128) attn_kernel(
    const __half* __restrict__ qkv, const float* __restrict__ rpb,
    __half* __restrict__ ctx)
{
    extern __shared__ __half skv[];
    const int w    = blockIdx.x;
    const int tid  = threadIdx.x;
    const int lane = tid & 31;
    const int warp = tid >> 5;
    const int tq   = lane & 3, g = lane >> 2;
    const int lsub = lane & 7, sel = lane >> 3;
    const float scale = 0.17677669529663687f;
    const size_t base = (size_t)w * NTOK * (3 * C_);

    {
        const int rr = tid >> 3, cb = tid & 7;
        const __half* src = qkv + base + (size_t)rr * (3 * C_);
        __half* dst = skv + rr * AROW;
        #pragma unroll
        for (int j = 0; j < 24; ++j) {
            int c = cb + j * 8;
            *(uint4*)(dst + c * 8) = *(const uint4*)(src + c * 8);
        }
    }
    __syncthreads();

    const uint32_t sb = (uint32_t)__cvta_generic_to_shared(skv);
    const uint32_t ldrow = (uint32_t)(((sel & 1) * 8 + lsub) * (AROW * 2));
    const uint32_t kadd  = (uint32_t)((sel >> 1) * 16);

    auto mkr = [&](int r, int m) {
        return (((r >> 2) - (m >> 2) + 3) * 7 + ((r & 3) - (m & 3) + 3)) * NH_;
    };
    const int m0 = 2 * tq, m1 = 2 * tq + 1, m2 = 2 * tq + 8, m3 = 2 * tq + 9;
    const int bA0 = mkr(g, m0),     bA1 = mkr(g, m1);
    const int bA2 = mkr(g + 8, m0), bA3 = mkr(g + 8, m1);
    const int bB0 = mkr(g, m2),     bB1 = mkr(g, m3);
    const int bB2 = mkr(g + 8, m2), bB3 = mkr(g + 8, m3);

    #pragma unroll
    for (int hi = 0; hi < 4; ++hi) {
        const int head = warp * 4 + hi;
        const uint32_t hb = (uint32_t)(head * HD_ * 2);

        float sc0[4] = {0.f, 0.f, 0.f, 0.f};
        float sc1[4] = {0.f, 0.f, 0.f, 0.f};
        #pragma unroll
        for (int kc = 0; kc < 2; ++kc) {
            uint32_t aq[4], bk[4];
            LDMX4(aq, sb + ldrow + hb + kc * 32 + kadd);
            LDMX4(bk, sb + ldrow + 1024 + hb + kc * 32 + kadd);
            uint32_t b0[2] = { bk[0], bk[2] };
            uint32_t b1[2] = { bk[1], bk[3] };
            mma_f16(sc0, aq, b0);
            mma_f16(sc1, aq, b1);
        }

        sc0[0] = sc0[0] * scale + rpb[bA0 + head];
        sc0[1] = sc0[1] * scale + rpb[bA1 + head];
        sc0[2] = sc0[2] * scale + rpb[bA2 + head];
        sc0[3] = sc0[3] * scale + rpb[bA3 + head];
        sc1[0] = sc1[0] * scale + rpb[bB0 + head];
        sc1[1] = sc1[1] * scale + rpb[bB1 + head];
        sc1[2] = sc1[2] * scale + rpb[bB2 + head];
        sc1[3] = sc1[3] * scale + rpb[bB3 + head];

        float mx0 = fmaxf(fmaxf(sc0[0], sc0[1]), fmaxf(sc1[0], sc1[1]));
        float mx1 = fmaxf(fmaxf(sc0[2], sc0[3]), fmaxf(sc1[2], sc1[3]));
        mx0 = fmaxf(mx0, __shfl_xor_sync(0xffffffffu, mx0, 1));
        mx0 = fmaxf(mx0, __shfl_xor_sync(0xffffffffu, mx0, 2));
        mx1 = fmaxf(mx1, __shfl_xor_sync(0xffffffffu, mx1, 1));
        mx1 = fmaxf(mx1, __shfl_xor_sync(0xffffffffu, mx1, 2));
        sc0[0] = expf(sc0[0] - mx0); sc0[1] = expf(sc0[1] - mx0);
        sc1[0] = expf(sc1[0] - mx0); sc1[1] = expf(sc1[1] - mx0);
        sc0[2] = expf(sc0[2] - mx1); sc0[3] = expf(sc0[3] - mx1);
        sc1[2] = expf(sc1[2] - mx1); sc1[3] = expf(sc1[3] - mx1);
        float sm0 = sc0[0] + sc0[1] + sc1[0] + sc1[1];
        float sm1 = sc0[2] + sc0[3] + sc1[2] + sc1[3];
        sm0 += __shfl_xor_sync(0xffffffffu, sm0, 1);
        sm0 += __shfl_xor_sync(0xffffffffu, sm0, 2);
        sm1 += __shfl_xor_sync(0xffffffffu, sm1, 1);
        sm1 += __shfl_xor_sync(0xffffffffu, sm1, 2);
        float inv0 = 1.f / sm0, inv1 = 1.f / sm1;

        uint32_t pa[4];
        pa[0] = h2u(__floats2half2_rn(sc0[0] * inv0, sc0[1] * inv0));
        pa[1] = h2u(__floats2half2_rn(sc0[2] * inv1, sc0[3] * inv1));
        pa[2] = h2u(__floats2half2_rn(sc1[0] * inv0, sc1[1] * inv0));
        pa[3] = h2u(__floats2half2_rn(sc1[2] * inv1, sc1[3] * inv1));

        uint32_t v0[4], v1[4];
        LDMX4T(v0, sb + ldrow + 2048 + hb + kadd);
        LDMX4T(v1, sb + ldrow + 2048 + hb + 32 + kadd);
        float oc[4][4];
        #pragma unroll
        for (int t2 = 0; t2 < 4; ++t2)
            #pragma unroll
            for (int e = 0; e < 4; ++e) oc[t2][e] = 0.f;
        { uint32_t b[2] = { v0[0], v0[1] }; mma_f16(oc[0], pa, b); }
        { uint32_t b[2] = { v0[2], v0[3] }; mma_f16(oc[1], pa, b); }
        { uint32_t b[2] = { v1[0], v1[1] }; mma_f16(oc[2], pa, b); }
        { uint32_t b[2] = { v1[2], v1[3] }; mma_f16(oc[3], pa, b); }

        __half2* o0 = (__half2*)(ctx + (size_t)(w * NTOK + g)     * C_ + head * HD_);
        __half2* o1 = (__half2*)(ctx + (size_t)(w * NTOK + g + 8) * C_ + head * HD_);
        #pragma unroll
        for (int t2 = 0; t2 < 4; ++t2) {
            o0[t2 * 4 + tq] = __floats2half2_rn(oc[t2][0], oc[t2][1]);
            o1[t2 * 4 + tq] = __floats2half2_rn(oc[t2][2], oc[t2][3]);
        }
    }
}

// ===================================================================
// LN2: fp16 in, fp16 out
// ===================================================================
__global__ void __launch_bounds__(128) ln2_kernel(
    const __half* __restrict__ in, const float* __restrict__ nw,
    const float* __restrict__ nb, __half* __restrict__ outp)
{
    int r = blockIdx.x;
    int t = threadIdx.x;
    int lane = t & 31, warp = t >> 5;
    const __half2* ip = (const __half2*)(in + (size_t)r * C_ + t * 4);
    float2 a = __half22float2(ip[0]);
    float2 b = __half22float2(ip[1]);
    float ls = a.x + a.y + b.x + b.y;
    float lq = a.x*a.x + a.y*a.y + b.x*b.x + b.y*b.y;
    #pragma unroll
    for (int off = 16; off; off >>= 1) {
        ls += __shfl_down_sync(0xffffffffu, ls, off);
        lq += __shfl_down_sync(0xffffffffu, lq, off);
    }
    __shared__ float ss[4], sq2[4];
    __shared__ float sm, sr;
    if (lane == 0) { ss[warp] = ls; sq2[warp] = lq; }
    __syncthreads();
    if (t == 0) {
        float S = ss[0] + ss[1] + ss[2] + ss[3];
        float Q = sq2[0] + sq2[1] + sq2[2] + sq2[3];
        float m = S * (1.f / C_);
        float var = Q * (1.f / C_) - m * m;
        sm = m; sr = rsqrtf(var + EPS_);
    }
    __syncthreads();
    float m = sm, rs = sr;
    float4 wv = ((const float4*)nw)[t];
    float4 bv = ((const float4*)nb)[t];
    float o0 = (a.x - m) * rs * wv.x + bv.x;
    float o1 = (a.y - m) * rs * wv.y + bv.y;
    float o2 = (b.x - m) * rs * wv.z + bv.z;
    float o3 = (b.y - m) * rs * wv.w + bv.w;
    __half2* op = (__half2*)(outp + (size_t)r * C_ + t * 4);
    op[0] = __floats2half2_rn(o0, o1);
    op[1] = __floats2half2_rn(o2, o3);
}

// ===================================================================
// host: tensormap creation via driver entry point
// ===================================================================
typedef CUresult (*PFN_encodeTiled)(
    CUtensorMap*, CUtensorMapDataType, cuuint32_t, void*,
    const cuuint64_t*, const cuuint64_t*, const cuuint32_t*, const cuuint32_t*,
    CUtensorMapInterleave, CUtensorMapSwizzle, CUtensorMapL2promotion,
    CUtensorMapFloatOOBfill);

static PFN_encodeTiled get_encoder() {
    static PFN_encodeTiled fn = nullptr;
    if (!fn) {
        void* p = nullptr;
        cudaDriverEntryPointQueryResult qr;
        cudaGetDriverEntryPointByVersion("cuTensorMapEncodeTiled", &p, 12000,
                                         cudaEnableDefault, &qr);
        fn = (PFN_encodeTiled)p;
    }
    return fn;
}

static void make_tm(CUtensorMap* tm, const void* ptr, uint64_t K, uint64_t Rows) {
    cuuint64_t dims[2]    = { K, Rows };
    cuuint64_t strides[1] = { K * 2 };
    cuuint32_t box[2]     = { 64, 128 };
    cuuint32_t es[2]      = { 1, 1 };
    get_encoder()(tm, CU_TENSOR_MAP_DATA_TYPE_UINT16, 2, (void*)ptr,
                  dims, strides, box, es,
                  CU_TENSOR_MAP_INTERLEAVE_NONE, CU_TENSOR_MAP_SWIZZLE_128B,
                  CU_TENSOR_MAP_L2_PROMOTION_L2_128B,
                  CU_TENSOR_MAP_FLOAT_OOB_FILL_NONE);
}

extern "C" void kernel_launch(void* const* d_in, const int* in_sizes, int n_in,
                              void* d_out, int out_size)
{
    const float* x     = (const float*)d_in[0];
    const float* n1w   = (const float*)d_in[1];
    const float* n1b   = (const float*)d_in[2];
    const float* qkvw  = (const float*)d_in[3];
    const float* qkvb  = (const float*)d_in[4];
    const float* rpb   = (const float*)d_in[5];
    const float* projw = (const float*)d_in[6];
    const float* projb = (const float*)d_in[7];
    const float* n2w   = (const float*)d_in[8];
    const float* n2b   = (const float*)d_in[9];
    const float* w1    = (const float*)d_in[10];
    const float* b1    = (const float*)d_in[11];
    const float* w2    = (const float*)d_in[12];
    const float* b2    = (const float*)d_in[13];
    float* out = (float*)d_out;

    __half *xh_h, *xh2_h, *qkv_h, *xn_h, *ctx_h, *hn_h, *h1_h, *wq_h, *wp_h, *w1_h, *w2_h;
    cudaGetSymbolAddress((void**)&xh_h,  g_xh_h);
    cudaGetSymbolAddress((void**)&xh2_h, g_xh2_h);
    cudaGetSymbolAddress((void**)&qkv_h, g_qkv_h);
    cudaGetSymbolAddress((void**)&xn_h,  g_xn_h);
    cudaGetSymbolAddress((void**)&ctx_h, g_ctx_h);
    cudaGetSymbolAddress((void**)&hn_h,  g_hn_h);
    cudaGetSymbolAddress((void**)&h1_h,  g_h1_h);
    cudaGetSymbolAddress((void**)&wq_h,  g_wq_h);
    cudaGetSymbolAddress((void**)&wp_h,  g_wp_h);
    cudaGetSymbolAddress((void**)&w1_h,  g_w1_h);
    cudaGetSymbolAddress((void**)&w2_h,  g_w2_h);

    static CUtensorMap tmA_xn, tmB_wq, tmA_ctx, tmB_wp, tmA_hn, tmB_w1, tmA_h1, tmB_w2;
    make_tm(&tmA_xn,  xn_h,  C_,   T_);
    make_tm(&tmB_wq,  wq_h,  C_,   3 * C_);
    make_tm(&tmA_ctx, ctx_h, C_,   T_);
    make_tm(&tmB_wp,  wp_h,  C_,   C_);
    make_tm(&tmA_hn,  hn_h,  C_,   T_);
    make_tm(&tmB_w1,  w1_h,  C_,   MLPH);
    make_tm(&tmA_h1,  h1_h,  MLPH, T_);
    make_tm(&tmB_w2,  w2_h,  MLPH, C_);

    int ln1_smem = 32 * 513 * 4;
    cudaFuncSetAttribute(ln1_kernel,  cudaFuncAttributeMaxDynamicSharedMemorySize, ln1_smem);
    cudaFuncSetAttribute(attn_kernel, cudaFuncAttributeMaxDynamicSharedMemorySize, ATTN_SMEM);
    cudaFuncSetAttribute(gemm_h<1>, cudaFuncAttributeMaxDynamicSharedMemorySize, GSMEM);
    cudaFuncSetAttribute(gemm_h<2>, cudaFuncAttributeMaxDynamicSharedMemorySize, GSMEM);
    cudaFuncSetAttribute(gemm_h<3>, cudaFuncAttributeMaxDynamicSharedMemorySize, GSMEM);
    cudaFuncSetAttribute(gemm_h<4>, cudaFuncAttributeMaxDynamicSharedMemorySize, GSMEM);

    // 1. transpose + LN1 (fp16 residual + fp16 LN out)
    ln1_kernel<<<B_ * H_, 256, ln1_smem>>>(x, n1w, n1b, xh_h, xn_h);

    // 0. fused weight conversion fp32 -> fp16 (one launch)
    {
        int total = (NQ + NP + N1 + N2) / 4;
        f2h_all_kernel<<<(total + 255) / 256, 256>>>(qkvw, projw, w1, w2,
                                                     wq_h, wp_h, w1_h, w2_h);
    }

    // 2. QKV projection -> fp16 qkv
    gemm_h<4><<<dim3((3 * C_) / 128, T_ / 128), 128, GSMEM>>>(
        tmA_xn, tmB_wq, qkvb, nullptr, qkv_h, 3 * C_, C_);

    // 3. window attention -> fp16 ctx (MMA path)
    attn_kernel<<<T_ / NTOK, 128, ATTN_SMEM>>>(qkv_h, rpb, ctx_h);

    // 4. proj + bias + fp16 residual -> fp16 xh2
    gemm_h<2><<<dim3(C_ / 128, T_ / 128), 128, GSMEM>>>(
        tmA_ctx, tmB_wp, projb, xh_h, xh2_h, C_, C_);

    // 5. LN2 (fp16 in) -> fp16 hn
    ln2_kernel<<<T_, 128>>>(xh2_h, n2w, n2b, hn_h);

    // 6. MLP1 + bias + GELU -> fp16 h1
    gemm_h<1><<<dim3(MLPH / 128, T_ / 128), 128, GSMEM>>>(
        tmA_hn, tmB_w1, b1, nullptr, h1_h, MLPH, C_);

    // 7. MLP2 + bias + fp16 residual -> fp32 permuted [B,C,H,W]
    gemm_h<3><<<dim3(C_ / 128, T_ / 128), 128, GSMEM>>>(
        tmA_h1, tmB_w2, b2, xh2_h, out, C_, MLPH);
}

// round 16
// speedup vs baseline: 3.8073x; 1.0096x over previous
#include <cuda_runtime.h>
#include <cuda.h>
#include <cuda_fp16.h>
#include <cstdint>
#include <cstdio>
#include <cstring>

// ---------------- problem constants ----------------
#define B_   32
#define C_   512
#define H_   32
#define W_   32
#define NH_  16
#define WS_  4
#define HD_  32
#define NTOK 16
#define T_   32768
#define MLPH 2048
#define EPS_ 1e-5f

// ---------------- scratch (device globals; no allocs allowed) ----------------
__device__ __half g_xh_h [ (size_t)T_ * C_ ];
__device__ __half g_xh2_h[ (size_t)T_ * C_ ];
__device__ __half g_qkv_h[ (size_t)T_ * 3 * C_ ];
__device__ __half g_xn_h [ (size_t)T_ * C_ ];
__device__ __half g_ctx_h[ (size_t)T_ * C_ ];
__device__ __half g_hn_h [ (size_t)T_ * C_ ];
__device__ __half g_h1_h [ (size_t)T_ * MLPH ];
__device__ __half g_wq_h [ (size_t)3 * C_ * C_ ];
__device__ __half g_wp_h [ (size_t)C_ * C_ ];
__device__ __half g_w1_h [ (size_t)MLPH * C_ ];
__device__ __half g_w2_h [ (size_t)C_ * MLPH ];

// ---------------- mma / ldmatrix ----------------
__device__ __forceinline__ void mma_f16(float* c, const uint32_t* a, const uint32_t* b) {
    asm volatile("mma.sync.aligned.m16n8k16.row.col.f32.f16.f16.f32 "
        "{%0,%1,%2,%3}, {%4,%5,%6,%7}, {%8,%9}, {%0,%1,%2,%3};\n"
        : "+f"(c[0]), "+f"(c[1]), "+f"(c[2]), "+f"(c[3])
        : "r"(a[0]), "r"(a[1]), "r"(a[2]), "r"(a[3]),
          "r"(b[0]), "r"(b[1]));
}

#define LDMX4(r, addr) \
    asm volatile("ldmatrix.sync.aligned.m8n8.x4.shared.b16 {%0,%1,%2,%3}, [%4];" \
        : "=r"((r)[0]), "=r"((r)[1]), "=r"((r)[2]), "=r"((r)[3]) : "r"(addr))

#define LDMX4T(r, addr) \
    asm volatile("ldmatrix.sync.aligned.m8n8.x4.trans.shared.b16 {%0,%1,%2,%3}, [%4];" \
        : "=r"((r)[0]), "=r"((r)[1]), "=r"((r)[2]), "=r"((r)[3]) : "r"(addr))

__device__ __forceinline__ uint32_t h2u(__half2 h) {
    uint32_t u;
    memcpy(&u, &h, 4);
    return u;
}

// ---------------- cp.async (attention staging) ----------------
__device__ __forceinline__ void cp16(const void* sdst, const void* gsrc) {
    uint32_t s = (uint32_t)__cvta_generic_to_shared(sdst);
    asm volatile("cp.async.cg.shared.global [%0], [%1], 16;\n" :: "r"(s), "l"(gsrc));
}
#define CP_COMMIT() asm volatile("cp.async.commit_group;\n" ::: "memory")
#define CP_WAIT0()  asm volatile("cp.async.wait_group 0;\n" ::: "memory")
#define CP_WAIT1()  asm volatile("cp.async.wait_group 1;\n" ::: "memory")

// ---------------- TMA / mbarrier ----------------
#define MBARRIER_INIT(mbar, count) \
    asm volatile("mbarrier.init.shared.b64 [%0], %1;" \
        :: "r"((uint32_t)(mbar)), "r"((uint32_t)(count)) : "memory")
#define MBARRIER_EXPECT_TX(mbar, bytes) \
    asm volatile("mbarrier.arrive.expect_tx.shared.b64 _, [%0], %1;" \
        :: "r"((uint32_t)(mbar)), "r"((uint32_t)(bytes)) : "memory")

#define MBARRIER_WAIT_PARITY(mbar, parity) do { \
    uint32_t _m = (uint32_t)(mbar), _p = (uint32_t)(parity), _d; \
    asm volatile("{\n\t.reg .pred p;\n\t" \
        "mbarrier.try_wait.parity.acquire.cta.shared::cta.b64 p, [%1], %2;\n\t" \
        "selp.b32 %0, 1, 0, p;\n\t}" : "=r"(_d) : "r"(_m), "r"(_p) : "memory"); \
    if (!_d) { \
        asm volatile("{\n\t.reg .pred P1;\n\t" \
            "WAIT_LOOP_%=:\n\t" \
            "mbarrier.try_wait.parity.acquire.cta.shared::cta.b64 P1, [%0], %1, 0x989680;\n\t" \
            "@P1 bra.uni WAIT_DONE_%=;\n\t" \
            "bra.uni WAIT_LOOP_%=;\n\t" \
            "WAIT_DONE_%=:\n\t}" :: "r"(_m), "r"(_p) : "memory"); \
    } \
} while (0)

#define TMA2D(saddr, tmap, cx, cy, mbar) \
    asm volatile("cp.async.bulk.tensor.2d.shared::cta.global.tile.mbarrier::complete_tx::bytes " \
        "[%0], [%1, {%2, %3}], [%4];" \
        :: "r"((uint32_t)(saddr)), "l"(tmap), "r"((int32_t)(cx)), "r"((int32_t)(cy)), \
           "r"((uint32_t)(mbar)) : "memory")

__device__ __forceinline__ float gelu_exact(float x) {
    return 0.5f * x * (1.0f + erff(x * 0.7071067811865475f));
}

// ===================================================================
// single fused fp32 -> fp16 conversion of all 4 weight matrices
// ===================================================================
#define NQ (3 * C_ * C_)
#define NP (C_ * C_)
#define N1 (MLPH * C_)
#define N2 (C_ * MLPH)
__global__ void f2h_all_kernel(const float* __restrict__ wq, const float* __restrict__ wp,
                               const float* __restrict__ w1, const float* __restrict__ w2,
                               __half* __restrict__ dq, __half* __restrict__ dp,
                               __half* __restrict__ d1, __half* __restrict__ d2) {
    int i = (blockIdx.x * blockDim.x + threadIdx.x) * 4;
    const float* s; __half* d; int off;
    if (i < NQ)                     { s = wq; d = dq; off = i; }
    else if (i < NQ + NP)           { s = wp; d = dp; off = i - NQ; }
    else if (i < NQ + NP + N1)      { s = w1; d = d1; off = i - NQ - NP; }
    else if (i < NQ + NP + N1 + N2) { s = w2; d = d2; off = i - NQ - NP - N1; }
    else return;
    float4 v = *(const float4*)(s + off);
    __half2* dpp = (__half2*)(d + off);
    dpp[0] = __floats2half2_rn(v.x, v.y);
    dpp[1] = __floats2half2_rn(v.z, v.w);
}

// ===================================================================
// fp16 GEMM (unchanged from R15): 2-stage TMA ring, 3 CTAs/SM
// ===================================================================
#define STAGE_B  32768
#define MB_OFF   (2 * STAGE_B)
#define GSMEM    (MB_OFF + 128)

template<int MODE>
__global__ void __launch_bounds__(128, 3) gemm_h(
    const __grid_constant__ CUtensorMap tmA,
    const __grid_constant__ CUtensorMap tmB,
    const float* __restrict__ bias, const void* __restrict__ resv,
    void* __restrict__ outv, int N, int K)
{
    extern __shared__ __align__(1024) char smem[];
    const uint32_t sbase = (uint32_t)__cvta_generic_to_shared(smem);
    const uint32_t mb = sbase + MB_OFF;

    const int tid  = threadIdx.x;
    const int lane = tid & 31, warp = tid >> 5;
    const int bm   = blockIdx.y * 128;
    const int bn   = blockIdx.x * 128;
    const int wm   = (warp & 1) * 64;
    const int wn   = (warp >> 1) * 64;
    const int tq   = lane & 3, g = lane >> 2;
    const int nK   = K >> 6;

    const int lsub = lane & 7;
    const int lh   = (lane >> 3) & 1;
    const int lk   = lane >> 4;
    const uint32_t rowoff = (uint32_t)((lh * 8 + lsub) * 128);

    if (tid == 0) {
        MBARRIER_INIT(mb,     1);
        MBARRIER_INIT(mb + 8, 1);
    }
    __syncthreads();

    float acc[4][8][4];
    #pragma unroll
    for (int i = 0; i < 4; ++i)
        #pragma unroll
        for (int j = 0; j < 8; ++j)
            #pragma unroll
            for (int e = 0; e < 4; ++e) acc[i][j][e] = 0.f;

    if (tid == 0) {
        MBARRIER_EXPECT_TX(mb, STAGE_B);
        TMA2D(sbase,         &tmA, 0, bm, mb);
        TMA2D(sbase + 16384, &tmB, 0, bn, mb);
    }

    for (int kt = 0; kt < nK; ++kt) {
        const int st = kt & 1;
        MBARRIER_WAIT_PARITY(mb + 8 * st, (kt >> 1) & 1);
        __syncthreads();

        if (tid == 0) {
            int kn = kt + 1;
            if (kn < nK) {
                int sn = kn & 1;
                MBARRIER_EXPECT_TX(mb + 8 * sn, STAGE_B);
                TMA2D(sbase + sn * STAGE_B,         &tmA, kn * 64, bm, mb + 8 * sn);
                TMA2D(sbase + sn * STAGE_B + 16384, &tmB, kn * 64, bn, mb + 8 * sn);
            }
        }

        const uint32_t As = sbase + st * STAGE_B;
        const uint32_t Bs = As + 16384;

        #pragma unroll
        for (int j = 0; j < 4; ++j) {
            const uint32_t ck = (uint32_t)((((2 * j) + lk) ^ lsub) * 16);
            uint32_t a[4][4], bb[4][4];
            #pragma unroll
            for (int mi = 0; mi < 4; ++mi)
                LDMX4(a[mi], As + (uint32_t)((wm + mi * 16) * 128) + rowoff + ck);
            #pragma unroll
            for (int np = 0; np < 4; ++np)
                LDMX4(bb[np], Bs + (uint32_t)((wn + np * 16) * 128) + rowoff + ck);
            #pragma unroll
            for (int mi = 0; mi < 4; ++mi) {
                #pragma unroll
                for (int np = 0; np < 4; ++np) {
                    uint32_t b0[2] = { bb[np][0], bb[np][2] };
                    uint32_t b1[2] = { bb[np][1], bb[np][3] };
                    mma_f16(acc[mi][2 * np],     a[mi], b0);
                    mma_f16(acc[mi][2 * np + 1], a[mi], b1);
                }
            }
        }
    }

    #pragma unroll
    for (int mi = 0; mi < 4; ++mi) {
        #pragma unroll
        for (int ni = 0; ni < 8; ++ni) {
            int c = bn + wn + ni * 8 + tq * 2;
            float2 bv = *(const float2*)(bias + c);
            #pragma unroll
            for (int half = 0; half < 2; ++half) {
                int r = bm + wm + mi * 16 + g + half * 8;
                float v0 = acc[mi][ni][half * 2 + 0] + bv.x;
                float v1 = acc[mi][ni][half * 2 + 1] + bv.y;
                if (MODE == 1) {
                    *(__half2*)((__half*)outv + (size_t)r * N + c) =
                        __floats2half2_rn(gelu_exact(v0), gelu_exact(v1));
                } else if (MODE == 2) {
                    float2 rf = __half22float2(
                        *(const __half2*)((const __half*)resv + (size_t)r * N + c));
                    *(__half2*)((__half*)outv + (size_t)r * N + c) =
                        __floats2half2_rn(v0 + rf.x, v1 + rf.y);
                } else if (MODE == 4) {
                    *(__half2*)((__half*)outv + (size_t)r * N + c) =
                        __floats2half2_rn(v0, v1);
                } else {
                    float2 rf = __half22float2(
                        *(const __half2*)((const __half*)resv + (size_t)r * N + c));
                    v0 += rf.x; v1 += rf.y;
                    float* out = (float*)outv;
                    int wi = r >> 4, tt = r & 15;
                    int bb2 = wi >> 6, wh = (wi >> 3) & 7, ww = wi & 7;
                    int hh = wh * 4 + (tt >> 2), wc = ww * 4 + (tt & 3);
                    out[(((size_t)bb2 * C_ + c)     * H_ + hh) * W_ + wc] = v0;
                    out[(((size_t)bb2 * C_ + c + 1) * H_ + hh) * W_ + wc] = v1;
                }
            }
        }
    }
}

// ===================================================================
// Kernel 1: transpose [B,C,H,W] -> token rows (window-major), LN1
// ===================================================================
__global__ void __launch_bounds__(256) ln1_kernel(
    const float* __restrict__ x, const float* __restrict__ nw,
    const float* __restrict__ nb, __half* __restrict__ xh, __half* __restrict__ xn)
{
    extern __shared__ float tile[];  // [32][513]
    __shared__ float s_sum[32], s_sq[32], s_mean[32], s_rstd[32];
    int bidx = blockIdx.x;
    int bb = bidx >> 5, h = bidx & 31;
    int t = threadIdx.x;
    if (t < 32) { s_sum[t] = 0.f; s_sq[t] = 0.f; }
    __syncthreads();

    const float* xp = x + ((size_t)bb * C_) * (H_ * W_) + (size_t)h * W_;
    float lsum = 0.f, lsq = 0.f;
    for (int idx = t; idx < C_ * 32; idx += 256) {
        int c = idx >> 5, ww = idx & 31;
        float v = xp[(size_t)c * (H_ * W_) + ww];
        tile[ww * 513 + c] = v;
        lsum += v; lsq += v * v;
    }
    atomicAdd(&s_sum[t & 31], lsum);
    atomicAdd(&s_sq [t & 31], lsq);
    __syncthreads();
    if (t < 32) {
        float m = s_sum[t] * (1.f / C_);
        float v = s_sq[t] * (1.f / C_) - m * m;
        s_mean[t] = m; s_rstd[t] = rsqrtf(v + EPS_);
    }
    __syncthreads();

    int wh = h >> 2, i = h & 3;
    for (int idx = t; idx < 32 * C_; idx += 256) {
        int ww = idx >> 9, c = idx & (C_ - 1);
        int wwi = ww >> 2, j = ww & 3;
        int wid = (bb * 8 + wh) * 8 + wwi;
        size_t r = (size_t)wid * NTOK + i * 4 + j;
        float v = tile[ww * 513 + c];
        xh[r * C_ + c] = __float2half(v);
        xn[r * C_ + c] = __float2half((v - s_mean[ww]) * s_rstd[ww] * nw[c] + nb[c]);
    }
}

// ===================================================================
// MMA windowed attention, pipelined: block = 4 windows, double-buffered
// cp.async staging (issue w+1 while computing w). Compute body = R13 MMA.
// ===================================================================
#define AROW 1544
#define ABUF (NTOK * AROW)               // halves per buffer
#define WPB  4
#define ATTN_SMEM (2 * ABUF * 2)         // 98816 B

__global__ void __launch_bounds__(128) attn_kernel(
    const __half* __restrict__ qkv, const float* __restrict__ rpb,
    __half* __restrict__ ctx)
{
    extern __shared__ __half skv[];
    const int tid  = threadIdx.x;
    const int lane = tid & 31;
    const int warp = tid >> 5;
    const int tq   = lane & 3, g = lane >> 2;
    const int lsub = lane & 7, sel = lane >> 3;
    const float scale = 0.17677669529663687f;
    const int w0 = blockIdx.x * WPB;

    const int rr = tid >> 3, cb = tid & 7;

    auto stage = [&](int buf, int w) {
        const __half* src = qkv + ((size_t)(w * NTOK + rr)) * (3 * C_);
        __half* dst = skv + buf * ABUF + rr * AROW;
        #pragma unroll
        for (int j = 0; j < 24; ++j) {
            int c = cb + j * 8;
            cp16(dst + c * 8, src + c * 8);
        }
        CP_COMMIT();
    };

    const uint32_t sb = (uint32_t)__cvta_generic_to_shared(skv);
    const uint32_t ldrow = (uint32_t)(((sel & 1) * 8 + lsub) * (AROW * 2));
    const uint32_t kadd  = (uint32_t)((sel >> 1) * 16);

    auto mkr = [&](int r, int m) {
        return (((r >> 2) - (m >> 2) + 3) * 7 + ((r & 3) - (m & 3) + 3)) * NH_;
    };
    const int m0 = 2 * tq, m1 = 2 * tq + 1, m2 = 2 * tq + 8, m3 = 2 * tq + 9;
    const int bA0 = mkr(g, m0),     bA1 = mkr(g, m1);
    const int bA2 = mkr(g + 8, m0), bA3 = mkr(g + 8, m1);
    const int bB0 = mkr(g, m2),     bB1 = mkr(g, m3);
    const int bB2 = mkr(g + 8, m2), bB3 = mkr(g + 8, m3);

    stage(0, w0);

    #pragma unroll 1
    for (int i = 0; i < WPB; ++i) {
        if (i > 0) __syncthreads();          // compute(i-1) done before overwriting its buffer
        if (i < WPB - 1) { stage((i + 1) & 1, w0 + i + 1); CP_WAIT1(); }
        else             { CP_WAIT0(); }
        __syncthreads();

        const int w = w0 + i;
        const uint32_t bufb = sb + (uint32_t)((i & 1) * ABUF * 2);

        #pragma unroll
        for (int hi = 0; hi < 4; ++hi) {
            const int head = warp * 4 + hi;
            const uint32_t hb = (uint32_t)(head * HD_ * 2);

            float sc0[4] = {0.f, 0.f, 0.f, 0.f};
            float sc1[4] = {0.f, 0.f, 0.f, 0.f};
            #pragma unroll
            for (int kc = 0; kc < 2; ++kc) {
                uint32_t aq[4], bk[4];
                LDMX4(aq, bufb + ldrow + hb + kc * 32 + kadd);
                LDMX4(bk, bufb + ldrow + 1024 + hb + kc * 32 + kadd);
                uint32_t b0[2] = { bk[0], bk[2] };
                uint32_t b1[2] = { bk[1], bk[3] };
                mma_f16(sc0, aq, b0);
                mma_f16(sc1, aq, b1);
            }

            sc0[0] = sc0[0] * scale + rpb[bA0 + head];
            sc0[1] = sc0[1] * scale + rpb[bA1 + head];
            sc0[2] = sc0[2] * scale + rpb[bA2 + head];
            sc0[3] = sc0[3] * scale + rpb[bA3 + head];
            sc1[0] = sc1[0] * scale + rpb[bB0 + head];
            sc1[1] = sc1[1] * scale + rpb[bB1 + head];
            sc1[2] = sc1[2] * scale + rpb[bB2 + head];
            sc1[3] = sc1[3] * scale + rpb[bB3 + head];

            float mx0 = fmaxf(fmaxf(sc0[0], sc0[1]), fmaxf(sc1[0], sc1[1]));
            float mx1 = fmaxf(fmaxf(sc0[2], sc0[3]), fmaxf(sc1[2], sc1[3]));
            mx0 = fmaxf(mx0, __shfl_xor_sync(0xffffffffu, mx0, 1));
            mx0 = fmaxf(mx0, __shfl_xor_sync(0xffffffffu, mx0, 2));
            mx1 = fmaxf(mx1, __shfl_xor_sync(0xffffffffu, mx1, 1));
            mx1 = fmaxf(mx1, __shfl_xor_sync(0xffffffffu, mx1, 2));
            sc0[0] = expf(sc0[0] - mx0); sc0[1] = expf(sc0[1] - mx0);
            sc1[0] = expf(sc1[0] - mx0); sc1[1] = expf(sc1[1] - mx0);
            sc0[2] = expf(sc0[2] - mx1); sc0[3] = expf(sc0[3] - mx1);
            sc1[2] = expf(sc1[2] - mx1); sc1[3] = expf(sc1[3] - mx1);
            float sm0 = sc0[0] + sc0[1] + sc1[0] + sc1[1];
            float sm1 = sc0[2] + sc0[3] + sc1[2] + sc1[3];
            sm0 += __shfl_xor_sync(0xffffffffu, sm0, 1);
            sm0 += __shfl_xor_sync(0xffffffffu, sm0, 2);
            sm1 += __shfl_xor_sync(0xffffffffu, sm1, 1);
            sm1 += __shfl_xor_sync(0xffffffffu, sm1, 2);
            float inv0 = 1.f / sm0, inv1 = 1.f / sm1;

            uint32_t pa[4];
            pa[0] = h2u(__floats2half2_rn(sc0[0] * inv0, sc0[1] * inv0));
            pa[1] = h2u(__floats2half2_rn(sc0[2] * inv1, sc0[3] * inv1));
            pa[2] = h2u(__floats2half2_rn(sc1[0] * inv0, sc1[1] * inv0));
            pa[3] = h2u(__floats2half2_rn(sc1[2] * inv1, sc1[3] * inv1));

            uint32_t v0[4], v1[4];
            LDMX4T(v0, bufb + ldrow + 2048 + hb + kadd);
            LDMX4T(v1, bufb + ldrow + 2048 + hb + 32 + kadd);
            float oc[4][4];
            #pragma unroll
            for (int t2 = 0; t2 < 4; ++t2)
                #pragma unroll
                for (int e = 0; e < 4; ++e) oc[t2][e] = 0.f;
            { uint32_t b[2] = { v0[0], v0[1] }; mma_f16(oc[0], pa, b); }
            { uint32_t b[2] = { v0[2], v0[3] }; mma_f16(oc[1], pa, b); }
            { uint32_t b[2] = { v1[0], v1[1] }; mma_f16(oc[2], pa, b); }
            { uint32_t b[2] = { v1[2], v1[3] }; mma_f16(oc[3], pa, b); }

            __half2* o0 = (__half2*)(ctx + (size_t)(w * NTOK + g)     * C_ + head * HD_);
            __half2* o1 = (__half2*)(ctx + (size_t)(w * NTOK + g + 8) * C_ + head * HD_);
            #pragma unroll
            for (int t2 = 0; t2 < 4; ++t2) {
                o0[t2 * 4 + tq] = __floats2half2_rn(oc[t2][0], oc[t2][1]);
                o1[t2 * 4 + tq] = __floats2half2_rn(oc[t2][2], oc[t2][3]);
            }
        }
    }
}

// ===================================================================
// LN2: fp16 in, fp16 out
// ===================================================================
__global__ void __launch_bounds__(128) ln2_kernel(
    const __half* __restrict__ in, const float* __restrict__ nw,
    const float* __restrict__ nb, __half* __restrict__ outp)
{
    int r = blockIdx.x;
    int t = threadIdx.x;
    int lane = t & 31, warp = t >> 5;
    const __half2* ip = (const __half2*)(in + (size_t)r * C_ + t * 4);
    float2 a = __half22float2(ip[0]);
    float2 b = __half22float2(ip[1]);
    float ls = a.x + a.y + b.x + b.y;
    float lq = a.x*a.x + a.y*a.y + b.x*b.x + b.y*b.y;
    #pragma unroll
    for (int off = 16; off; off >>= 1) {
        ls += __shfl_down_sync(0xffffffffu, ls, off);
        lq += __shfl_down_sync(0xffffffffu, lq, off);
    }
    __shared__ float ss[4], sq2[4];
    __shared__ float sm, sr;
    if (lane == 0) { ss[warp] = ls; sq2[warp] = lq; }
    __syncthreads();
    if (t == 0) {
        float S = ss[0] + ss[1] + ss[2] + ss[3];
        float Q = sq2[0] + sq2[1] + sq2[2] + sq2[3];
        float m = S * (1.f / C_);
        float var = Q * (1.f / C_) - m * m;
        sm = m; sr = rsqrtf(var + EPS_);
    }
    __syncthreads();
    float m = sm, rs = sr;
    float4 wv = ((const float4*)nw)[t];
    float4 bv = ((const float4*)nb)[t];
    float o0 = (a.x - m) * rs * wv.x + bv.x;
    float o1 = (a.y - m) * rs * wv.y + bv.y;
    float o2 = (b.x - m) * rs * wv.z + bv.z;
    float o3 = (b.y - m) * rs * wv.w + bv.w;
    __half2* op = (__half2*)(outp + (size_t)r * C_ + t * 4);
    op[0] = __floats2half2_rn(o0, o1);
    op[1] = __floats2half2_rn(o2, o3);
}

// ===================================================================
// host: tensormap creation via driver entry point
// ===================================================================
typedef CUresult (*PFN_encodeTiled)(
    CUtensorMap*, CUtensorMapDataType, cuuint32_t, void*,
    const cuuint64_t*, const cuuint64_t*, const cuuint32_t*, const cuuint32_t*,
    CUtensorMapInterleave, CUtensorMapSwizzle, CUtensorMapL2promotion,
    CUtensorMapFloatOOBfill);

static PFN_encodeTiled get_encoder() {
    static PFN_encodeTiled fn = nullptr;
    if (!fn) {
        void* p = nullptr;
        cudaDriverEntryPointQueryResult qr;
        cudaGetDriverEntryPointByVersion("cuTensorMapEncodeTiled", &p, 12000,
                                         cudaEnableDefault, &qr);
        fn = (PFN_encodeTiled)p;
    }
    return fn;
}

static void make_tm(CUtensorMap* tm, const void* ptr, uint64_t K, uint64_t Rows) {
    cuuint64_t dims[2]    = { K, Rows };
    cuuint64_t strides[1] = { K * 2 };
    cuuint32_t box[2]     = { 64, 128 };
    cuuint32_t es[2]      = { 1, 1 };
    get_encoder()(tm, CU_TENSOR_MAP_DATA_TYPE_UINT16, 2, (void*)ptr,
                  dims, strides, box, es,
                  CU_TENSOR_MAP_INTERLEAVE_NONE, CU_TENSOR_MAP_SWIZZLE_128B,
                  CU_TENSOR_MAP_L2_PROMOTION_L2_128B,
                  CU_TENSOR_MAP_FLOAT_OOB_FILL_NONE);
}

extern "C" void kernel_launch(void* const* d_in, const int* in_sizes, int n_in,
                              void* d_out, int out_size)
{
    const float* x     = (const float*)d_in[0];
    const float* n1w   = (const float*)d_in[1];
    const float* n1b   = (const float*)d_in[2];
    const float* qkvw  = (const float*)d_in[3];
    const float* qkvb  = (const float*)d_in[4];
    const float* rpb   = (const float*)d_in[5];
    const float* projw = (const float*)d_in[6];
    const float* projb = (const float*)d_in[7];
    const float* n2w   = (const float*)d_in[8];
    const float* n2b   = (const float*)d_in[9];
    const float* w1    = (const float*)d_in[10];
    const float* b1    = (const float*)d_in[11];
    const float* w2    = (const float*)d_in[12];
    const float* b2    = (const float*)d_in[13];
    float* out = (float*)d_out;

    __half *xh_h, *xh2_h, *qkv_h, *xn_h, *ctx_h, *hn_h, *h1_h, *wq_h, *wp_h, *w1_h, *w2_h;
    cudaGetSymbolAddress((void**)&xh_h,  g_xh_h);
    cudaGetSymbolAddress((void**)&xh2_h, g_xh2_h);
    cudaGetSymbolAddress((void**)&qkv_h, g_qkv_h);
    cudaGetSymbolAddress((void**)&xn_h,  g_xn_h);
    cudaGetSymbolAddress((void**)&ctx_h, g_ctx_h);
    cudaGetSymbolAddress((void**)&hn_h,  g_hn_h);
    cudaGetSymbolAddress((void**)&h1_h,  g_h1_h);
    cudaGetSymbolAddress((void**)&wq_h,  g_wq_h);
    cudaGetSymbolAddress((void**)&wp_h,  g_wp_h);
    cudaGetSymbolAddress((void**)&w1_h,  g_w1_h);
    cudaGetSymbolAddress((void**)&w2_h,  g_w2_h);

    static CUtensorMap tmA_xn, tmB_wq, tmA_ctx, tmB_wp, tmA_hn, tmB_w1, tmA_h1, tmB_w2;
    make_tm(&tmA_xn,  xn_h,  C_,   T_);
    make_tm(&tmB_wq,  wq_h,  C_,   3 * C_);
    make_tm(&tmA_ctx, ctx_h, C_,   T_);
    make_tm(&tmB_wp,  wp_h,  C_,   C_);
    make_tm(&tmA_hn,  hn_h,  C_,   T_);
    make_tm(&tmB_w1,  w1_h,  C_,   MLPH);
    make_tm(&tmA_h1,  h1_h,  MLPH, T_);
    make_tm(&tmB_w2,  w2_h,  MLPH, C_);

    int ln1_smem = 32 * 513 * 4;
    cudaFuncSetAttribute(ln1_kernel,  cudaFuncAttributeMaxDynamicSharedMemorySize, ln1_smem);
    cudaFuncSetAttribute(attn_kernel, cudaFuncAttributeMaxDynamicSharedMemorySize, ATTN_SMEM);
    cudaFuncSetAttribute(gemm_h<1>, cudaFuncAttributeMaxDynamicSharedMemorySize, GSMEM);
    cudaFuncSetAttribute(gemm_h<2>, cudaFuncAttributeMaxDynamicSharedMemorySize, GSMEM);
    cudaFuncSetAttribute(gemm_h<3>, cudaFuncAttributeMaxDynamicSharedMemorySize, GSMEM);
    cudaFuncSetAttribute(gemm_h<4>, cudaFuncAttributeMaxDynamicSharedMemorySize, GSMEM);

    // 1. transpose + LN1 (fp16 residual + fp16 LN out)
    ln1_kernel<<<B_ * H_, 256, ln1_smem>>>(x, n1w, n1b, xh_h, xn_h);

    // 0. fused weight conversion fp32 -> fp16 (one launch)
    {
        int total = (NQ + NP + N1 + N2) / 4;
        f2h_all_kernel<<<(total + 255) / 256, 256>>>(qkvw, projw, w1, w2,
                                                     wq_h, wp_h, w1_h, w2_h);
    }

    // 2. QKV projection -> fp16 qkv
    gemm_h<4><<<dim3((3 * C_) / 128, T_ / 128), 128, GSMEM>>>(
        tmA_xn, tmB_wq, qkvb, nullptr, qkv_h, 3 * C_, C_);

    // 3. window attention -> fp16 ctx (pipelined 4 windows/block)
    attn_kernel<<<T_ / NTOK / WPB, 128, ATTN_SMEM>>>(qkv_h, rpb, ctx_h);

    // 4. proj + bias + fp16 residual -> fp16 xh2
    gemm_h<2><<<dim3(C_ / 128, T_ / 128), 128, GSMEM>>>(
        tmA_ctx, tmB_wp, projb, xh_h, xh2_h, C_, C_);

    // 5. LN2 (fp16 in) -> fp16 hn
    ln2_kernel<<<T_, 128>>>(xh2_h, n2w, n2b, hn_h);

    // 6. MLP1 + bias + GELU -> fp16 h1
    gemm_h<1><<<dim3(MLPH / 128, T_ / 128), 128, GSMEM>>>(
        tmA_hn, tmB_w1, b1, nullptr, h1_h, MLPH, C_);

    // 7. MLP2 + bias + fp16 residual -> fp32 permuted [B,C,H,W]
    gemm_h<3><<<dim3(C_ / 128, T_ / 128), 128, GSMEM>>>(
        tmA_h1, tmB_w2, b2, xh2_h, out, C_, MLPH);
}